// round 11
// baseline (speedup 1.0000x reference)
#include <cuda_runtime.h>
#include <cuda_fp16.h>
#include <math.h>
#include <math_constants.h>
#include <stdint.h>

#define NROW 8192   // B*S
#define DIM  1024
#define SEQ  2048
#define NBATCH 4
#define HID  4096
#define CHUNKS 16
#define TCHUNK (SEQ / CHUNKS)   // 128
#define NQKV 3072

// ---------------- scratch (static device globals; no runtime alloc) ----------
__device__ uint16_t g_h_hi[(size_t)NROW * DIM];      // bf16 planes (QKV path)
__device__ uint16_t g_h_lo[(size_t)NROW * DIM];
__device__ uint16_t g_Wqkv_hi[(size_t)NQKV * DIM];
__device__ uint16_t g_Wqkv_lo[(size_t)NQKV * DIM];
__device__ uint16_t g_W116[(size_t)HID * DIM];       // fp16 transposed weights
__device__ uint16_t g_W216[(size_t)DIM * HID];
__device__ int8_t g_W1q1[(size_t)HID * DIM];
__device__ int8_t g_W1q2[(size_t)HID * DIM];
__device__ int8_t g_W2q1[(size_t)DIM * HID];
__device__ int8_t g_W2q2[(size_t)DIM * HID];
__device__ int8_t g_h2q1[(size_t)NROW * DIM];
__device__ int8_t g_h2q2[(size_t)NROW * DIM];
__device__ int8_t g_m1q1[(size_t)NROW * HID];
__device__ int8_t g_m1q2[(size_t)NROW * HID];
__device__ float g_m1f[(size_t)NROW * HID];          // fp32 m1 intermediate
__device__ float g_sh2[NROW];
__device__ float g_sm1[NROW];
__device__ unsigned g_m1max[NROW];
__device__ float g_sW1[HID];
__device__ float g_sW2[DIM];
__device__ float  g_qkv[(size_t)NROW * NQKV];
__device__ float  g_bqkv[NQKV];
__device__ float2 g_Qhat[(size_t)NROW * DIM];
__device__ float2 g_Mhat[(size_t)NROW * DIM];
__device__ float  g_xmid[(size_t)NROW * DIM];
__device__ float2 g_tw[512];
__device__ float2 g_part[NBATCH * CHUNKS * DIM];

// ---------------- helpers ----------------
__device__ __forceinline__ uint32_t smem_u32(const void* p) {
    uint32_t a;
    asm("{ .reg .u64 t; cvta.to.shared.u64 t, %1; cvt.u32.u64 %0, t; }" : "=r"(a) : "l"(p));
    return a;
}
__device__ __forceinline__ uint32_t pack_f16(float x0, float x1) {
    uint32_t h;
    asm("cvt.rn.f16x2.f32 %0, %1, %2;" : "=r"(h) : "f"(x1), "f"(x0));
    return h;
}
// split pair (x0,x1) -> packed bf16x2 hi (low half = x0) and lo
__device__ __forceinline__ void split2(float x0, float x1, uint32_t& hi, uint32_t& lo) {
    uint32_t h;
    asm("cvt.rn.bf16x2.f32 %0, %1, %2;" : "=r"(h) : "f"(x1), "f"(x0));
    float h0 = __uint_as_float(h << 16);
    float h1 = __uint_as_float(h & 0xFFFF0000u);
    float l0 = x0 - h0;
    float l1 = x1 - h1;
    asm("cvt.rn.bf16x2.f32 %0, %1, %2;" : "=r"(lo) : "f"(l1), "f"(l0));
    hi = h;
}
__device__ __forceinline__ void mma_bf16(float* d, const uint32_t* a, const uint32_t* b) {
    asm volatile("mma.sync.aligned.m16n8k16.row.col.f32.bf16.bf16.f32 "
        "{%0,%1,%2,%3}, {%4,%5,%6,%7}, {%8,%9}, {%0,%1,%2,%3};"
        : "+f"(d[0]), "+f"(d[1]), "+f"(d[2]), "+f"(d[3])
        : "r"(a[0]), "r"(a[1]), "r"(a[2]), "r"(a[3]), "r"(b[0]), "r"(b[1]));
}
__device__ __forceinline__ void mma_s8(int* d, const uint32_t* a, const uint32_t* b) {
    asm volatile("mma.sync.aligned.m16n8k32.row.col.s32.s8.s8.s32 "
        "{%0,%1,%2,%3}, {%4,%5,%6,%7}, {%8,%9}, {%0,%1,%2,%3};"
        : "+r"(d[0]), "+r"(d[1]), "+r"(d[2]), "+r"(d[3])
        : "r"(a[0]), "r"(a[1]), "r"(a[2]), "r"(a[3]), "r"(b[0]), "r"(b[1]));
}
__device__ __forceinline__ void cpa16(uint32_t dst, const void* src) {
    asm volatile("cp.async.cg.shared.global [%0], [%1], 16;" :: "r"(dst), "l"(src) : "memory");
}
__device__ __forceinline__ float2 c_add(float2 a, float2 b){return make_float2(a.x+b.x,a.y+b.y);}
__device__ __forceinline__ float2 c_sub(float2 a, float2 b){return make_float2(a.x-b.x,a.y-b.y);}
__device__ __forceinline__ float2 c_mul(float2 a, float2 b){return make_float2(a.x*b.x-a.y*b.y,a.x*b.y+a.y*b.x);}
__device__ __forceinline__ float2 c_negi(float2 a){return make_float2(a.y,-a.x);}
__device__ __forceinline__ void quant2(float y, float inv_s, int& q1, int& q2) {
    float q = y * inv_s;
    q1 = __float2int_rn(q);
    q2 = __float2int_rn((q - (float)q1) * 254.0f);
}
__device__ __forceinline__ uint32_t pack4(int a, int b, int c, int d) {
    return (uint32_t)(a & 0xFF) | ((uint32_t)(b & 0xFF) << 8) |
           ((uint32_t)(c & 0xFF) << 16) | ((uint32_t)(d & 0xFF) << 24);
}

// ---------------- small init kernels ----------------
__global__ void init_tw_kernel() {
    int i = threadIdx.x;
    double th = -2.0 * CUDART_PI * (double)i / 1024.0;
    g_tw[i] = make_float2((float)cos(th), (float)sin(th));
}
__global__ void bias_concat_kernel(const float* bq, const float* bk, const float* bv) {
    int i = blockIdx.x * 256 + threadIdx.x;
    float v = (i < 1024) ? bq[i] : (i < 2048) ? bk[i - 1024] : bv[i - 2048];
    g_bqkv[i] = v;
}
__global__ void zero_m1max_kernel() {
    g_m1max[blockIdx.x * 256 + threadIdx.x] = 0u;
}

// ---------------- weight transpose + bf16 split (QKV) ----------------
__global__ __launch_bounds__(256) void transpose_split_kernel(
    const float* __restrict__ in, uint16_t* __restrict__ ohi,
    uint16_t* __restrict__ olo, int R, int C)
{
    __shared__ float t[32][33];
    int bx = blockIdx.x, by = blockIdx.y;
    int x = bx * 32 + threadIdx.x;
    int y0 = by * 32 + threadIdx.y;
    #pragma unroll
    for (int j = 0; j < 32; j += 8)
        t[threadIdx.y + j][threadIdx.x] = in[(size_t)(y0 + j) * C + x];
    __syncthreads();
    int tl = threadIdx.y * 32 + threadIdx.x;
    int kp = tl & 15;
    int nr0 = tl >> 4;
    uint32_t* hw32 = (uint32_t*)ohi;
    uint32_t* lw32 = (uint32_t*)olo;
    #pragma unroll
    for (int rep = 0; rep < 2; rep++) {
        int nrel = nr0 + rep * 16;
        size_t n = (size_t)bx * 32 + nrel;
        int kg = by * 32 + kp * 2;
        uint32_t hw, lw;
        split2(t[kp * 2][nrel], t[kp * 2 + 1][nrel], hw, lw);
        size_t widx = (n * (size_t)R + kg) >> 1;
        hw32[widx] = hw;
        lw32[widx] = lw;
    }
}

// ---------------- weight transpose to fp16 (MLP) ----------------
__global__ __launch_bounds__(256) void transpose_f16_kernel(
    const float* __restrict__ in, uint16_t* __restrict__ o16, int R, int C)
{
    __shared__ float t[32][33];
    int bx = blockIdx.x, by = blockIdx.y;
    int x = bx * 32 + threadIdx.x;
    int y0 = by * 32 + threadIdx.y;
    #pragma unroll
    for (int j = 0; j < 32; j += 8)
        t[threadIdx.y + j][threadIdx.x] = in[(size_t)(y0 + j) * C + x];
    __syncthreads();
    int tl = threadIdx.y * 32 + threadIdx.x;
    int kp = tl & 15;
    int nr0 = tl >> 4;
    uint32_t* w32 = (uint32_t*)o16;
    #pragma unroll
    for (int rep = 0; rep < 2; rep++) {
        int nrel = nr0 + rep * 16;
        size_t n = (size_t)bx * 32 + nrel;
        int kg = by * 32 + kp * 2;
        w32[(n * (size_t)R + kg) >> 1] = pack_f16(t[kp * 2][nrel], t[kp * 2 + 1][nrel]);
    }
}

// ---------------- per-row weight quantization (fp16 src -> int8 planes) ------
__global__ __launch_bounds__(256) void wquant_kernel(
    const uint16_t* __restrict__ src, int8_t* __restrict__ q1p,
    int8_t* __restrict__ q2p, float* __restrict__ sOut, int K)
{
    __shared__ float redm[256];
    size_t row = blockIdx.x;
    int tid = threadIdx.x;
    int per = K / 256;
    const __half* sp = (const __half*)(src + row * (size_t)K) + tid * per;
    float m = 0.f;
    for (int i = 0; i < per; i++) m = fmaxf(m, fabsf(__half2float(sp[i])));
    redm[tid] = m;
    __syncthreads();
    #pragma unroll
    for (int s = 128; s > 0; s >>= 1) {
        if (tid < s) redm[tid] = fmaxf(redm[tid], redm[tid + s]);
        __syncthreads();
    }
    float mx = fmaxf(redm[0], 1e-20f);
    if (tid == 0) sOut[row] = mx / 127.0f;
    float inv = 127.0f / mx;
    uint32_t* o1 = (uint32_t*)(q1p + row * (size_t)K) + tid * (per / 4);
    uint32_t* o2 = (uint32_t*)(q2p + row * (size_t)K) + tid * (per / 4);
    for (int i = 0; i < per / 4; i++) {
        int a1[4], a2[4];
        #pragma unroll
        for (int j = 0; j < 4; j++)
            quant2(__half2float(sp[i * 4 + j]), inv, a1[j], a2[j]);
        o1[i] = pack4(a1[0], a1[1], a1[2], a1[3]);
        o2[i] = pack4(a2[0], a2[1], a2[2], a2[3]);
    }
}

// ---------------- m1 row quantization (fp32 src + precomputed max) ----------
__global__ __launch_bounds__(256) void m1quant_kernel() {
    size_t row = blockIdx.x;
    int tid = threadIdx.x;
    float mx = fmaxf(__uint_as_float(g_m1max[row]), 1e-20f);
    if (tid == 0) g_sm1[row] = mx / 127.0f;
    float inv = 127.0f / mx;
    const float4* sp = (const float4*)(g_m1f + row * (size_t)HID) + tid * 4;
    uint32_t* o1 = (uint32_t*)(g_m1q1 + row * (size_t)HID) + tid * 4;
    uint32_t* o2 = (uint32_t*)(g_m1q2 + row * (size_t)HID) + tid * 4;
    #pragma unroll
    for (int i = 0; i < 4; i++) {
        float4 v = sp[i];
        int a1[4], a2[4];
        quant2(v.x, inv, a1[0], a2[0]);
        quant2(v.y, inv, a1[1], a2[1]);
        quant2(v.z, inv, a1[2], a2[2]);
        quant2(v.w, inv, a1[3], a2[3]);
        o1[i] = pack4(a1[0], a1[1], a1[2], a1[3]);
        o2[i] = pack4(a2[0], a2[1], a2[2], a2[3]);
    }
}

// ---------------- block reductions ----------------
__device__ __forceinline__ float2 block_reduce2(float2 v, float2* sh) {
    int tid = threadIdx.x;
    sh[tid] = v;
    __syncthreads();
    #pragma unroll
    for (int s = 128; s > 0; s >>= 1) {
        if (tid < s) {
            sh[tid].x += sh[tid + s].x;
            sh[tid].y += sh[tid + s].y;
        }
        __syncthreads();
    }
    float2 r = sh[0];
    __syncthreads();
    return r;
}
__device__ __forceinline__ float block_reduce_max(float v, float* sh) {
    int tid = threadIdx.x;
    sh[tid] = v;
    __syncthreads();
    #pragma unroll
    for (int s = 128; s > 0; s >>= 1) {
        if (tid < s) sh[tid] = fmaxf(sh[tid], sh[tid + s]);
        __syncthreads();
    }
    float r = sh[0];
    __syncthreads();
    return r;
}

// ---------------- LayerNorm 1 -> bf16 hi/lo planes (QKV path) ----------------
__global__ __launch_bounds__(256) void ln_split_kernel(
    const float* __restrict__ x, const float* __restrict__ g,
    const float* __restrict__ b, uint16_t* __restrict__ ohi,
    uint16_t* __restrict__ olo)
{
    __shared__ float2 red[256];
    size_t row = blockIdx.x;
    int tid = threadIdx.x;
    float4 v = ((const float4*)(x + row * DIM))[tid];
    float s = v.x + v.y + v.z + v.w;
    float ss = v.x * v.x + v.y * v.y + v.z * v.z + v.w * v.w;
    float2 tot = block_reduce2(make_float2(s, ss), red);
    float mu = tot.x * (1.0f / DIM);
    float var = tot.y * (1.0f / DIM) - mu * mu;
    float rstd = rsqrtf(var + 1e-5f);
    float4 gg = ((const float4*)g)[tid];
    float4 bb = ((const float4*)b)[tid];
    float y0 = (v.x - mu) * rstd * gg.x + bb.x;
    float y1 = (v.y - mu) * rstd * gg.y + bb.y;
    float y2 = (v.z - mu) * rstd * gg.z + bb.z;
    float y3 = (v.w - mu) * rstd * gg.w + bb.w;
    uint32_t h0, l0, h1, l1;
    split2(y0, y1, h0, l0);
    split2(y2, y3, h1, l1);
    uint32_t* hw = (uint32_t*)ohi;
    uint32_t* lw = (uint32_t*)olo;
    size_t wb = row * 512 + tid * 2;
    hw[wb] = h0; hw[wb + 1] = h1;
    lw[wb] = l0; lw[wb + 1] = l1;
}

// -------- 1024-pt radix-4 Stockham FFT, bank-conflict-free swizzles --------
__device__ __forceinline__ int swz(int g, int a) {
    if (g == 1) return a ^ ((a >> 4) & 3);
    if (g == 2) return a ^ ((a >> 2) & 0xC);
    return a;
}
__device__ __forceinline__ float2* fft1024(float2* bufA, float2* bufB) {
    float2* x = bufA;
    float2* y = bufB;
    int n4 = 256, s = 1;
    #pragma unroll
    for (int st = 0; st < 5; st++) {
        __syncthreads();
        int i = threadIdx.x;
        int p = i / s;
        int q = i - p * s;
        float2 w1 = g_tw[p * s];
        float2 w2 = g_tw[2 * p * s];
        float2 x0 = x[swz(st, q + s * p)];
        float2 x1 = x[swz(st, q + s * (p + n4))];
        float2 x2 = x[swz(st, q + s * (p + 2 * n4))];
        float2 x3 = x[swz(st, q + s * (p + 3 * n4))];
        float2 za0 = c_add(x0, x2);
        float2 za1 = c_mul(c_sub(x0, x2), w1);
        float2 zb0 = c_add(x1, x3);
        float2 zb1 = c_mul(c_negi(c_sub(x1, x3)), w1);
        int ob = q + s * 4 * p;
        y[swz(st + 1, ob)]         = c_add(za0, zb0);
        y[swz(st + 1, ob + s)]     = c_add(za1, zb1);
        y[swz(st + 1, ob + 2 * s)] = c_mul(c_sub(za0, zb0), w2);
        y[swz(st + 1, ob + 3 * s)] = c_mul(c_sub(za1, zb1), w2);
        float2* t = x; x = y; y = t;
        n4 >>= 2; s <<= 2;
    }
    __syncthreads();
    return x;
}

// -------- fused QKV FFT: Q̂ -> g_Qhat ; K̂·V̂ -> g_Mhat ----------------------
__global__ __launch_bounds__(256) void fft_qkv_kernel() {
    __shared__ __align__(16) float2 bufA[1024];
    __shared__ __align__(16) float2 bufB[1024];
    __shared__ __align__(16) float2 kbuf[1024];
    size_t row = blockIdx.x;
    int tid = threadIdx.x;
    const float* base = g_qkv + row * NQKV;

    #pragma unroll
    for (int j = 0; j < 4; j++) {
        int idx = tid + j * 256;
        bufA[idx] = make_float2(base[idx], 0.f);
    }
    float2* res = fft1024(bufA, bufB);
    float2* qp = g_Qhat + row * DIM;
    #pragma unroll
    for (int j = 0; j < 4; j++) {
        int idx = tid + j * 256;
        float2 f = res[idx];
        float inv = 1.0f / fmaxf(sqrtf(f.x * f.x + f.y * f.y), 1e-8f);
        qp[idx] = make_float2(f.x * inv, f.y * inv);
    }
    __syncthreads();

    #pragma unroll
    for (int j = 0; j < 4; j++) {
        int idx = tid + j * 256;
        bufA[idx] = make_float2(base[1024 + idx], 0.f);
    }
    res = fft1024(bufA, bufB);
    #pragma unroll
    for (int j = 0; j < 4; j++) {
        int idx = tid + j * 256;
        float2 f = res[idx];
        float inv = 1.0f / fmaxf(sqrtf(f.x * f.x + f.y * f.y), 1e-8f);
        kbuf[idx] = make_float2(f.x * inv, f.y * inv);
    }
    __syncthreads();

    #pragma unroll
    for (int j = 0; j < 4; j++) {
        int idx = tid + j * 256;
        bufA[idx] = make_float2(base[2048 + idx], 0.f);
    }
    res = fft1024(bufA, bufB);
    float2* mp = g_Mhat + row * DIM;
    #pragma unroll
    for (int j = 0; j < 4; j++) {
        int idx = tid + j * 256;
        float2 f = res[idx];
        float inv = 1.0f / fmaxf(sqrtf(f.x * f.x + f.y * f.y), 1e-8f);
        f.x *= inv; f.y *= inv;
        float2 k = kbuf[idx];
        mp[idx] = make_float2(k.x * f.x - k.y * f.y,
                              k.x * f.y + k.y * f.x);
    }
}

// ---------------- chain pass A: per-chunk partial sums ----------------
__global__ __launch_bounds__(256) void chain_partial_kernel() {
    int gid = blockIdx.x * 256 + threadIdx.x;
    int bin = gid & 1023;
    int chunk = (gid >> 10) & (CHUNKS - 1);
    int b = gid >> 14;
    size_t base = ((size_t)b * SEQ + (size_t)chunk * TCHUNK) * DIM + bin;
    float2 s = make_float2(0.f, 0.f);
    #pragma unroll 4
    for (int i = 0; i < TCHUNK; i++) {
        float2 p = g_Mhat[base + (size_t)i * DIM];
        s.x += p.x; s.y += p.y;
    }
    g_part[gid] = s;
}

// ---------------- chain pass B: scan within chunk + apply conj(Q̂) --------
__global__ __launch_bounds__(256) void chain_apply_kernel() {
    int gid = blockIdx.x * 256 + threadIdx.x;
    int bin = gid & 1023;
    int chunk = (gid >> 10) & (CHUNKS - 1);
    int b = gid >> 14;
    float2 acc = make_float2(0.f, 0.f);
    for (int c = 0; c < chunk; c++) {
        float2 p = g_part[((b * CHUNKS) + c) * 1024 + bin];
        acc.x += p.x; acc.y += p.y;
    }
    size_t base = ((size_t)b * SEQ + (size_t)chunk * TCHUNK) * DIM + bin;
    #pragma unroll 4
    for (int i = 0; i < TCHUNK; i++) {
        size_t off = base + (size_t)i * DIM;
        float2 p = g_Mhat[off];
        acc.x += p.x; acc.y += p.y;
        float2 q = g_Qhat[off];
        g_Mhat[off] = make_float2(acc.x * q.x + acc.y * q.y,
                                  acc.y * q.x - acc.x * q.y);
    }
}

// ------- inverse FFT + residual + LN2 -> xmid fp32 + int8 planes + scale -----
__global__ __launch_bounds__(256) void ifft_res_ln_q8_kernel(
    const float* __restrict__ x, const float* __restrict__ g,
    const float* __restrict__ b)
{
    __shared__ __align__(16) float2 bufA[1024];
    __shared__ __align__(16) float2 bufB[1024];
    size_t row = blockIdx.x;
    int tid = threadIdx.x;
    const float2* mp = g_Mhat + row * DIM;
    #pragma unroll
    for (int j = 0; j < 4; j++) {
        int idx = tid + j * 256;
        float2 m = mp[idx];
        bufA[idx] = make_float2(m.x, -m.y);
    }
    float2* res = fft1024(bufA, bufB);   // = bufB
    float mixed[4];
    #pragma unroll
    for (int j = 0; j < 4; j++) mixed[j] = res[tid + j * 256].x * (1.0f / 1024.0f);
    __syncthreads();
    float* sbuf = (float*)bufA;
    const float* xp = x + row * DIM;
    float* xo = g_xmid + row * DIM;
    float s = 0.f, ss = 0.f;
    #pragma unroll
    for (int j = 0; j < 4; j++) {
        int idx = tid + j * 256;
        float v = xp[idx] + mixed[j];
        xo[idx] = v;
        sbuf[idx] = v;
        s += v; ss += v * v;
    }
    __syncthreads();
    float2 tot = block_reduce2(make_float2(s, ss), bufB);
    float mu = tot.x * (1.0f / DIM);
    float var = tot.y * (1.0f / DIM) - mu * mu;
    float rstd = rsqrtf(var + 1e-5f);
    float4 vv = ((const float4*)sbuf)[tid];
    float4 gg = ((const float4*)g)[tid];
    float4 bb = ((const float4*)b)[tid];
    float y[4];
    y[0] = (vv.x - mu) * rstd * gg.x + bb.x;
    y[1] = (vv.y - mu) * rstd * gg.y + bb.y;
    y[2] = (vv.z - mu) * rstd * gg.z + bb.z;
    y[3] = (vv.w - mu) * rstd * gg.w + bb.w;
    float m = fmaxf(fmaxf(fabsf(y[0]), fabsf(y[1])), fmaxf(fabsf(y[2]), fabsf(y[3])));
    float mx = fmaxf(block_reduce_max(m, (float*)bufB), 1e-20f);
    if (tid == 0) g_sh2[row] = mx / 127.0f;
    float inv = 127.0f / mx;
    int a1[4], a2[4];
    #pragma unroll
    for (int j = 0; j < 4; j++) quant2(y[j], inv, a1[j], a2[j]);
    ((uint32_t*)(g_h2q1 + row * DIM))[tid] = pack4(a1[0], a1[1], a1[2], a1[3]);
    ((uint32_t*)(g_h2q2 + row * DIM))[tid] = pack4(a2[0], a2[1], a2[2], a2[3]);
}

// ================== bf16x3 mma.sync GEMM (QKV), 256x128 CTA tile ============
// Proven R8 kernel, EPI0 (bias) only.
#define A_PL_B 20480u
#define B_PL_B 10240u
#define BSTAGE_B 61440u
#define BSTAGE_W 15360u
#define SMEM_BGEMM (2 * BSTAGE_B)         // 122880

__global__ __launch_bounds__(256) void mma_gemm_qkv(
    const uint16_t* __restrict__ Ahi, const uint16_t* __restrict__ Alo,
    const uint16_t* __restrict__ Bhi, const uint16_t* __restrict__ Blo,
    const float* __restrict__ bias, float* __restrict__ Cf, int N, int K)
{
    extern __shared__ uint32_t smu[];
    uint32_t su = smem_u32(smu);

    int tid = threadIdx.x;
    int wid = tid >> 5;
    int lane = tid & 31;
    int wm = wid & 3;
    int wn = wid >> 2;
    int bx = blockIdx.x, by = blockIdx.y;
    int gq = lane >> 2, tq = lane & 3;

    const uint16_t* aH = Ahi + (size_t)(by * 256 + tid) * K;
    const uint16_t* aL = Alo + (size_t)(by * 256 + tid) * K;
    int brow = tid >> 1;
    int bcp = (tid & 1) * 2;
    const uint16_t* bH = Bhi + (size_t)(bx * 128 + brow) * K;
    const uint16_t* bL = Blo + (size_t)(bx * 128 + brow) * K;

    #define BLOAD_STAGE(s, k0) do { \
        uint32_t _sb = su + (uint32_t)(s) * BSTAGE_B; \
        uint32_t _da = _sb + (uint32_t)tid * 80u; \
        _Pragma("unroll") \
        for (int c = 0; c < 4; c++) { \
            cpa16(_da + c * 16,           aH + (k0) + c * 8); \
            cpa16(_da + A_PL_B + c * 16,  aL + (k0) + c * 8); \
        } \
        uint32_t _db = _sb + 2 * A_PL_B + (uint32_t)brow * 80u + (uint32_t)bcp * 16u; \
        _Pragma("unroll") \
        for (int c = 0; c < 2; c++) { \
            cpa16(_db + c * 16,           bH + (k0) + (bcp + c) * 8); \
            cpa16(_db + B_PL_B + c * 16,  bL + (k0) + (bcp + c) * 8); \
        } \
        asm volatile("cp.async.commit_group;" ::: "memory"); \
    } while (0)

    float acc[4][8][4];
    #pragma unroll
    for (int mt = 0; mt < 4; mt++)
        #pragma unroll
        for (int nt = 0; nt < 8; nt++)
            #pragma unroll
            for (int i = 0; i < 4; i++) acc[mt][nt][i] = 0.f;

    int KT = K >> 5;
    BLOAD_STAGE(0, 0);

    int aBase0 = (wm * 64 + gq) * 20 + tq;
    int bBase0 = (wn * 64 + gq) * 20 + tq;

    for (int it = 0; it < KT; it++) {
        asm volatile("cp.async.wait_group 0;" ::: "memory");
        __syncthreads();
        if (it + 1 < KT) BLOAD_STAGE((it + 1) & 1, (it + 1) * 32);

        int s = it & 1;
        const uint32_t* ah_t = smu + s * BSTAGE_W;
        const uint32_t* al_t = ah_t + 5120;
        const uint32_t* bh_t = ah_t + 10240;
        const uint32_t* bl_t = ah_t + 12800;

        #pragma unroll
        for (int ks = 0; ks < 2; ks++) {
            int ko = ks * 8;
            uint32_t ah[4][4], al[4][4], bb[8][2];
            #pragma unroll
            for (int mt = 0; mt < 4; mt++) {
                int base = aBase0 + mt * 320 + ko;
                ah[mt][0] = ah_t[base];
                ah[mt][1] = ah_t[base + 160];
                ah[mt][2] = ah_t[base + 4];
                ah[mt][3] = ah_t[base + 164];
                al[mt][0] = al_t[base];
                al[mt][1] = al_t[base + 160];
                al[mt][2] = al_t[base + 4];
                al[mt][3] = al_t[base + 164];
            }
            #pragma unroll
            for (int nt = 0; nt < 8; nt++) {
                int base = bBase0 + nt * 160 + ko;
                bb[nt][0] = bh_t[base];
                bb[nt][1] = bh_t[base + 4];
            }
            #pragma unroll
            for (int mt = 0; mt < 4; mt++)
                #pragma unroll
                for (int nt = 0; nt < 8; nt++) {
                    mma_bf16(acc[mt][nt], ah[mt], bb[nt]);
                    mma_bf16(acc[mt][nt], al[mt], bb[nt]);
                }
            #pragma unroll
            for (int nt = 0; nt < 8; nt++) {
                int base = bBase0 + nt * 160 + ko;
                bb[nt][0] = bl_t[base];
                bb[nt][1] = bl_t[base + 4];
            }
            #pragma unroll
            for (int mt = 0; mt < 4; mt++)
                #pragma unroll
                for (int nt = 0; nt < 8; nt++)
                    mma_bf16(acc[mt][nt], ah[mt], bb[nt]);
        }
        __syncthreads();
    }

    #pragma unroll
    for (int mt = 0; mt < 4; mt++) {
        #pragma unroll
        for (int nt = 0; nt < 8; nt++) {
            int r0 = by * 256 + wm * 64 + mt * 16 + gq;
            int c0 = bx * 128 + wn * 64 + nt * 8 + tq * 2;
            float b0 = bias[c0], b1 = bias[c0 + 1];
            #pragma unroll
            for (int half = 0; half < 2; half++) {
                size_t r = r0 + half * 8;
                float2 o;
                o.x = acc[mt][nt][half * 2 + 0] + b0;
                o.y = acc[mt][nt][half * 2 + 1] + b1;
                *(float2*)(Cf + r * (size_t)N + c0) = o;
            }
        }
    }
}

// ============ int8 4-pass (exact) mma.sync GEMM, 128x128 CTA tile ============
// 512 threads, 16 warps (8m x 2n), warp tile 16x64, BK=64, 2-stage cp.async.
// Planes per stage: A1|A2|B1|B2, each 128 rows x 80B stride (64B data).
// x = s*(q1 + q2/254) exactly; acc1=q1q1, acc2=q1q2'+q2q1', acc3=q2q2'.
// EPI 1: bias+GELU -> fp32 m1 + rowmax atomics ; EPI 2: bias+res -> Cf
#define PL_B 10240u
#define QSTAGE_B 40960u
#define QSTAGE_W 10240u
#define SMEM_QGEMM (2 * QSTAGE_B)         // 81920

template<int EPI>
__global__ __launch_bounds__(512) void q8_gemm4(
    const int8_t* __restrict__ A1, const int8_t* __restrict__ A2,
    const int8_t* __restrict__ B1, const int8_t* __restrict__ B2,
    const float* __restrict__ sA, const float* __restrict__ sB,
    const float* __restrict__ bias, const float* __restrict__ res,
    float* __restrict__ Cf, int N, int K)
{
    extern __shared__ uint32_t smu[];
    uint32_t su = smem_u32(smu);

    int tid = threadIdx.x;
    int wid = tid >> 5;
    int lane = tid & 31;
    int wm = wid & 7;        // 0..7 -> 16-row slice
    int wn = wid >> 3;       // 0..1 -> 64-col slice
    int bx = blockIdx.x, by = blockIdx.y;
    int gq = lane >> 2, tq = lane & 3;

    // loaders: 512 threads, asel = plane (A1,A2,B1,B2), arow = row 0..127
    int arow = tid & 127;
    int asel = tid >> 7;
    const int8_t* gsrc;
    if (asel == 0)      gsrc = A1 + (size_t)(by * 128 + arow) * K;
    else if (asel == 1) gsrc = A2 + (size_t)(by * 128 + arow) * K;
    else if (asel == 2) gsrc = B1 + (size_t)(bx * 128 + arow) * K;
    else                gsrc = B2 + (size_t)(bx * 128 + arow) * K;

    #define QLOAD_STAGE(s, k0) do { \
        uint32_t _d = su + (uint32_t)(s) * QSTAGE_B + (uint32_t)asel * PL_B + (uint32_t)arow * 80u; \
        _Pragma("unroll") \
        for (int c = 0; c < 4; c++) \
            cpa16(_d + c * 16, gsrc + (k0) + c * 16); \
        asm volatile("cp.async.commit_group;" ::: "memory"); \
    } while (0)

    int acc1[8][4], acc2[8][4], acc3[8][4];
    #pragma unroll
    for (int nt = 0; nt < 8; nt++)
        #pragma unroll
        for (int i = 0; i < 4; i++) { acc1[nt][i] = 0; acc2[nt][i] = 0; acc3[nt][i] = 0; }

    int KT = K >> 6;
    QLOAD_STAGE(0, 0);

    int aBase0 = (wm * 16 + gq) * 20 + tq;
    int bBase0 = (wn * 64 + gq) * 20 + tq;

    for (int it = 0; it < KT; it++) {
        asm volatile("cp.async.wait_group 0;" ::: "memory");
        __syncthreads();
        if (it + 1 < KT) QLOAD_STAGE((it + 1) & 1, (it + 1) * 64);

        int s = it & 1;
        const uint32_t* a1_t = smu + s * QSTAGE_W;
        const uint32_t* a2_t = a1_t + 2560;
        const uint32_t* b1_t = a1_t + 5120;
        const uint32_t* b2_t = a1_t + 7680;

        #pragma unroll
        for (int ks = 0; ks < 2; ks++) {
            int ko = ks * 8;
            uint32_t af1[4], af2[4], bf[8][2];
            {
                int base = aBase0 + ko;
                af1[0] = a1_t[base];
                af1[1] = a1_t[base + 160];
                af1[2] = a1_t[base + 4];
                af1[3] = a1_t[base + 164];
                af2[0] = a2_t[base];
                af2[1] = a2_t[base + 160];
                af2[2] = a2_t[base + 4];
                af2[3] = a2_t[base + 164];
            }
            #pragma unroll
            for (int nt = 0; nt < 8; nt++) {
                int base = bBase0 + nt * 160 + ko;
                bf[nt][0] = b1_t[base];
                bf[nt][1] = b1_t[base + 4];
            }
            // acc1 += q1*q1' ; acc2 += q2*q1'
            #pragma unroll
            for (int nt = 0; nt < 8; nt++) {
                mma_s8(acc1[nt], af1, bf[nt]);
                mma_s8(acc2[nt], af2, bf[nt]);
            }
            // reload b2: acc2 += q1*q2' ; acc3 += q2*q2'
            #pragma unroll
            for (int nt = 0; nt < 8; nt++) {
                int base = bBase0 + nt * 160 + ko;
                bf[nt][0] = b2_t[base];
                bf[nt][1] = b2_t[base + 4];
            }
            #pragma unroll
            for (int nt = 0; nt < 8; nt++) {
                mma_s8(acc2[nt], af1, bf[nt]);
                mma_s8(acc3[nt], af2, bf[nt]);
            }
        }
        __syncthreads();
    }

    // ---- epilogue ----
    float rm[2];
    rm[0] = rm[1] = 0.f;
    #pragma unroll
    for (int nt = 0; nt < 8; nt++) {
        int r0 = by * 128 + wm * 16 + gq;
        int c0 = bx * 128 + wn * 64 + nt * 8 + tq * 2;
        float b0 = bias[c0], b1 = bias[c0 + 1];
        float sb0 = sB[c0], sb1 = sB[c0 + 1];
        #pragma unroll
        for (int half = 0; half < 2; half++) {
            size_t r = r0 + half * 8;
            float sar = sA[r];
            float p0 = (float)acc1[nt][half * 2 + 0]
                     + (float)acc2[nt][half * 2 + 0] * (1.0f / 254.0f)
                     + (float)acc3[nt][half * 2 + 0] * (1.0f / 64516.0f);
            float p1 = (float)acc1[nt][half * 2 + 1]
                     + (float)acc2[nt][half * 2 + 1] * (1.0f / 254.0f)
                     + (float)acc3[nt][half * 2 + 1] * (1.0f / 64516.0f);
            float v0 = sar * sb0 * p0 + b0;
            float v1 = sar * sb1 * p1 + b1;
            if (EPI == 1) {
                v0 = 0.5f * v0 * (1.0f + erff(v0 * 0.70710678118654752f));
                v1 = 0.5f * v1 * (1.0f + erff(v1 * 0.70710678118654752f));
                float2 o; o.x = v0; o.y = v1;
                *(float2*)(Cf + r * (size_t)N + c0) = o;
                rm[half] = fmaxf(rm[half], fmaxf(fabsf(v0), fabsf(v1)));
            } else {
                float2 rv = *(const float2*)(res + r * (size_t)N + c0);
                v0 += rv.x; v1 += rv.y;
                float2 o; o.x = v0; o.y = v1;
                *(float2*)(Cf + r * (size_t)N + c0) = o;
            }
        }
    }
    if (EPI == 1) {
        #pragma unroll
        for (int half = 0; half < 2; half++) {
            size_t r = (size_t)by * 128 + wm * 16 + gq + half * 8;
            atomicMax(&g_m1max[r], __float_as_uint(rm[half]));
        }
    }
}

// ---------------- launch ----------------
extern "C" void kernel_launch(void* const* d_in, const int* in_sizes, int n_in,
                              void* d_out, int out_size)
{
    const float* x     = (const float*)d_in[0];
    const float* Wq    = (const float*)d_in[1];
    const float* bq    = (const float*)d_in[2];
    const float* Wk    = (const float*)d_in[3];
    const float* bk    = (const float*)d_in[4];
    const float* Wv    = (const float*)d_in[5];
    const float* bv    = (const float*)d_in[6];
    const float* ln1_g = (const float*)d_in[7];
    const float* ln1_b = (const float*)d_in[8];
    const float* ln2_g = (const float*)d_in[9];
    const float* ln2_b = (const float*)d_in[10];
    const float* W1    = (const float*)d_in[11];
    const float* b1    = (const float*)d_in[12];
    const float* W2    = (const float*)d_in[13];
    const float* b2    = (const float*)d_in[14];
    float* out = (float*)d_out;

    uint16_t *hHi, *hLo, *WqkvHi, *WqkvLo, *W116, *W216;
    int8_t *h2q1, *h2q2, *m1q1, *m1q2, *W1q1, *W1q2, *W2q1, *W2q2;
    float *qkv, *xmid, *bqkv, *sh2, *sm1, *sW1, *sW2, *m1f;
    cudaGetSymbolAddress((void**)&hHi,    g_h_hi);
    cudaGetSymbolAddress((void**)&hLo,    g_h_lo);
    cudaGetSymbolAddress((void**)&WqkvHi, g_Wqkv_hi);
    cudaGetSymbolAddress((void**)&WqkvLo, g_Wqkv_lo);
    cudaGetSymbolAddress((void**)&W116,   g_W116);
    cudaGetSymbolAddress((void**)&W216,   g_W216);
    cudaGetSymbolAddress((void**)&h2q1,   g_h2q1);
    cudaGetSymbolAddress((void**)&h2q2,   g_h2q2);
    cudaGetSymbolAddress((void**)&m1q1,   g_m1q1);
    cudaGetSymbolAddress((void**)&m1q2,   g_m1q2);
    cudaGetSymbolAddress((void**)&W1q1,   g_W1q1);
    cudaGetSymbolAddress((void**)&W1q2,   g_W1q2);
    cudaGetSymbolAddress((void**)&W2q1,   g_W2q1);
    cudaGetSymbolAddress((void**)&W2q2,   g_W2q2);
    cudaGetSymbolAddress((void**)&qkv,    g_qkv);
    cudaGetSymbolAddress((void**)&xmid,   g_xmid);
    cudaGetSymbolAddress((void**)&bqkv,   g_bqkv);
    cudaGetSymbolAddress((void**)&sh2,    g_sh2);
    cudaGetSymbolAddress((void**)&sm1,    g_sm1);
    cudaGetSymbolAddress((void**)&sW1,    g_sW1);
    cudaGetSymbolAddress((void**)&sW2,    g_sW2);
    cudaGetSymbolAddress((void**)&m1f,    g_m1f);

    cudaFuncSetAttribute(mma_gemm_qkv, cudaFuncAttributeMaxDynamicSharedMemorySize, SMEM_BGEMM);
    cudaFuncSetAttribute(q8_gemm4<1>, cudaFuncAttributeMaxDynamicSharedMemorySize, SMEM_QGEMM);
    cudaFuncSetAttribute(q8_gemm4<2>, cudaFuncAttributeMaxDynamicSharedMemorySize, SMEM_QGEMM);

    init_tw_kernel<<<1, 512>>>();
    bias_concat_kernel<<<NQKV / 256, 256>>>(bq, bk, bv);
    zero_m1max_kernel<<<NROW / 256, 256>>>();

    // QKV weights -> bf16 hi/lo planes (bf16x3 path)
    transpose_split_kernel<<<dim3(32, 32), dim3(32, 8)>>>(Wq, WqkvHi, WqkvLo, DIM, DIM);
    transpose_split_kernel<<<dim3(32, 32), dim3(32, 8)>>>(Wk, WqkvHi + (size_t)1024 * DIM, WqkvLo + (size_t)1024 * DIM, DIM, DIM);
    transpose_split_kernel<<<dim3(32, 32), dim3(32, 8)>>>(Wv, WqkvHi + (size_t)2048 * DIM, WqkvLo + (size_t)2048 * DIM, DIM, DIM);

    // MLP weights -> fp16 -> int8 planes + per-row scales
    transpose_f16_kernel<<<dim3(128, 32), dim3(32, 8)>>>(W1, W116, DIM, HID);
    transpose_f16_kernel<<<dim3(32, 128), dim3(32, 8)>>>(W2, W216, HID, DIM);
    wquant_kernel<<<HID, 256>>>(W116, W1q1, W1q2, sW1, DIM);
    wquant_kernel<<<DIM, 256>>>(W216, W2q1, W2q2, sW2, HID);

    // LN1 -> bf16 planes
    ln_split_kernel<<<NROW, 256>>>(x, ln1_g, ln1_b, hHi, hLo);

    // fused QKV projection (bf16x3, 256x128 tiles)
    mma_gemm_qkv<<<dim3(NQKV / 128, NROW / 256), 256, SMEM_BGEMM>>>(
        hHi, hLo, WqkvHi, WqkvLo, bqkv, qkv, NQKV, DIM);

    // fused FFT + normalize for q,k,v
    fft_qkv_kernel<<<NROW, 256>>>();

    // causal cumsum in Fourier domain, fused * conj(Q̂)
    chain_partial_kernel<<<(NBATCH * CHUNKS * DIM) / 256, 256>>>();
    chain_apply_kernel<<<(NBATCH * CHUNKS * DIM) / 256, 256>>>();

    // inverse FFT + residual + LN2 -> xmid + int8 planes + scale
    ifft_res_ln_q8_kernel<<<NROW, 256>>>(x, ln2_g, ln2_b);

    // MLP1 (int8 4-pass, GELU -> fp32 m1 + rowmax), quantize m1, MLP2 (+res)
    q8_gemm4<1><<<dim3(HID / 128, NROW / 128), 512, SMEM_QGEMM>>>(
        h2q1, h2q2, W1q1, W1q2, sh2, sW1, b1, nullptr, m1f, HID, DIM);
    m1quant_kernel<<<NROW, 256>>>();
    q8_gemm4<2><<<dim3(DIM / 128, NROW / 128), 512, SMEM_QGEMM>>>(
        m1q1, m1q2, W2q1, W2q2, sm1, sW2, b2, xmid, out, DIM, HID);

    (void)in_sizes; (void)n_in; (void)out_size;
}

// round 12
// speedup vs baseline: 3.3456x; 3.3456x over previous
#include <cuda_runtime.h>
#include <cuda_fp16.h>
#include <math.h>
#include <math_constants.h>
#include <stdint.h>

#define NROW 8192   // B*S
#define DIM  1024
#define SEQ  2048
#define NBATCH 4
#define HID  4096
#define CHUNKS 16
#define TCHUNK (SEQ / CHUNKS)   // 128
#define NQKV 3072

// ---------------- scratch (static device globals; no runtime alloc) ----------
__device__ uint16_t g_h_hi[(size_t)NROW * DIM];      // bf16 planes (QKV path)
__device__ uint16_t g_h_lo[(size_t)NROW * DIM];
__device__ uint16_t g_Wqkv_hi[(size_t)NQKV * DIM];
__device__ uint16_t g_Wqkv_lo[(size_t)NQKV * DIM];
__device__ uint16_t g_W116[(size_t)HID * DIM];       // fp16 transposed weights
__device__ uint16_t g_W216[(size_t)DIM * HID];
__device__ uint16_t g_h216[(size_t)NROW * DIM];      // fp16 h2
__device__ uint16_t g_m116[(size_t)NROW * HID];      // fp16 m1
__device__ float  g_qkv[(size_t)NROW * NQKV];
__device__ float  g_bqkv[NQKV];
__device__ float2 g_Qhat[(size_t)NROW * DIM];
__device__ float2 g_Mhat[(size_t)NROW * DIM];
__device__ float  g_xmid[(size_t)NROW * DIM];
__device__ float2 g_tw[512];
__device__ float2 g_part[NBATCH * CHUNKS * DIM];

// ---------------- helpers ----------------
__device__ __forceinline__ uint32_t smem_u32(const void* p) {
    uint32_t a;
    asm("{ .reg .u64 t; cvta.to.shared.u64 t, %1; cvt.u32.u64 %0, t; }" : "=r"(a) : "l"(p));
    return a;
}
__device__ __forceinline__ uint32_t pack_f16(float x0, float x1) {
    uint32_t h;
    asm("cvt.rn.f16x2.f32 %0, %1, %2;" : "=r"(h) : "f"(x1), "f"(x0));
    return h;
}
// split pair (x0,x1) -> packed bf16x2 hi (low half = x0) and lo
__device__ __forceinline__ void split2(float x0, float x1, uint32_t& hi, uint32_t& lo) {
    uint32_t h;
    asm("cvt.rn.bf16x2.f32 %0, %1, %2;" : "=r"(h) : "f"(x1), "f"(x0));
    float h0 = __uint_as_float(h << 16);
    float h1 = __uint_as_float(h & 0xFFFF0000u);
    float l0 = x0 - h0;
    float l1 = x1 - h1;
    asm("cvt.rn.bf16x2.f32 %0, %1, %2;" : "=r"(lo) : "f"(l1), "f"(l0));
    hi = h;
}
__device__ __forceinline__ void mma_bf16(float* d, const uint32_t* a, const uint32_t* b) {
    asm volatile("mma.sync.aligned.m16n8k16.row.col.f32.bf16.bf16.f32 "
        "{%0,%1,%2,%3}, {%4,%5,%6,%7}, {%8,%9}, {%0,%1,%2,%3};"
        : "+f"(d[0]), "+f"(d[1]), "+f"(d[2]), "+f"(d[3])
        : "r"(a[0]), "r"(a[1]), "r"(a[2]), "r"(a[3]), "r"(b[0]), "r"(b[1]));
}
__device__ __forceinline__ void mma_f16(float* d, const uint32_t* a, const uint32_t* b) {
    asm volatile("mma.sync.aligned.m16n8k16.row.col.f32.f16.f16.f32 "
        "{%0,%1,%2,%3}, {%4,%5,%6,%7}, {%8,%9}, {%0,%1,%2,%3};"
        : "+f"(d[0]), "+f"(d[1]), "+f"(d[2]), "+f"(d[3])
        : "r"(a[0]), "r"(a[1]), "r"(a[2]), "r"(a[3]), "r"(b[0]), "r"(b[1]));
}
__device__ __forceinline__ void cpa16(uint32_t dst, const void* src) {
    asm volatile("cp.async.cg.shared.global [%0], [%1], 16;" :: "r"(dst), "l"(src) : "memory");
}
__device__ __forceinline__ float2 c_add(float2 a, float2 b){return make_float2(a.x+b.x,a.y+b.y);}
__device__ __forceinline__ float2 c_sub(float2 a, float2 b){return make_float2(a.x-b.x,a.y-b.y);}
__device__ __forceinline__ float2 c_mul(float2 a, float2 b){return make_float2(a.x*b.x-a.y*b.y,a.x*b.y+a.y*b.x);}
__device__ __forceinline__ float2 c_negi(float2 a){return make_float2(a.y,-a.x);}

// ---------------- small init kernels ----------------
__global__ void init_tw_kernel() {
    int i = threadIdx.x;
    double th = -2.0 * CUDART_PI * (double)i / 1024.0;
    g_tw[i] = make_float2((float)cos(th), (float)sin(th));
}
__global__ void bias_concat_kernel(const float* bq, const float* bk, const float* bv) {
    int i = blockIdx.x * 256 + threadIdx.x;
    float v = (i < 1024) ? bq[i] : (i < 2048) ? bk[i - 1024] : bv[i - 2048];
    g_bqkv[i] = v;
}

// ---------------- weight transpose + bf16 split (QKV) ----------------
__global__ __launch_bounds__(256) void transpose_split_kernel(
    const float* __restrict__ in, uint16_t* __restrict__ ohi,
    uint16_t* __restrict__ olo, int R, int C)
{
    __shared__ float t[32][33];
    int bx = blockIdx.x, by = blockIdx.y;
    int x = bx * 32 + threadIdx.x;
    int y0 = by * 32 + threadIdx.y;
    #pragma unroll
    for (int j = 0; j < 32; j += 8)
        t[threadIdx.y + j][threadIdx.x] = in[(size_t)(y0 + j) * C + x];
    __syncthreads();
    int tl = threadIdx.y * 32 + threadIdx.x;
    int kp = tl & 15;
    int nr0 = tl >> 4;
    uint32_t* hw32 = (uint32_t*)ohi;
    uint32_t* lw32 = (uint32_t*)olo;
    #pragma unroll
    for (int rep = 0; rep < 2; rep++) {
        int nrel = nr0 + rep * 16;
        size_t n = (size_t)bx * 32 + nrel;
        int kg = by * 32 + kp * 2;
        uint32_t hw, lw;
        split2(t[kp * 2][nrel], t[kp * 2 + 1][nrel], hw, lw);
        size_t widx = (n * (size_t)R + kg) >> 1;
        hw32[widx] = hw;
        lw32[widx] = lw;
    }
}

// ---------------- weight transpose to fp16 (MLP) ----------------
__global__ __launch_bounds__(256) void transpose_f16_kernel(
    const float* __restrict__ in, uint16_t* __restrict__ o16, int R, int C)
{
    __shared__ float t[32][33];
    int bx = blockIdx.x, by = blockIdx.y;
    int x = bx * 32 + threadIdx.x;
    int y0 = by * 32 + threadIdx.y;
    #pragma unroll
    for (int j = 0; j < 32; j += 8)
        t[threadIdx.y + j][threadIdx.x] = in[(size_t)(y0 + j) * C + x];
    __syncthreads();
    int tl = threadIdx.y * 32 + threadIdx.x;
    int kp = tl & 15;
    int nr0 = tl >> 4;
    uint32_t* w32 = (uint32_t*)o16;
    #pragma unroll
    for (int rep = 0; rep < 2; rep++) {
        int nrel = nr0 + rep * 16;
        size_t n = (size_t)bx * 32 + nrel;
        int kg = by * 32 + kp * 2;
        w32[(n * (size_t)R + kg) >> 1] = pack_f16(t[kp * 2][nrel], t[kp * 2 + 1][nrel]);
    }
}

// ---------------- block reduction ----------------
__device__ __forceinline__ float2 block_reduce2(float2 v, float2* sh) {
    int tid = threadIdx.x;
    sh[tid] = v;
    __syncthreads();
    #pragma unroll
    for (int s = 128; s > 0; s >>= 1) {
        if (tid < s) {
            sh[tid].x += sh[tid + s].x;
            sh[tid].y += sh[tid + s].y;
        }
        __syncthreads();
    }
    float2 r = sh[0];
    __syncthreads();
    return r;
}

// ---------------- LayerNorm 1 -> bf16 hi/lo planes ----------------
__global__ __launch_bounds__(256) void ln_split_kernel(
    const float* __restrict__ x, const float* __restrict__ g,
    const float* __restrict__ b, uint16_t* __restrict__ ohi,
    uint16_t* __restrict__ olo)
{
    __shared__ float2 red[256];
    size_t row = blockIdx.x;
    int tid = threadIdx.x;
    float4 v = ((const float4*)(x + row * DIM))[tid];
    float s = v.x + v.y + v.z + v.w;
    float ss = v.x * v.x + v.y * v.y + v.z * v.z + v.w * v.w;
    float2 tot = block_reduce2(make_float2(s, ss), red);
    float mu = tot.x * (1.0f / DIM);
    float var = tot.y * (1.0f / DIM) - mu * mu;
    float rstd = rsqrtf(var + 1e-5f);
    float4 gg = ((const float4*)g)[tid];
    float4 bb = ((const float4*)b)[tid];
    float y0 = (v.x - mu) * rstd * gg.x + bb.x;
    float y1 = (v.y - mu) * rstd * gg.y + bb.y;
    float y2 = (v.z - mu) * rstd * gg.z + bb.z;
    float y3 = (v.w - mu) * rstd * gg.w + bb.w;
    uint32_t h0, l0, h1, l1;
    split2(y0, y1, h0, l0);
    split2(y2, y3, h1, l1);
    uint32_t* hw = (uint32_t*)ohi;
    uint32_t* lw = (uint32_t*)olo;
    size_t wb = row * 512 + tid * 2;
    hw[wb] = h0; hw[wb + 1] = h1;
    lw[wb] = l0; lw[wb + 1] = l1;
}

// -------- 1024-pt radix-4 Stockham FFT, bank-conflict-free swizzles --------
__device__ __forceinline__ int swz(int g, int a) {
    if (g == 1) return a ^ ((a >> 4) & 3);
    if (g == 2) return a ^ ((a >> 2) & 0xC);
    return a;
}
__device__ __forceinline__ float2* fft1024(float2* bufA, float2* bufB) {
    float2* x = bufA;
    float2* y = bufB;
    int n4 = 256, s = 1;
    #pragma unroll
    for (int st = 0; st < 5; st++) {
        __syncthreads();
        int i = threadIdx.x;
        int p = i / s;
        int q = i - p * s;
        float2 w1 = g_tw[p * s];
        float2 w2 = g_tw[2 * p * s];
        float2 x0 = x[swz(st, q + s * p)];
        float2 x1 = x[swz(st, q + s * (p + n4))];
        float2 x2 = x[swz(st, q + s * (p + 2 * n4))];
        float2 x3 = x[swz(st, q + s * (p + 3 * n4))];
        float2 za0 = c_add(x0, x2);
        float2 za1 = c_mul(c_sub(x0, x2), w1);
        float2 zb0 = c_add(x1, x3);
        float2 zb1 = c_mul(c_negi(c_sub(x1, x3)), w1);
        int ob = q + s * 4 * p;
        y[swz(st + 1, ob)]         = c_add(za0, zb0);
        y[swz(st + 1, ob + s)]     = c_add(za1, zb1);
        y[swz(st + 1, ob + 2 * s)] = c_mul(c_sub(za0, zb0), w2);
        y[swz(st + 1, ob + 3 * s)] = c_mul(c_sub(za1, zb1), w2);
        float2* t = x; x = y; y = t;
        n4 >>= 2; s <<= 2;
    }
    __syncthreads();
    return x;
}

// -------- fused QKV FFT: Q̂ -> g_Qhat ; K̂·V̂ -> g_Mhat ----------------------
__global__ __launch_bounds__(256) void fft_qkv_kernel() {
    __shared__ __align__(16) float2 bufA[1024];
    __shared__ __align__(16) float2 bufB[1024];
    __shared__ __align__(16) float2 kbuf[1024];
    size_t row = blockIdx.x;
    int tid = threadIdx.x;
    const float* base = g_qkv + row * NQKV;

    #pragma unroll
    for (int j = 0; j < 4; j++) {
        int idx = tid + j * 256;
        bufA[idx] = make_float2(base[idx], 0.f);
    }
    float2* res = fft1024(bufA, bufB);
    float2* qp = g_Qhat + row * DIM;
    #pragma unroll
    for (int j = 0; j < 4; j++) {
        int idx = tid + j * 256;
        float2 f = res[idx];
        float inv = 1.0f / fmaxf(sqrtf(f.x * f.x + f.y * f.y), 1e-8f);
        qp[idx] = make_float2(f.x * inv, f.y * inv);
    }
    __syncthreads();

    #pragma unroll
    for (int j = 0; j < 4; j++) {
        int idx = tid + j * 256;
        bufA[idx] = make_float2(base[1024 + idx], 0.f);
    }
    res = fft1024(bufA, bufB);
    #pragma unroll
    for (int j = 0; j < 4; j++) {
        int idx = tid + j * 256;
        float2 f = res[idx];
        float inv = 1.0f / fmaxf(sqrtf(f.x * f.x + f.y * f.y), 1e-8f);
        kbuf[idx] = make_float2(f.x * inv, f.y * inv);
    }
    __syncthreads();

    #pragma unroll
    for (int j = 0; j < 4; j++) {
        int idx = tid + j * 256;
        bufA[idx] = make_float2(base[2048 + idx], 0.f);
    }
    res = fft1024(bufA, bufB);
    float2* mp = g_Mhat + row * DIM;
    #pragma unroll
    for (int j = 0; j < 4; j++) {
        int idx = tid + j * 256;
        float2 f = res[idx];
        float inv = 1.0f / fmaxf(sqrtf(f.x * f.x + f.y * f.y), 1e-8f);
        f.x *= inv; f.y *= inv;
        float2 k = kbuf[idx];
        mp[idx] = make_float2(k.x * f.x - k.y * f.y,
                              k.x * f.y + k.y * f.x);
    }
}

// ---------------- chain pass A: per-chunk partial sums ----------------
__global__ __launch_bounds__(256) void chain_partial_kernel() {
    int gid = blockIdx.x * 256 + threadIdx.x;
    int bin = gid & 1023;
    int chunk = (gid >> 10) & (CHUNKS - 1);
    int b = gid >> 14;
    size_t base = ((size_t)b * SEQ + (size_t)chunk * TCHUNK) * DIM + bin;
    float2 s = make_float2(0.f, 0.f);
    #pragma unroll 4
    for (int i = 0; i < TCHUNK; i++) {
        float2 p = g_Mhat[base + (size_t)i * DIM];
        s.x += p.x; s.y += p.y;
    }
    g_part[gid] = s;
}

// ---------------- chain pass B: scan within chunk + apply conj(Q̂) --------
__global__ __launch_bounds__(256) void chain_apply_kernel() {
    int gid = blockIdx.x * 256 + threadIdx.x;
    int bin = gid & 1023;
    int chunk = (gid >> 10) & (CHUNKS - 1);
    int b = gid >> 14;
    float2 acc = make_float2(0.f, 0.f);
    for (int c = 0; c < chunk; c++) {
        float2 p = g_part[((b * CHUNKS) + c) * 1024 + bin];
        acc.x += p.x; acc.y += p.y;
    }
    size_t base = ((size_t)b * SEQ + (size_t)chunk * TCHUNK) * DIM + bin;
    #pragma unroll 4
    for (int i = 0; i < TCHUNK; i++) {
        size_t off = base + (size_t)i * DIM;
        float2 p = g_Mhat[off];
        acc.x += p.x; acc.y += p.y;
        float2 q = g_Qhat[off];
        g_Mhat[off] = make_float2(acc.x * q.x + acc.y * q.y,
                                  acc.y * q.x - acc.x * q.y);
    }
}

// ------- inverse FFT + residual + LN2, emits xmid fp32 and h2 fp16 plane ----
__global__ __launch_bounds__(256) void ifft_res_ln_kernel(
    const float* __restrict__ x, const float* __restrict__ g,
    const float* __restrict__ b, uint16_t* __restrict__ o16)
{
    __shared__ __align__(16) float2 bufA[1024];
    __shared__ __align__(16) float2 bufB[1024];
    size_t row = blockIdx.x;
    int tid = threadIdx.x;
    const float2* mp = g_Mhat + row * DIM;
    #pragma unroll
    for (int j = 0; j < 4; j++) {
        int idx = tid + j * 256;
        float2 m = mp[idx];
        bufA[idx] = make_float2(m.x, -m.y);
    }
    float2* res = fft1024(bufA, bufB);   // = bufB
    float mixed[4];
    #pragma unroll
    for (int j = 0; j < 4; j++) mixed[j] = res[tid + j * 256].x * (1.0f / 1024.0f);
    __syncthreads();
    float* sbuf = (float*)bufA;
    const float* xp = x + row * DIM;
    float* xo = g_xmid + row * DIM;
    float s = 0.f, ss = 0.f;
    #pragma unroll
    for (int j = 0; j < 4; j++) {
        int idx = tid + j * 256;
        float v = xp[idx] + mixed[j];
        xo[idx] = v;
        sbuf[idx] = v;
        s += v; ss += v * v;
    }
    __syncthreads();
    float2 tot = block_reduce2(make_float2(s, ss), bufB);
    float mu = tot.x * (1.0f / DIM);
    float var = tot.y * (1.0f / DIM) - mu * mu;
    float rstd = rsqrtf(var + 1e-5f);
    float4 vv = ((const float4*)sbuf)[tid];
    float4 gg = ((const float4*)g)[tid];
    float4 bb = ((const float4*)b)[tid];
    float y0 = (vv.x - mu) * rstd * gg.x + bb.x;
    float y1 = (vv.y - mu) * rstd * gg.y + bb.y;
    float y2 = (vv.z - mu) * rstd * gg.z + bb.z;
    float y3 = (vv.w - mu) * rstd * gg.w + bb.w;
    uint32_t* w = (uint32_t*)o16;
    size_t wb = row * 512 + tid * 2;
    w[wb]     = pack_f16(y0, y1);
    w[wb + 1] = pack_f16(y2, y3);
}

// ================== bf16x3 mma.sync GEMM (QKV), 256x128 CTA tile ============
#define A_PL_B 20480u
#define B_PL_B 10240u
#define BSTAGE_B 61440u
#define BSTAGE_W 15360u
#define SMEM_BGEMM (2 * BSTAGE_B)         // 122880

__global__ __launch_bounds__(256) void mma_gemm_qkv(
    const uint16_t* __restrict__ Ahi, const uint16_t* __restrict__ Alo,
    const uint16_t* __restrict__ Bhi, const uint16_t* __restrict__ Blo,
    const float* __restrict__ bias, float* __restrict__ Cf, int N, int K)
{
    extern __shared__ uint32_t smu[];
    uint32_t su = smem_u32(smu);

    int tid = threadIdx.x;
    int wid = tid >> 5;
    int lane = tid & 31;
    int wm = wid & 3;
    int wn = wid >> 2;
    int bx = blockIdx.x, by = blockIdx.y;
    int gq = lane >> 2, tq = lane & 3;

    const uint16_t* aH = Ahi + (size_t)(by * 256 + tid) * K;
    const uint16_t* aL = Alo + (size_t)(by * 256 + tid) * K;
    int brow = tid >> 1;
    int bcp = (tid & 1) * 2;
    const uint16_t* bH = Bhi + (size_t)(bx * 128 + brow) * K;
    const uint16_t* bL = Blo + (size_t)(bx * 128 + brow) * K;

    #define BLOAD_STAGE(s, k0) do { \
        uint32_t _sb = su + (uint32_t)(s) * BSTAGE_B; \
        uint32_t _da = _sb + (uint32_t)tid * 80u; \
        _Pragma("unroll") \
        for (int c = 0; c < 4; c++) { \
            cpa16(_da + c * 16,           aH + (k0) + c * 8); \
            cpa16(_da + A_PL_B + c * 16,  aL + (k0) + c * 8); \
        } \
        uint32_t _db = _sb + 2 * A_PL_B + (uint32_t)brow * 80u + (uint32_t)bcp * 16u; \
        _Pragma("unroll") \
        for (int c = 0; c < 2; c++) { \
            cpa16(_db + c * 16,           bH + (k0) + (bcp + c) * 8); \
            cpa16(_db + B_PL_B + c * 16,  bL + (k0) + (bcp + c) * 8); \
        } \
        asm volatile("cp.async.commit_group;" ::: "memory"); \
    } while (0)

    float acc[4][8][4];
    #pragma unroll
    for (int mt = 0; mt < 4; mt++)
        #pragma unroll
        for (int nt = 0; nt < 8; nt++)
            #pragma unroll
            for (int i = 0; i < 4; i++) acc[mt][nt][i] = 0.f;

    int KT = K >> 5;
    BLOAD_STAGE(0, 0);

    int aBase0 = (wm * 64 + gq) * 20 + tq;
    int bBase0 = (wn * 64 + gq) * 20 + tq;

    for (int it = 0; it < KT; it++) {
        asm volatile("cp.async.wait_group 0;" ::: "memory");
        __syncthreads();
        if (it + 1 < KT) BLOAD_STAGE((it + 1) & 1, (it + 1) * 32);

        int s = it & 1;
        const uint32_t* ah_t = smu + s * BSTAGE_W;
        const uint32_t* al_t = ah_t + 5120;
        const uint32_t* bh_t = ah_t + 10240;
        const uint32_t* bl_t = ah_t + 12800;

        #pragma unroll
        for (int ks = 0; ks < 2; ks++) {
            int ko = ks * 8;
            uint32_t ah[4][4], al[4][4], bb[8][2];
            #pragma unroll
            for (int mt = 0; mt < 4; mt++) {
                int base = aBase0 + mt * 320 + ko;
                ah[mt][0] = ah_t[base];
                ah[mt][1] = ah_t[base + 160];
                ah[mt][2] = ah_t[base + 4];
                ah[mt][3] = ah_t[base + 164];
                al[mt][0] = al_t[base];
                al[mt][1] = al_t[base + 160];
                al[mt][2] = al_t[base + 4];
                al[mt][3] = al_t[base + 164];
            }
            #pragma unroll
            for (int nt = 0; nt < 8; nt++) {
                int base = bBase0 + nt * 160 + ko;
                bb[nt][0] = bh_t[base];
                bb[nt][1] = bh_t[base + 4];
            }
            #pragma unroll
            for (int mt = 0; mt < 4; mt++)
                #pragma unroll
                for (int nt = 0; nt < 8; nt++) {
                    mma_bf16(acc[mt][nt], ah[mt], bb[nt]);
                    mma_bf16(acc[mt][nt], al[mt], bb[nt]);
                }
            #pragma unroll
            for (int nt = 0; nt < 8; nt++) {
                int base = bBase0 + nt * 160 + ko;
                bb[nt][0] = bl_t[base];
                bb[nt][1] = bl_t[base + 4];
            }
            #pragma unroll
            for (int mt = 0; mt < 4; mt++)
                #pragma unroll
                for (int nt = 0; nt < 8; nt++)
                    mma_bf16(acc[mt][nt], ah[mt], bb[nt]);
        }
        __syncthreads();
    }

    #pragma unroll
    for (int mt = 0; mt < 4; mt++) {
        #pragma unroll
        for (int nt = 0; nt < 8; nt++) {
            int r0 = by * 256 + wm * 64 + mt * 16 + gq;
            int c0 = bx * 128 + wn * 64 + nt * 8 + tq * 2;
            float b0 = bias[c0], b1 = bias[c0 + 1];
            #pragma unroll
            for (int half = 0; half < 2; half++) {
                size_t r = r0 + half * 8;
                float2 o;
                o.x = acc[mt][nt][half * 2 + 0] + b0;
                o.y = acc[mt][nt][half * 2 + 1] + b1;
                *(float2*)(Cf + r * (size_t)N + c0) = o;
            }
        }
    }
}

// ================== fp16 single-pass mma.sync GEMM (MLP), 256x128 tile ======
// Proven R9 kernel. EPI: 1 = bias+GELU -> fp16 plane ; 2 = bias+res -> Cf
#define FA_PL_B 20480u
#define FSTAGE_B 30720u
#define FSTAGE_W 7680u
#define SMEM_FGEMM (2 * FSTAGE_B)         // 61440

template<int EPI>
__global__ __launch_bounds__(256) void mma_gemm_f16(
    const uint16_t* __restrict__ A, const uint16_t* __restrict__ B,
    const float* __restrict__ bias, const float* __restrict__ res,
    float* __restrict__ Cf, uint32_t* __restrict__ C16,
    int N, int K)
{
    extern __shared__ uint32_t smu[];
    uint32_t su = smem_u32(smu);

    int tid = threadIdx.x;
    int wid = tid >> 5;
    int lane = tid & 31;
    int wm = wid & 3;
    int wn = wid >> 2;
    int bx = blockIdx.x, by = blockIdx.y;
    int gq = lane >> 2, tq = lane & 3;

    const uint16_t* aP = A + (size_t)(by * 256 + tid) * K;
    int brow = tid >> 1;
    int bcp = (tid & 1) * 2;
    const uint16_t* bP = B + (size_t)(bx * 128 + brow) * K;

    #define FLOAD_STAGE(s, k0) do { \
        uint32_t _sb = su + (uint32_t)(s) * FSTAGE_B; \
        uint32_t _da = _sb + (uint32_t)tid * 80u; \
        _Pragma("unroll") \
        for (int c = 0; c < 4; c++) \
            cpa16(_da + c * 16, aP + (k0) + c * 8); \
        uint32_t _db = _sb + FA_PL_B + (uint32_t)brow * 80u + (uint32_t)bcp * 16u; \
        _Pragma("unroll") \
        for (int c = 0; c < 2; c++) \
            cpa16(_db + c * 16, bP + (k0) + (bcp + c) * 8); \
        asm volatile("cp.async.commit_group;" ::: "memory"); \
    } while (0)

    float acc[4][8][4];
    #pragma unroll
    for (int mt = 0; mt < 4; mt++)
        #pragma unroll
        for (int nt = 0; nt < 8; nt++)
            #pragma unroll
            for (int i = 0; i < 4; i++) acc[mt][nt][i] = 0.f;

    int KT = K >> 5;
    FLOAD_STAGE(0, 0);

    int aBase0 = (wm * 64 + gq) * 20 + tq;
    int bBase0 = (wn * 64 + gq) * 20 + tq;

    for (int it = 0; it < KT; it++) {
        asm volatile("cp.async.wait_group 0;" ::: "memory");
        __syncthreads();
        if (it + 1 < KT) FLOAD_STAGE((it + 1) & 1, (it + 1) * 32);

        int s = it & 1;
        const uint32_t* a_t = smu + s * FSTAGE_W;
        const uint32_t* b_t = a_t + 5120;

        #pragma unroll
        for (int ks = 0; ks < 2; ks++) {
            int ko = ks * 8;
            uint32_t ah[4][4], bb[8][2];
            #pragma unroll
            for (int mt = 0; mt < 4; mt++) {
                int base = aBase0 + mt * 320 + ko;
                ah[mt][0] = a_t[base];
                ah[mt][1] = a_t[base + 160];
                ah[mt][2] = a_t[base + 4];
                ah[mt][3] = a_t[base + 164];
            }
            #pragma unroll
            for (int nt = 0; nt < 8; nt++) {
                int base = bBase0 + nt * 160 + ko;
                bb[nt][0] = b_t[base];
                bb[nt][1] = b_t[base + 4];
            }
            #pragma unroll
            for (int mt = 0; mt < 4; mt++)
                #pragma unroll
                for (int nt = 0; nt < 8; nt++)
                    mma_f16(acc[mt][nt], ah[mt], bb[nt]);
        }
        __syncthreads();
    }

    #pragma unroll
    for (int mt = 0; mt < 4; mt++) {
        #pragma unroll
        for (int nt = 0; nt < 8; nt++) {
            int r0 = by * 256 + wm * 64 + mt * 16 + gq;
            int c0 = bx * 128 + wn * 64 + nt * 8 + tq * 2;
            float b0 = bias[c0], b1 = bias[c0 + 1];
            #pragma unroll
            for (int half = 0; half < 2; half++) {
                size_t r = r0 + half * 8;
                float v0 = acc[mt][nt][half * 2 + 0] + b0;
                float v1 = acc[mt][nt][half * 2 + 1] + b1;
                if (EPI == 1) {
                    v0 = 0.5f * v0 * (1.0f + erff(v0 * 0.70710678118654752f));
                    v1 = 0.5f * v1 * (1.0f + erff(v1 * 0.70710678118654752f));
                    C16[(r * (size_t)N + c0) >> 1] = pack_f16(v0, v1);
                } else {
                    float2 rv = *(const float2*)(res + r * (size_t)N + c0);
                    v0 += rv.x; v1 += rv.y;
                    float2 o; o.x = v0; o.y = v1;
                    *(float2*)(Cf + r * (size_t)N + c0) = o;
                }
            }
        }
    }
}

// ---------------- launch ----------------
extern "C" void kernel_launch(void* const* d_in, const int* in_sizes, int n_in,
                              void* d_out, int out_size)
{
    const float* x     = (const float*)d_in[0];
    const float* Wq    = (const float*)d_in[1];
    const float* bq    = (const float*)d_in[2];
    const float* Wk    = (const float*)d_in[3];
    const float* bk    = (const float*)d_in[4];
    const float* Wv    = (const float*)d_in[5];
    const float* bv    = (const float*)d_in[6];
    const float* ln1_g = (const float*)d_in[7];
    const float* ln1_b = (const float*)d_in[8];
    const float* ln2_g = (const float*)d_in[9];
    const float* ln2_b = (const float*)d_in[10];
    const float* W1    = (const float*)d_in[11];
    const float* b1    = (const float*)d_in[12];
    const float* W2    = (const float*)d_in[13];
    const float* b2    = (const float*)d_in[14];
    float* out = (float*)d_out;

    uint16_t *hHi, *hLo, *WqkvHi, *WqkvLo, *W116, *W216, *h216, *m116;
    float *qkv, *xmid, *bqkv;
    cudaGetSymbolAddress((void**)&hHi,    g_h_hi);
    cudaGetSymbolAddress((void**)&hLo,    g_h_lo);
    cudaGetSymbolAddress((void**)&WqkvHi, g_Wqkv_hi);
    cudaGetSymbolAddress((void**)&WqkvLo, g_Wqkv_lo);
    cudaGetSymbolAddress((void**)&W116,   g_W116);
    cudaGetSymbolAddress((void**)&W216,   g_W216);
    cudaGetSymbolAddress((void**)&h216,   g_h216);
    cudaGetSymbolAddress((void**)&m116,   g_m116);
    cudaGetSymbolAddress((void**)&qkv,    g_qkv);
    cudaGetSymbolAddress((void**)&xmid,   g_xmid);
    cudaGetSymbolAddress((void**)&bqkv,   g_bqkv);

    cudaFuncSetAttribute(mma_gemm_qkv, cudaFuncAttributeMaxDynamicSharedMemorySize, SMEM_BGEMM);
    cudaFuncSetAttribute(mma_gemm_f16<1>, cudaFuncAttributeMaxDynamicSharedMemorySize, SMEM_FGEMM);
    cudaFuncSetAttribute(mma_gemm_f16<2>, cudaFuncAttributeMaxDynamicSharedMemorySize, SMEM_FGEMM);

    init_tw_kernel<<<1, 512>>>();
    bias_concat_kernel<<<NQKV / 256, 256>>>(bq, bk, bv);

    // QKV weights -> bf16 hi/lo planes; MLP weights -> fp16
    transpose_split_kernel<<<dim3(32, 32), dim3(32, 8)>>>(Wq, WqkvHi, WqkvLo, DIM, DIM);
    transpose_split_kernel<<<dim3(32, 32), dim3(32, 8)>>>(Wk, WqkvHi + (size_t)1024 * DIM, WqkvLo + (size_t)1024 * DIM, DIM, DIM);
    transpose_split_kernel<<<dim3(32, 32), dim3(32, 8)>>>(Wv, WqkvHi + (size_t)2048 * DIM, WqkvLo + (size_t)2048 * DIM, DIM, DIM);
    transpose_f16_kernel<<<dim3(128, 32), dim3(32, 8)>>>(W1, W116, DIM, HID);
    transpose_f16_kernel<<<dim3(32, 128), dim3(32, 8)>>>(W2, W216, HID, DIM);

    // LN1 -> bf16 planes
    ln_split_kernel<<<NROW, 256>>>(x, ln1_g, ln1_b, hHi, hLo);

    // fused QKV projection (bf16x3, high precision for the amplified path)
    mma_gemm_qkv<<<dim3(NQKV / 128, NROW / 256), 256, SMEM_BGEMM>>>(
        hHi, hLo, WqkvHi, WqkvLo, bqkv, qkv, NQKV, DIM);

    // fused FFT + normalize for q,k,v
    fft_qkv_kernel<<<NROW, 256>>>();

    // causal cumsum in Fourier domain, fused * conj(Q̂)
    chain_partial_kernel<<<(NBATCH * CHUNKS * DIM) / 256, 256>>>();
    chain_apply_kernel<<<(NBATCH * CHUNKS * DIM) / 256, 256>>>();

    // inverse FFT + residual + LN2 (emits xmid fp32 + h2 fp16 plane)
    ifft_res_ln_kernel<<<NROW, 256>>>(x, ln2_g, ln2_b, h216);

    // MLP (fp16 single-pass)
    mma_gemm_f16<1><<<dim3(HID / 128, NROW / 256), 256, SMEM_FGEMM>>>(
        h216, W116, b1, nullptr, nullptr, (uint32_t*)m116, HID, DIM);
    mma_gemm_f16<2><<<dim3(DIM / 128, NROW / 256), 256, SMEM_FGEMM>>>(
        m116, W216, b2, xmid, out, nullptr, DIM, HID);

    (void)in_sizes; (void)n_in; (void)out_size;
}

// round 13
// speedup vs baseline: 3.4392x; 1.0280x over previous
#include <cuda_runtime.h>
#include <cuda_fp16.h>
#include <math.h>
#include <math_constants.h>
#include <stdint.h>

#define NROW 8192   // B*S
#define DIM  1024
#define SEQ  2048
#define NBATCH 4
#define HID  4096
#define CHUNKS 16
#define TCHUNK (SEQ / CHUNKS)   // 128
#define NQKV 3072

// ---------------- scratch (static device globals; no runtime alloc) ----------
__device__ uint16_t g_h_hi[(size_t)NROW * DIM];      // bf16 planes (QKV path)
__device__ uint16_t g_h_lo[(size_t)NROW * DIM];
__device__ uint16_t g_Wqkv_hi[(size_t)NQKV * DIM];
__device__ uint16_t g_Wqkv_lo[(size_t)NQKV * DIM];
__device__ uint16_t g_W116[(size_t)HID * DIM];       // fp16 transposed weights
__device__ uint16_t g_W216[(size_t)DIM * HID];
__device__ uint16_t g_h216[(size_t)NROW * DIM];      // fp16 h2
__device__ uint16_t g_m116[(size_t)NROW * HID];      // fp16 m1
__device__ float  g_qkv[(size_t)NROW * NQKV];
__device__ float  g_bqkv[NQKV];
__device__ float2 g_Qhat[(size_t)NROW * DIM];
__device__ float2 g_Mhat[(size_t)NROW * DIM];
__device__ float  g_xmid[(size_t)NROW * DIM];
__device__ float2 g_tw[512];
__device__ float2 g_part[NBATCH * CHUNKS * DIM];

// ---------------- helpers ----------------
__device__ __forceinline__ uint32_t smem_u32(const void* p) {
    uint32_t a;
    asm("{ .reg .u64 t; cvta.to.shared.u64 t, %1; cvt.u32.u64 %0, t; }" : "=r"(a) : "l"(p));
    return a;
}
__device__ __forceinline__ uint32_t pack_f16(float x0, float x1) {
    uint32_t h;
    asm("cvt.rn.f16x2.f32 %0, %1, %2;" : "=r"(h) : "f"(x1), "f"(x0));
    return h;
}
// split pair (x0,x1) -> packed bf16x2 hi (low half = x0) and lo
__device__ __forceinline__ void split2(float x0, float x1, uint32_t& hi, uint32_t& lo) {
    uint32_t h;
    asm("cvt.rn.bf16x2.f32 %0, %1, %2;" : "=r"(h) : "f"(x1), "f"(x0));
    float h0 = __uint_as_float(h << 16);
    float h1 = __uint_as_float(h & 0xFFFF0000u);
    float l0 = x0 - h0;
    float l1 = x1 - h1;
    asm("cvt.rn.bf16x2.f32 %0, %1, %2;" : "=r"(lo) : "f"(l1), "f"(l0));
    hi = h;
}
__device__ __forceinline__ void mma_bf16(float* d, const uint32_t* a, const uint32_t* b) {
    asm volatile("mma.sync.aligned.m16n8k16.row.col.f32.bf16.bf16.f32 "
        "{%0,%1,%2,%3}, {%4,%5,%6,%7}, {%8,%9}, {%0,%1,%2,%3};"
        : "+f"(d[0]), "+f"(d[1]), "+f"(d[2]), "+f"(d[3])
        : "r"(a[0]), "r"(a[1]), "r"(a[2]), "r"(a[3]), "r"(b[0]), "r"(b[1]));
}
__device__ __forceinline__ void mma_f16(float* d, const uint32_t* a, const uint32_t* b) {
    asm volatile("mma.sync.aligned.m16n8k16.row.col.f32.f16.f16.f32 "
        "{%0,%1,%2,%3}, {%4,%5,%6,%7}, {%8,%9}, {%0,%1,%2,%3};"
        : "+f"(d[0]), "+f"(d[1]), "+f"(d[2]), "+f"(d[3])
        : "r"(a[0]), "r"(a[1]), "r"(a[2]), "r"(a[3]), "r"(b[0]), "r"(b[1]));
}
__device__ __forceinline__ void cpa16(uint32_t dst, const void* src) {
    asm volatile("cp.async.cg.shared.global [%0], [%1], 16;" :: "r"(dst), "l"(src) : "memory");
}
__device__ __forceinline__ float2 c_add(float2 a, float2 b){return make_float2(a.x+b.x,a.y+b.y);}
__device__ __forceinline__ float2 c_sub(float2 a, float2 b){return make_float2(a.x-b.x,a.y-b.y);}
__device__ __forceinline__ float2 c_mul(float2 a, float2 b){return make_float2(a.x*b.x-a.y*b.y,a.x*b.y+a.y*b.x);}
__device__ __forceinline__ float2 c_negi(float2 a){return make_float2(a.y,-a.x);}
__device__ __forceinline__ float2 c_norm(float2 f) {
    float inv = 1.0f / fmaxf(sqrtf(f.x * f.x + f.y * f.y), 1e-8f);
    return make_float2(f.x * inv, f.y * inv);
}

// ---------------- small init kernels ----------------
__global__ void init_tw_kernel() {
    int i = threadIdx.x;
    double th = -2.0 * CUDART_PI * (double)i / 1024.0;
    g_tw[i] = make_float2((float)cos(th), (float)sin(th));
}
__global__ void bias_concat_kernel(const float* bq, const float* bk, const float* bv) {
    int i = blockIdx.x * 256 + threadIdx.x;
    float v = (i < 1024) ? bq[i] : (i < 2048) ? bk[i - 1024] : bv[i - 2048];
    g_bqkv[i] = v;
}

// ---------------- weight transpose + bf16 split (QKV) ----------------
__global__ __launch_bounds__(256) void transpose_split_kernel(
    const float* __restrict__ in, uint16_t* __restrict__ ohi,
    uint16_t* __restrict__ olo, int R, int C)
{
    __shared__ float t[32][33];
    int bx = blockIdx.x, by = blockIdx.y;
    int x = bx * 32 + threadIdx.x;
    int y0 = by * 32 + threadIdx.y;
    #pragma unroll
    for (int j = 0; j < 32; j += 8)
        t[threadIdx.y + j][threadIdx.x] = in[(size_t)(y0 + j) * C + x];
    __syncthreads();
    int tl = threadIdx.y * 32 + threadIdx.x;
    int kp = tl & 15;
    int nr0 = tl >> 4;
    uint32_t* hw32 = (uint32_t*)ohi;
    uint32_t* lw32 = (uint32_t*)olo;
    #pragma unroll
    for (int rep = 0; rep < 2; rep++) {
        int nrel = nr0 + rep * 16;
        size_t n = (size_t)bx * 32 + nrel;
        int kg = by * 32 + kp * 2;
        uint32_t hw, lw;
        split2(t[kp * 2][nrel], t[kp * 2 + 1][nrel], hw, lw);
        size_t widx = (n * (size_t)R + kg) >> 1;
        hw32[widx] = hw;
        lw32[widx] = lw;
    }
}

// ---------------- weight transpose to fp16 (MLP) ----------------
__global__ __launch_bounds__(256) void transpose_f16_kernel(
    const float* __restrict__ in, uint16_t* __restrict__ o16, int R, int C)
{
    __shared__ float t[32][33];
    int bx = blockIdx.x, by = blockIdx.y;
    int x = bx * 32 + threadIdx.x;
    int y0 = by * 32 + threadIdx.y;
    #pragma unroll
    for (int j = 0; j < 32; j += 8)
        t[threadIdx.y + j][threadIdx.x] = in[(size_t)(y0 + j) * C + x];
    __syncthreads();
    int tl = threadIdx.y * 32 + threadIdx.x;
    int kp = tl & 15;
    int nr0 = tl >> 4;
    uint32_t* w32 = (uint32_t*)o16;
    #pragma unroll
    for (int rep = 0; rep < 2; rep++) {
        int nrel = nr0 + rep * 16;
        size_t n = (size_t)bx * 32 + nrel;
        int kg = by * 32 + kp * 2;
        w32[(n * (size_t)R + kg) >> 1] = pack_f16(t[kp * 2][nrel], t[kp * 2 + 1][nrel]);
    }
}

// ---------------- block reductions ----------------
__device__ __forceinline__ float2 block_reduce2(float2 v, float2* sh) {
    int tid = threadIdx.x;
    sh[tid] = v;
    __syncthreads();
    #pragma unroll
    for (int s = 128; s > 0; s >>= 1) {
        if (tid < s) {
            sh[tid].x += sh[tid + s].x;
            sh[tid].y += sh[tid + s].y;
        }
        __syncthreads();
    }
    float2 r = sh[0];
    __syncthreads();
    return r;
}
__device__ __forceinline__ float4 block_reduce4(float4 v, float4* sh) {
    int tid = threadIdx.x;
    sh[tid] = v;
    __syncthreads();
    #pragma unroll
    for (int s = 128; s > 0; s >>= 1) {
        if (tid < s) {
            sh[tid].x += sh[tid + s].x;
            sh[tid].y += sh[tid + s].y;
            sh[tid].z += sh[tid + s].z;
            sh[tid].w += sh[tid + s].w;
        }
        __syncthreads();
    }
    float4 r = sh[0];
    __syncthreads();
    return r;
}

// ---------------- LayerNorm 1 -> bf16 hi/lo planes ----------------
__global__ __launch_bounds__(256) void ln_split_kernel(
    const float* __restrict__ x, const float* __restrict__ g,
    const float* __restrict__ b, uint16_t* __restrict__ ohi,
    uint16_t* __restrict__ olo)
{
    __shared__ float2 red[256];
    size_t row = blockIdx.x;
    int tid = threadIdx.x;
    float4 v = ((const float4*)(x + row * DIM))[tid];
    float s = v.x + v.y + v.z + v.w;
    float ss = v.x * v.x + v.y * v.y + v.z * v.z + v.w * v.w;
    float2 tot = block_reduce2(make_float2(s, ss), red);
    float mu = tot.x * (1.0f / DIM);
    float var = tot.y * (1.0f / DIM) - mu * mu;
    float rstd = rsqrtf(var + 1e-5f);
    float4 gg = ((const float4*)g)[tid];
    float4 bb = ((const float4*)b)[tid];
    float y0 = (v.x - mu) * rstd * gg.x + bb.x;
    float y1 = (v.y - mu) * rstd * gg.y + bb.y;
    float y2 = (v.z - mu) * rstd * gg.z + bb.z;
    float y3 = (v.w - mu) * rstd * gg.w + bb.w;
    uint32_t h0, l0, h1, l1;
    split2(y0, y1, h0, l0);
    split2(y2, y3, h1, l1);
    uint32_t* hw = (uint32_t*)ohi;
    uint32_t* lw = (uint32_t*)olo;
    size_t wb = row * 512 + tid * 2;
    hw[wb] = h0; hw[wb + 1] = h1;
    lw[wb] = l0; lw[wb + 1] = l1;
}

// -------- 1024-pt radix-4 Stockham FFT, bank-conflict-free swizzles --------
__device__ __forceinline__ int swz(int g, int a) {
    if (g == 1) return a ^ ((a >> 4) & 3);
    if (g == 2) return a ^ ((a >> 2) & 0xC);
    return a;
}
__device__ __forceinline__ float2* fft1024(float2* bufA, float2* bufB) {
    float2* x = bufA;
    float2* y = bufB;
    int n4 = 256, s = 1;
    #pragma unroll
    for (int st = 0; st < 5; st++) {
        __syncthreads();
        int i = threadIdx.x;
        int p = i / s;
        int q = i - p * s;
        float2 w1 = g_tw[p * s];
        float2 w2 = g_tw[2 * p * s];
        float2 x0 = x[swz(st, q + s * p)];
        float2 x1 = x[swz(st, q + s * (p + n4))];
        float2 x2 = x[swz(st, q + s * (p + 2 * n4))];
        float2 x3 = x[swz(st, q + s * (p + 3 * n4))];
        float2 za0 = c_add(x0, x2);
        float2 za1 = c_mul(c_sub(x0, x2), w1);
        float2 zb0 = c_add(x1, x3);
        float2 zb1 = c_mul(c_negi(c_sub(x1, x3)), w1);
        int ob = q + s * 4 * p;
        y[swz(st + 1, ob)]         = c_add(za0, zb0);
        y[swz(st + 1, ob + s)]     = c_add(za1, zb1);
        y[swz(st + 1, ob + 2 * s)] = c_mul(c_sub(za0, zb0), w2);
        y[swz(st + 1, ob + 3 * s)] = c_mul(c_sub(za1, zb1), w2);
        float2* t = x; x = y; y = t;
        n4 >>= 2; s <<= 2;
    }
    __syncthreads();
    return x;
}

// -------- fused QKV FFT, 2 rows/block via real-packing -----------------
// FFT(q+ik) -> Q̂,K̂ by Hermitian split; FFT(v0+iv1) -> V̂0,V̂1.
// 3 FFTs per 2 rows. Scale factor 2 cancels in unit-normalization.
__global__ __launch_bounds__(256) void fft_qkv_pair_kernel() {
    __shared__ __align__(16) float2 bufA[1024];
    __shared__ __align__(16) float2 bufB[1024];
    __shared__ __align__(16) float2 kb0[1024];
    __shared__ __align__(16) float2 kb1[1024];
    size_t row0 = (size_t)blockIdx.x * 2;
    size_t row1 = row0 + 1;
    int tid = threadIdx.x;
    const float* b0 = g_qkv + row0 * NQKV;
    const float* b1 = g_qkv + row1 * NQKV;

    // --- FFT 1: q0 + i*k0 ---
    #pragma unroll
    for (int j = 0; j < 4; j++) {
        int idx = tid + j * 256;
        bufA[idx] = make_float2(b0[idx], b0[1024 + idx]);
    }
    float2* res = fft1024(bufA, bufB);
    float2* qp0 = g_Qhat + row0 * DIM;
    #pragma unroll
    for (int j = 0; j < 4; j++) {
        int idx = tid + j * 256;
        int midx = (1024 - idx) & 1023;
        float2 Zc = res[idx];
        float2 Zm = res[midx];
        float2 fq = make_float2(Zc.x + Zm.x, Zc.y - Zm.y);
        float2 fk = make_float2(Zc.y + Zm.y, Zm.x - Zc.x);
        qp0[idx] = c_norm(fq);
        kb0[idx] = c_norm(fk);
    }
    __syncthreads();

    // --- FFT 2: q1 + i*k1 ---
    #pragma unroll
    for (int j = 0; j < 4; j++) {
        int idx = tid + j * 256;
        bufA[idx] = make_float2(b1[idx], b1[1024 + idx]);
    }
    res = fft1024(bufA, bufB);
    float2* qp1 = g_Qhat + row1 * DIM;
    #pragma unroll
    for (int j = 0; j < 4; j++) {
        int idx = tid + j * 256;
        int midx = (1024 - idx) & 1023;
        float2 Zc = res[idx];
        float2 Zm = res[midx];
        float2 fq = make_float2(Zc.x + Zm.x, Zc.y - Zm.y);
        float2 fk = make_float2(Zc.y + Zm.y, Zm.x - Zc.x);
        qp1[idx] = c_norm(fq);
        kb1[idx] = c_norm(fk);
    }
    __syncthreads();

    // --- FFT 3: v0 + i*v1 ---
    #pragma unroll
    for (int j = 0; j < 4; j++) {
        int idx = tid + j * 256;
        bufA[idx] = make_float2(b0[2048 + idx], b1[2048 + idx]);
    }
    res = fft1024(bufA, bufB);
    float2* mp0 = g_Mhat + row0 * DIM;
    float2* mp1 = g_Mhat + row1 * DIM;
    #pragma unroll
    for (int j = 0; j < 4; j++) {
        int idx = tid + j * 256;
        int midx = (1024 - idx) & 1023;
        float2 Zc = res[idx];
        float2 Zm = res[midx];
        float2 v0 = c_norm(make_float2(Zc.x + Zm.x, Zc.y - Zm.y));
        float2 v1 = c_norm(make_float2(Zc.y + Zm.y, Zm.x - Zc.x));
        mp0[idx] = c_mul(kb0[idx], v0);
        mp1[idx] = c_mul(kb1[idx], v1);
    }
}

// ---------------- chain pass A: per-chunk partial sums ----------------
__global__ __launch_bounds__(256) void chain_partial_kernel() {
    int gid = blockIdx.x * 256 + threadIdx.x;
    int bin = gid & 1023;
    int chunk = (gid >> 10) & (CHUNKS - 1);
    int b = gid >> 14;
    size_t base = ((size_t)b * SEQ + (size_t)chunk * TCHUNK) * DIM + bin;
    float2 s = make_float2(0.f, 0.f);
    #pragma unroll 4
    for (int i = 0; i < TCHUNK; i++) {
        float2 p = g_Mhat[base + (size_t)i * DIM];
        s.x += p.x; s.y += p.y;
    }
    g_part[gid] = s;
}

// ---------------- chain pass B: scan within chunk + apply conj(Q̂) --------
__global__ __launch_bounds__(256) void chain_apply_kernel() {
    int gid = blockIdx.x * 256 + threadIdx.x;
    int bin = gid & 1023;
    int chunk = (gid >> 10) & (CHUNKS - 1);
    int b = gid >> 14;
    float2 acc = make_float2(0.f, 0.f);
    for (int c = 0; c < chunk; c++) {
        float2 p = g_part[((b * CHUNKS) + c) * 1024 + bin];
        acc.x += p.x; acc.y += p.y;
    }
    size_t base = ((size_t)b * SEQ + (size_t)chunk * TCHUNK) * DIM + bin;
    #pragma unroll 4
    for (int i = 0; i < TCHUNK; i++) {
        size_t off = base + (size_t)i * DIM;
        float2 p = g_Mhat[off];
        acc.x += p.x; acc.y += p.y;
        float2 q = g_Qhat[off];
        g_Mhat[off] = make_float2(acc.x * q.x + acc.y * q.y,
                                  acc.y * q.x - acc.x * q.y);
    }
}

// ------- paired inverse FFT + residual + LN2 (2 rows per block) --------
// M̂ rows are Hermitian -> ifft real -> fft(conj(M0)+i*conj(M1)) = N*(r0+i*r1)
__global__ __launch_bounds__(256) void ifft_res_ln_pair_kernel(
    const float* __restrict__ x, const float* __restrict__ g,
    const float* __restrict__ b, uint16_t* __restrict__ o16)
{
    __shared__ __align__(16) float2 bufA[1024];
    __shared__ __align__(16) float2 bufB[1024];
    size_t row0 = (size_t)blockIdx.x * 2;
    size_t row1 = row0 + 1;
    int tid = threadIdx.x;
    const float2* m0 = g_Mhat + row0 * DIM;
    const float2* m1 = g_Mhat + row1 * DIM;
    #pragma unroll
    for (int j = 0; j < 4; j++) {
        int idx = tid + j * 256;
        float2 a = m0[idx];
        float2 c = m1[idx];
        // conj(M0) + i*conj(M1) = (M0.x + M1.y, -M0.y + M1.x)
        bufA[idx] = make_float2(a.x + c.y, c.x - a.y);
    }
    float2* res = fft1024(bufA, bufB);   // = bufB; Y = N*(r0 + i*r1)
    float mixed0[4], mixed1[4];
    #pragma unroll
    for (int j = 0; j < 4; j++) {
        float2 Y = res[tid + j * 256];
        mixed0[j] = Y.x * (1.0f / 1024.0f);
        mixed1[j] = Y.y * (1.0f / 1024.0f);
    }
    __syncthreads();
    float* s0 = (float*)bufA;            // bufA dead: stash both rows
    float* s1 = s0 + 1024;
    const float* xp0 = x + row0 * DIM;
    const float* xp1 = x + row1 * DIM;
    float* xo0 = g_xmid + row0 * DIM;
    float* xo1 = g_xmid + row1 * DIM;
    float su0 = 0.f, ss0 = 0.f, su1 = 0.f, ss1 = 0.f;
    #pragma unroll
    for (int j = 0; j < 4; j++) {
        int idx = tid + j * 256;
        float v0 = xp0[idx] + mixed0[j];
        float v1 = xp1[idx] + mixed1[j];
        xo0[idx] = v0; s0[idx] = v0;
        xo1[idx] = v1; s1[idx] = v1;
        su0 += v0; ss0 += v0 * v0;
        su1 += v1; ss1 += v1 * v1;
    }
    __syncthreads();                     // res reads done before bufB reuse
    float4 tot = block_reduce4(make_float4(su0, ss0, su1, ss1), (float4*)bufB);
    float mu0 = tot.x * (1.0f / DIM);
    float rstd0 = rsqrtf(tot.y * (1.0f / DIM) - mu0 * mu0 + 1e-5f);
    float mu1 = tot.z * (1.0f / DIM);
    float rstd1 = rsqrtf(tot.w * (1.0f / DIM) - mu1 * mu1 + 1e-5f);
    float4 gg = ((const float4*)g)[tid];
    float4 bb = ((const float4*)b)[tid];
    uint32_t* w = (uint32_t*)o16;
    {
        float4 vv = ((const float4*)s0)[tid];
        float y0 = (vv.x - mu0) * rstd0 * gg.x + bb.x;
        float y1 = (vv.y - mu0) * rstd0 * gg.y + bb.y;
        float y2 = (vv.z - mu0) * rstd0 * gg.z + bb.z;
        float y3 = (vv.w - mu0) * rstd0 * gg.w + bb.w;
        size_t wb = row0 * 512 + tid * 2;
        w[wb]     = pack_f16(y0, y1);
        w[wb + 1] = pack_f16(y2, y3);
    }
    {
        float4 vv = ((const float4*)s1)[tid];
        float y0 = (vv.x - mu1) * rstd1 * gg.x + bb.x;
        float y1 = (vv.y - mu1) * rstd1 * gg.y + bb.y;
        float y2 = (vv.z - mu1) * rstd1 * gg.z + bb.z;
        float y3 = (vv.w - mu1) * rstd1 * gg.w + bb.w;
        size_t wb = row1 * 512 + tid * 2;
        w[wb]     = pack_f16(y0, y1);
        w[wb + 1] = pack_f16(y2, y3);
    }
}

// ================== bf16x3 mma.sync GEMM (QKV), 256x128 CTA tile ============
#define A_PL_B 20480u
#define B_PL_B 10240u
#define BSTAGE_B 61440u
#define BSTAGE_W 15360u
#define SMEM_BGEMM (2 * BSTAGE_B)         // 122880

__global__ __launch_bounds__(256) void mma_gemm_qkv(
    const uint16_t* __restrict__ Ahi, const uint16_t* __restrict__ Alo,
    const uint16_t* __restrict__ Bhi, const uint16_t* __restrict__ Blo,
    const float* __restrict__ bias, float* __restrict__ Cf, int N, int K)
{
    extern __shared__ uint32_t smu[];
    uint32_t su = smem_u32(smu);

    int tid = threadIdx.x;
    int wid = tid >> 5;
    int lane = tid & 31;
    int wm = wid & 3;
    int wn = wid >> 2;
    int bx = blockIdx.x, by = blockIdx.y;
    int gq = lane >> 2, tq = lane & 3;

    const uint16_t* aH = Ahi + (size_t)(by * 256 + tid) * K;
    const uint16_t* aL = Alo + (size_t)(by * 256 + tid) * K;
    int brow = tid >> 1;
    int bcp = (tid & 1) * 2;
    const uint16_t* bH = Bhi + (size_t)(bx * 128 + brow) * K;
    const uint16_t* bL = Blo + (size_t)(bx * 128 + brow) * K;

    #define BLOAD_STAGE(s, k0) do { \
        uint32_t _sb = su + (uint32_t)(s) * BSTAGE_B; \
        uint32_t _da = _sb + (uint32_t)tid * 80u; \
        _Pragma("unroll") \
        for (int c = 0; c < 4; c++) { \
            cpa16(_da + c * 16,           aH + (k0) + c * 8); \
            cpa16(_da + A_PL_B + c * 16,  aL + (k0) + c * 8); \
        } \
        uint32_t _db = _sb + 2 * A_PL_B + (uint32_t)brow * 80u + (uint32_t)bcp * 16u; \
        _Pragma("unroll") \
        for (int c = 0; c < 2; c++) { \
            cpa16(_db + c * 16,           bH + (k0) + (bcp + c) * 8); \
            cpa16(_db + B_PL_B + c * 16,  bL + (k0) + (bcp + c) * 8); \
        } \
        asm volatile("cp.async.commit_group;" ::: "memory"); \
    } while (0)

    float acc[4][8][4];
    #pragma unroll
    for (int mt = 0; mt < 4; mt++)
        #pragma unroll
        for (int nt = 0; nt < 8; nt++)
            #pragma unroll
            for (int i = 0; i < 4; i++) acc[mt][nt][i] = 0.f;

    int KT = K >> 5;
    BLOAD_STAGE(0, 0);

    int aBase0 = (wm * 64 + gq) * 20 + tq;
    int bBase0 = (wn * 64 + gq) * 20 + tq;

    for (int it = 0; it < KT; it++) {
        asm volatile("cp.async.wait_group 0;" ::: "memory");
        __syncthreads();
        if (it + 1 < KT) BLOAD_STAGE((it + 1) & 1, (it + 1) * 32);

        int s = it & 1;
        const uint32_t* ah_t = smu + s * BSTAGE_W;
        const uint32_t* al_t = ah_t + 5120;
        const uint32_t* bh_t = ah_t + 10240;
        const uint32_t* bl_t = ah_t + 12800;

        #pragma unroll
        for (int ks = 0; ks < 2; ks++) {
            int ko = ks * 8;
            uint32_t ah[4][4], al[4][4], bb[8][2];
            #pragma unroll
            for (int mt = 0; mt < 4; mt++) {
                int base = aBase0 + mt * 320 + ko;
                ah[mt][0] = ah_t[base];
                ah[mt][1] = ah_t[base + 160];
                ah[mt][2] = ah_t[base + 4];
                ah[mt][3] = ah_t[base + 164];
                al[mt][0] = al_t[base];
                al[mt][1] = al_t[base + 160];
                al[mt][2] = al_t[base + 4];
                al[mt][3] = al_t[base + 164];
            }
            #pragma unroll
            for (int nt = 0; nt < 8; nt++) {
                int base = bBase0 + nt * 160 + ko;
                bb[nt][0] = bh_t[base];
                bb[nt][1] = bh_t[base + 4];
            }
            #pragma unroll
            for (int mt = 0; mt < 4; mt++)
                #pragma unroll
                for (int nt = 0; nt < 8; nt++) {
                    mma_bf16(acc[mt][nt], ah[mt], bb[nt]);
                    mma_bf16(acc[mt][nt], al[mt], bb[nt]);
                }
            #pragma unroll
            for (int nt = 0; nt < 8; nt++) {
                int base = bBase0 + nt * 160 + ko;
                bb[nt][0] = bl_t[base];
                bb[nt][1] = bl_t[base + 4];
            }
            #pragma unroll
            for (int mt = 0; mt < 4; mt++)
                #pragma unroll
                for (int nt = 0; nt < 8; nt++)
                    mma_bf16(acc[mt][nt], ah[mt], bb[nt]);
        }
        __syncthreads();
    }

    #pragma unroll
    for (int mt = 0; mt < 4; mt++) {
        #pragma unroll
        for (int nt = 0; nt < 8; nt++) {
            int r0 = by * 256 + wm * 64 + mt * 16 + gq;
            int c0 = bx * 128 + wn * 64 + nt * 8 + tq * 2;
            float b0 = bias[c0], b1 = bias[c0 + 1];
            #pragma unroll
            for (int half = 0; half < 2; half++) {
                size_t r = r0 + half * 8;
                float2 o;
                o.x = acc[mt][nt][half * 2 + 0] + b0;
                o.y = acc[mt][nt][half * 2 + 1] + b1;
                *(float2*)(Cf + r * (size_t)N + c0) = o;
            }
        }
    }
}

// ================== fp16 single-pass mma.sync GEMM (MLP), 256x128 tile ======
#define FA_PL_B 20480u
#define FSTAGE_B 30720u
#define FSTAGE_W 7680u
#define SMEM_FGEMM (2 * FSTAGE_B)         // 61440

template<int EPI>
__global__ __launch_bounds__(256) void mma_gemm_f16(
    const uint16_t* __restrict__ A, const uint16_t* __restrict__ B,
    const float* __restrict__ bias, const float* __restrict__ res,
    float* __restrict__ Cf, uint32_t* __restrict__ C16,
    int N, int K)
{
    extern __shared__ uint32_t smu[];
    uint32_t su = smem_u32(smu);

    int tid = threadIdx.x;
    int wid = tid >> 5;
    int lane = tid & 31;
    int wm = wid & 3;
    int wn = wid >> 2;
    int bx = blockIdx.x, by = blockIdx.y;
    int gq = lane >> 2, tq = lane & 3;

    const uint16_t* aP = A + (size_t)(by * 256 + tid) * K;
    int brow = tid >> 1;
    int bcp = (tid & 1) * 2;
    const uint16_t* bP = B + (size_t)(bx * 128 + brow) * K;

    #define FLOAD_STAGE(s, k0) do { \
        uint32_t _sb = su + (uint32_t)(s) * FSTAGE_B; \
        uint32_t _da = _sb + (uint32_t)tid * 80u; \
        _Pragma("unroll") \
        for (int c = 0; c < 4; c++) \
            cpa16(_da + c * 16, aP + (k0) + c * 8); \
        uint32_t _db = _sb + FA_PL_B + (uint32_t)brow * 80u + (uint32_t)bcp * 16u; \
        _Pragma("unroll") \
        for (int c = 0; c < 2; c++) \
            cpa16(_db + c * 16, bP + (k0) + (bcp + c) * 8); \
        asm volatile("cp.async.commit_group;" ::: "memory"); \
    } while (0)

    float acc[4][8][4];
    #pragma unroll
    for (int mt = 0; mt < 4; mt++)
        #pragma unroll
        for (int nt = 0; nt < 8; nt++)
            #pragma unroll
            for (int i = 0; i < 4; i++) acc[mt][nt][i] = 0.f;

    int KT = K >> 5;
    FLOAD_STAGE(0, 0);

    int aBase0 = (wm * 64 + gq) * 20 + tq;
    int bBase0 = (wn * 64 + gq) * 20 + tq;

    for (int it = 0; it < KT; it++) {
        asm volatile("cp.async.wait_group 0;" ::: "memory");
        __syncthreads();
        if (it + 1 < KT) FLOAD_STAGE((it + 1) & 1, (it + 1) * 32);

        int s = it & 1;
        const uint32_t* a_t = smu + s * FSTAGE_W;
        const uint32_t* b_t = a_t + 5120;

        #pragma unroll
        for (int ks = 0; ks < 2; ks++) {
            int ko = ks * 8;
            uint32_t ah[4][4], bb[8][2];
            #pragma unroll
            for (int mt = 0; mt < 4; mt++) {
                int base = aBase0 + mt * 320 + ko;
                ah[mt][0] = a_t[base];
                ah[mt][1] = a_t[base + 160];
                ah[mt][2] = a_t[base + 4];
                ah[mt][3] = a_t[base + 164];
            }
            #pragma unroll
            for (int nt = 0; nt < 8; nt++) {
                int base = bBase0 + nt * 160 + ko;
                bb[nt][0] = b_t[base];
                bb[nt][1] = b_t[base + 4];
            }
            #pragma unroll
            for (int mt = 0; mt < 4; mt++)
                #pragma unroll
                for (int nt = 0; nt < 8; nt++)
                    mma_f16(acc[mt][nt], ah[mt], bb[nt]);
        }
        __syncthreads();
    }

    #pragma unroll
    for (int mt = 0; mt < 4; mt++) {
        #pragma unroll
        for (int nt = 0; nt < 8; nt++) {
            int r0 = by * 256 + wm * 64 + mt * 16 + gq;
            int c0 = bx * 128 + wn * 64 + nt * 8 + tq * 2;
            float b0 = bias[c0], b1 = bias[c0 + 1];
            #pragma unroll
            for (int half = 0; half < 2; half++) {
                size_t r = r0 + half * 8;
                float v0 = acc[mt][nt][half * 2 + 0] + b0;
                float v1 = acc[mt][nt][half * 2 + 1] + b1;
                if (EPI == 1) {
                    v0 = 0.5f * v0 * (1.0f + erff(v0 * 0.70710678118654752f));
                    v1 = 0.5f * v1 * (1.0f + erff(v1 * 0.70710678118654752f));
                    C16[(r * (size_t)N + c0) >> 1] = pack_f16(v0, v1);
                } else {
                    float2 rv = *(const float2*)(res + r * (size_t)N + c0);
                    v0 += rv.x; v1 += rv.y;
                    float2 o; o.x = v0; o.y = v1;
                    *(float2*)(Cf + r * (size_t)N + c0) = o;
                }
            }
        }
    }
}

// ---------------- launch ----------------
extern "C" void kernel_launch(void* const* d_in, const int* in_sizes, int n_in,
                              void* d_out, int out_size)
{
    const float* x     = (const float*)d_in[0];
    const float* Wq    = (const float*)d_in[1];
    const float* bq    = (const float*)d_in[2];
    const float* Wk    = (const float*)d_in[3];
    const float* bk    = (const float*)d_in[4];
    const float* Wv    = (const float*)d_in[5];
    const float* bv    = (const float*)d_in[6];
    const float* ln1_g = (const float*)d_in[7];
    const float* ln1_b = (const float*)d_in[8];
    const float* ln2_g = (const float*)d_in[9];
    const float* ln2_b = (const float*)d_in[10];
    const float* W1    = (const float*)d_in[11];
    const float* b1    = (const float*)d_in[12];
    const float* W2    = (const float*)d_in[13];
    const float* b2    = (const float*)d_in[14];
    float* out = (float*)d_out;

    uint16_t *hHi, *hLo, *WqkvHi, *WqkvLo, *W116, *W216, *h216, *m116;
    float *qkv, *xmid, *bqkv;
    cudaGetSymbolAddress((void**)&hHi,    g_h_hi);
    cudaGetSymbolAddress((void**)&hLo,    g_h_lo);
    cudaGetSymbolAddress((void**)&WqkvHi, g_Wqkv_hi);
    cudaGetSymbolAddress((void**)&WqkvLo, g_Wqkv_lo);
    cudaGetSymbolAddress((void**)&W116,   g_W116);
    cudaGetSymbolAddress((void**)&W216,   g_W216);
    cudaGetSymbolAddress((void**)&h216,   g_h216);
    cudaGetSymbolAddress((void**)&m116,   g_m116);
    cudaGetSymbolAddress((void**)&qkv,    g_qkv);
    cudaGetSymbolAddress((void**)&xmid,   g_xmid);
    cudaGetSymbolAddress((void**)&bqkv,   g_bqkv);

    cudaFuncSetAttribute(mma_gemm_qkv, cudaFuncAttributeMaxDynamicSharedMemorySize, SMEM_BGEMM);
    cudaFuncSetAttribute(mma_gemm_f16<1>, cudaFuncAttributeMaxDynamicSharedMemorySize, SMEM_FGEMM);
    cudaFuncSetAttribute(mma_gemm_f16<2>, cudaFuncAttributeMaxDynamicSharedMemorySize, SMEM_FGEMM);

    init_tw_kernel<<<1, 512>>>();
    bias_concat_kernel<<<NQKV / 256, 256>>>(bq, bk, bv);

    // QKV weights -> bf16 hi/lo planes; MLP weights -> fp16
    transpose_split_kernel<<<dim3(32, 32), dim3(32, 8)>>>(Wq, WqkvHi, WqkvLo, DIM, DIM);
    transpose_split_kernel<<<dim3(32, 32), dim3(32, 8)>>>(Wk, WqkvHi + (size_t)1024 * DIM, WqkvLo + (size_t)1024 * DIM, DIM, DIM);
    transpose_split_kernel<<<dim3(32, 32), dim3(32, 8)>>>(Wv, WqkvHi + (size_t)2048 * DIM, WqkvLo + (size_t)2048 * DIM, DIM, DIM);
    transpose_f16_kernel<<<dim3(128, 32), dim3(32, 8)>>>(W1, W116, DIM, HID);
    transpose_f16_kernel<<<dim3(32, 128), dim3(32, 8)>>>(W2, W216, HID, DIM);

    // LN1 -> bf16 planes
    ln_split_kernel<<<NROW, 256>>>(x, ln1_g, ln1_b, hHi, hLo);

    // fused QKV projection (bf16x3, high precision for the amplified path)
    mma_gemm_qkv<<<dim3(NQKV / 128, NROW / 256), 256, SMEM_BGEMM>>>(
        hHi, hLo, WqkvHi, WqkvLo, bqkv, qkv, NQKV, DIM);

    // fused FFT + normalize for q,k,v — real-packed, 2 rows/block
    fft_qkv_pair_kernel<<<NROW / 2, 256>>>();

    // causal cumsum in Fourier domain, fused * conj(Q̂)
    chain_partial_kernel<<<(NBATCH * CHUNKS * DIM) / 256, 256>>>();
    chain_apply_kernel<<<(NBATCH * CHUNKS * DIM) / 256, 256>>>();

    // paired inverse FFT + residual + LN2 (2 rows per transform)
    ifft_res_ln_pair_kernel<<<NROW / 2, 256>>>(x, ln2_g, ln2_b, h216);

    // MLP (fp16 single-pass)
    mma_gemm_f16<1><<<dim3(HID / 128, NROW / 256), 256, SMEM_FGEMM>>>(
        h216, W116, b1, nullptr, nullptr, (uint32_t*)m116, HID, DIM);
    mma_gemm_f16<2><<<dim3(DIM / 128, NROW / 256), 256, SMEM_FGEMM>>>(
        m116, W216, b2, xmid, out, nullptr, DIM, HID);

    (void)in_sizes; (void)n_in; (void)out_size;
}

// round 14
// speedup vs baseline: 3.4785x; 1.0114x over previous
#include <cuda_runtime.h>
#include <cuda_fp16.h>
#include <math.h>
#include <math_constants.h>
#include <stdint.h>

#define NROW 8192   // B*S
#define DIM  1024
#define SEQ  2048
#define NBATCH 4
#define HID  4096
#define CHUNKS 16
#define TCHUNK (SEQ / CHUNKS)   // 128
#define NQKV 3072

// ---------------- scratch (static device globals; no runtime alloc) ----------
__device__ uint16_t g_h_hi[(size_t)NROW * DIM];      // bf16 planes (QKV path)
__device__ uint16_t g_h_lo[(size_t)NROW * DIM];
__device__ uint16_t g_Wqkv_hi[(size_t)NQKV * DIM];
__device__ uint16_t g_Wqkv_lo[(size_t)NQKV * DIM];
__device__ uint16_t g_W116[(size_t)HID * DIM];       // fp16 transposed weights
__device__ uint16_t g_W216[(size_t)DIM * HID];
__device__ uint16_t g_h216[(size_t)NROW * DIM];      // fp16 h2
__device__ uint16_t g_m116[(size_t)NROW * HID];      // fp16 m1
__device__ float  g_qkv[(size_t)NROW * NQKV];
__device__ float  g_bqkv[NQKV];
__device__ uint32_t g_Qhat[(size_t)NROW * DIM];      // half2 complex
__device__ uint32_t g_Mhat[(size_t)NROW * DIM];      // half2 complex
__device__ float  g_xmid[(size_t)NROW * DIM];
__device__ float2 g_tw[512];
__device__ float2 g_part[NBATCH * CHUNKS * DIM];

// ---------------- helpers ----------------
__device__ __forceinline__ uint32_t smem_u32(const void* p) {
    uint32_t a;
    asm("{ .reg .u64 t; cvta.to.shared.u64 t, %1; cvt.u32.u64 %0, t; }" : "=r"(a) : "l"(p));
    return a;
}
__device__ __forceinline__ uint32_t pack_f16(float x0, float x1) {
    uint32_t h;
    asm("cvt.rn.f16x2.f32 %0, %1, %2;" : "=r"(h) : "f"(x1), "f"(x0));
    return h;
}
__device__ __forceinline__ float2 unpack_f16(uint32_t w) {
    __half2 h = *(__half2*)&w;
    return __half22float2(h);
}
// split pair (x0,x1) -> packed bf16x2 hi (low half = x0) and lo
__device__ __forceinline__ void split2(float x0, float x1, uint32_t& hi, uint32_t& lo) {
    uint32_t h;
    asm("cvt.rn.bf16x2.f32 %0, %1, %2;" : "=r"(h) : "f"(x1), "f"(x0));
    float h0 = __uint_as_float(h << 16);
    float h1 = __uint_as_float(h & 0xFFFF0000u);
    float l0 = x0 - h0;
    float l1 = x1 - h1;
    asm("cvt.rn.bf16x2.f32 %0, %1, %2;" : "=r"(lo) : "f"(l1), "f"(l0));
    hi = h;
}
__device__ __forceinline__ void mma_bf16(float* d, const uint32_t* a, const uint32_t* b) {
    asm volatile("mma.sync.aligned.m16n8k16.row.col.f32.bf16.bf16.f32 "
        "{%0,%1,%2,%3}, {%4,%5,%6,%7}, {%8,%9}, {%0,%1,%2,%3};"
        : "+f"(d[0]), "+f"(d[1]), "+f"(d[2]), "+f"(d[3])
        : "r"(a[0]), "r"(a[1]), "r"(a[2]), "r"(a[3]), "r"(b[0]), "r"(b[1]));
}
__device__ __forceinline__ void mma_f16(float* d, const uint32_t* a, const uint32_t* b) {
    asm volatile("mma.sync.aligned.m16n8k16.row.col.f32.f16.f16.f32 "
        "{%0,%1,%2,%3}, {%4,%5,%6,%7}, {%8,%9}, {%0,%1,%2,%3};"
        : "+f"(d[0]), "+f"(d[1]), "+f"(d[2]), "+f"(d[3])
        : "r"(a[0]), "r"(a[1]), "r"(a[2]), "r"(a[3]), "r"(b[0]), "r"(b[1]));
}
__device__ __forceinline__ void cpa16(uint32_t dst, const void* src) {
    asm volatile("cp.async.cg.shared.global [%0], [%1], 16;" :: "r"(dst), "l"(src) : "memory");
}
__device__ __forceinline__ float2 c_add(float2 a, float2 b){return make_float2(a.x+b.x,a.y+b.y);}
__device__ __forceinline__ float2 c_sub(float2 a, float2 b){return make_float2(a.x-b.x,a.y-b.y);}
__device__ __forceinline__ float2 c_mul(float2 a, float2 b){return make_float2(a.x*b.x-a.y*b.y,a.x*b.y+a.y*b.x);}
__device__ __forceinline__ float2 c_negi(float2 a){return make_float2(a.y,-a.x);}
__device__ __forceinline__ float2 c_norm(float2 f) {
    float inv = 1.0f / fmaxf(sqrtf(f.x * f.x + f.y * f.y), 1e-8f);
    return make_float2(f.x * inv, f.y * inv);
}

// ---------------- small init kernels ----------------
__global__ void init_tw_kernel() {
    int i = threadIdx.x;
    double th = -2.0 * CUDART_PI * (double)i / 1024.0;
    g_tw[i] = make_float2((float)cos(th), (float)sin(th));
}
__global__ void bias_concat_kernel(const float* bq, const float* bk, const float* bv) {
    int i = blockIdx.x * 256 + threadIdx.x;
    float v = (i < 1024) ? bq[i] : (i < 2048) ? bk[i - 1024] : bv[i - 2048];
    g_bqkv[i] = v;
}

// ---------------- weight transpose + bf16 split (QKV) ----------------
__global__ __launch_bounds__(256) void transpose_split_kernel(
    const float* __restrict__ in, uint16_t* __restrict__ ohi,
    uint16_t* __restrict__ olo, int R, int C)
{
    __shared__ float t[32][33];
    int bx = blockIdx.x, by = blockIdx.y;
    int x = bx * 32 + threadIdx.x;
    int y0 = by * 32 + threadIdx.y;
    #pragma unroll
    for (int j = 0; j < 32; j += 8)
        t[threadIdx.y + j][threadIdx.x] = in[(size_t)(y0 + j) * C + x];
    __syncthreads();
    int tl = threadIdx.y * 32 + threadIdx.x;
    int kp = tl & 15;
    int nr0 = tl >> 4;
    uint32_t* hw32 = (uint32_t*)ohi;
    uint32_t* lw32 = (uint32_t*)olo;
    #pragma unroll
    for (int rep = 0; rep < 2; rep++) {
        int nrel = nr0 + rep * 16;
        size_t n = (size_t)bx * 32 + nrel;
        int kg = by * 32 + kp * 2;
        uint32_t hw, lw;
        split2(t[kp * 2][nrel], t[kp * 2 + 1][nrel], hw, lw);
        size_t widx = (n * (size_t)R + kg) >> 1;
        hw32[widx] = hw;
        lw32[widx] = lw;
    }
}

// ---------------- weight transpose to fp16 (MLP) ----------------
__global__ __launch_bounds__(256) void transpose_f16_kernel(
    const float* __restrict__ in, uint16_t* __restrict__ o16, int R, int C)
{
    __shared__ float t[32][33];
    int bx = blockIdx.x, by = blockIdx.y;
    int x = bx * 32 + threadIdx.x;
    int y0 = by * 32 + threadIdx.y;
    #pragma unroll
    for (int j = 0; j < 32; j += 8)
        t[threadIdx.y + j][threadIdx.x] = in[(size_t)(y0 + j) * C + x];
    __syncthreads();
    int tl = threadIdx.y * 32 + threadIdx.x;
    int kp = tl & 15;
    int nr0 = tl >> 4;
    uint32_t* w32 = (uint32_t*)o16;
    #pragma unroll
    for (int rep = 0; rep < 2; rep++) {
        int nrel = nr0 + rep * 16;
        size_t n = (size_t)bx * 32 + nrel;
        int kg = by * 32 + kp * 2;
        w32[(n * (size_t)R + kg) >> 1] = pack_f16(t[kp * 2][nrel], t[kp * 2 + 1][nrel]);
    }
}

// ---------------- block reductions ----------------
__device__ __forceinline__ float2 block_reduce2(float2 v, float2* sh) {
    int tid = threadIdx.x;
    sh[tid] = v;
    __syncthreads();
    #pragma unroll
    for (int s = 128; s > 0; s >>= 1) {
        if (tid < s) {
            sh[tid].x += sh[tid + s].x;
            sh[tid].y += sh[tid + s].y;
        }
        __syncthreads();
    }
    float2 r = sh[0];
    __syncthreads();
    return r;
}
__device__ __forceinline__ float4 block_reduce4(float4 v, float4* sh) {
    int tid = threadIdx.x;
    sh[tid] = v;
    __syncthreads();
    #pragma unroll
    for (int s = 128; s > 0; s >>= 1) {
        if (tid < s) {
            sh[tid].x += sh[tid + s].x;
            sh[tid].y += sh[tid + s].y;
            sh[tid].z += sh[tid + s].z;
            sh[tid].w += sh[tid + s].w;
        }
        __syncthreads();
    }
    float4 r = sh[0];
    __syncthreads();
    return r;
}

// ---------------- LayerNorm 1 -> bf16 hi/lo planes ----------------
__global__ __launch_bounds__(256) void ln_split_kernel(
    const float* __restrict__ x, const float* __restrict__ g,
    const float* __restrict__ b, uint16_t* __restrict__ ohi,
    uint16_t* __restrict__ olo)
{
    __shared__ float2 red[256];
    size_t row = blockIdx.x;
    int tid = threadIdx.x;
    float4 v = ((const float4*)(x + row * DIM))[tid];
    float s = v.x + v.y + v.z + v.w;
    float ss = v.x * v.x + v.y * v.y + v.z * v.z + v.w * v.w;
    float2 tot = block_reduce2(make_float2(s, ss), red);
    float mu = tot.x * (1.0f / DIM);
    float var = tot.y * (1.0f / DIM) - mu * mu;
    float rstd = rsqrtf(var + 1e-5f);
    float4 gg = ((const float4*)g)[tid];
    float4 bb = ((const float4*)b)[tid];
    float y0 = (v.x - mu) * rstd * gg.x + bb.x;
    float y1 = (v.y - mu) * rstd * gg.y + bb.y;
    float y2 = (v.z - mu) * rstd * gg.z + bb.z;
    float y3 = (v.w - mu) * rstd * gg.w + bb.w;
    uint32_t h0, l0, h1, l1;
    split2(y0, y1, h0, l0);
    split2(y2, y3, h1, l1);
    uint32_t* hw = (uint32_t*)ohi;
    uint32_t* lw = (uint32_t*)olo;
    size_t wb = row * 512 + tid * 2;
    hw[wb] = h0; hw[wb + 1] = h1;
    lw[wb] = l0; lw[wb + 1] = l1;
}

// -------- 1024-pt radix-4 Stockham FFT, bank-conflict-free swizzles --------
__device__ __forceinline__ int swz(int g, int a) {
    if (g == 1) return a ^ ((a >> 4) & 3);
    if (g == 2) return a ^ ((a >> 2) & 0xC);
    return a;
}
__device__ __forceinline__ float2* fft1024(float2* bufA, float2* bufB) {
    float2* x = bufA;
    float2* y = bufB;
    int n4 = 256, s = 1;
    #pragma unroll
    for (int st = 0; st < 5; st++) {
        __syncthreads();
        int i = threadIdx.x;
        int p = i / s;
        int q = i - p * s;
        float2 w1 = g_tw[p * s];
        float2 w2 = g_tw[2 * p * s];
        float2 x0 = x[swz(st, q + s * p)];
        float2 x1 = x[swz(st, q + s * (p + n4))];
        float2 x2 = x[swz(st, q + s * (p + 2 * n4))];
        float2 x3 = x[swz(st, q + s * (p + 3 * n4))];
        float2 za0 = c_add(x0, x2);
        float2 za1 = c_mul(c_sub(x0, x2), w1);
        float2 zb0 = c_add(x1, x3);
        float2 zb1 = c_mul(c_negi(c_sub(x1, x3)), w1);
        int ob = q + s * 4 * p;
        y[swz(st + 1, ob)]         = c_add(za0, zb0);
        y[swz(st + 1, ob + s)]     = c_add(za1, zb1);
        y[swz(st + 1, ob + 2 * s)] = c_mul(c_sub(za0, zb0), w2);
        y[swz(st + 1, ob + 3 * s)] = c_mul(c_sub(za1, zb1), w2);
        float2* t = x; x = y; y = t;
        n4 >>= 2; s <<= 2;
    }
    __syncthreads();
    return x;
}

// -------- fused QKV FFT, 2 rows/block via real-packing; half2 outputs -------
__global__ __launch_bounds__(256) void fft_qkv_pair_kernel() {
    __shared__ __align__(16) float2 bufA[1024];
    __shared__ __align__(16) float2 bufB[1024];
    __shared__ __align__(16) float2 kb0[1024];
    __shared__ __align__(16) float2 kb1[1024];
    size_t row0 = (size_t)blockIdx.x * 2;
    size_t row1 = row0 + 1;
    int tid = threadIdx.x;
    const float* b0 = g_qkv + row0 * NQKV;
    const float* b1 = g_qkv + row1 * NQKV;

    // --- FFT 1: q0 + i*k0 ---
    #pragma unroll
    for (int j = 0; j < 4; j++) {
        int idx = tid + j * 256;
        bufA[idx] = make_float2(b0[idx], b0[1024 + idx]);
    }
    float2* res = fft1024(bufA, bufB);
    uint32_t* qp0 = g_Qhat + row0 * DIM;
    #pragma unroll
    for (int j = 0; j < 4; j++) {
        int idx = tid + j * 256;
        int midx = (1024 - idx) & 1023;
        float2 Zc = res[idx];
        float2 Zm = res[midx];
        float2 fq = c_norm(make_float2(Zc.x + Zm.x, Zc.y - Zm.y));
        float2 fk = c_norm(make_float2(Zc.y + Zm.y, Zm.x - Zc.x));
        qp0[idx] = pack_f16(fq.x, fq.y);
        kb0[idx] = fk;
    }
    __syncthreads();

    // --- FFT 2: q1 + i*k1 ---
    #pragma unroll
    for (int j = 0; j < 4; j++) {
        int idx = tid + j * 256;
        bufA[idx] = make_float2(b1[idx], b1[1024 + idx]);
    }
    res = fft1024(bufA, bufB);
    uint32_t* qp1 = g_Qhat + row1 * DIM;
    #pragma unroll
    for (int j = 0; j < 4; j++) {
        int idx = tid + j * 256;
        int midx = (1024 - idx) & 1023;
        float2 Zc = res[idx];
        float2 Zm = res[midx];
        float2 fq = c_norm(make_float2(Zc.x + Zm.x, Zc.y - Zm.y));
        float2 fk = c_norm(make_float2(Zc.y + Zm.y, Zm.x - Zc.x));
        qp1[idx] = pack_f16(fq.x, fq.y);
        kb1[idx] = fk;
    }
    __syncthreads();

    // --- FFT 3: v0 + i*v1 ---
    #pragma unroll
    for (int j = 0; j < 4; j++) {
        int idx = tid + j * 256;
        bufA[idx] = make_float2(b0[2048 + idx], b1[2048 + idx]);
    }
    res = fft1024(bufA, bufB);
    uint32_t* mp0 = g_Mhat + row0 * DIM;
    uint32_t* mp1 = g_Mhat + row1 * DIM;
    #pragma unroll
    for (int j = 0; j < 4; j++) {
        int idx = tid + j * 256;
        int midx = (1024 - idx) & 1023;
        float2 Zc = res[idx];
        float2 Zm = res[midx];
        float2 v0 = c_norm(make_float2(Zc.x + Zm.x, Zc.y - Zm.y));
        float2 v1 = c_norm(make_float2(Zc.y + Zm.y, Zm.x - Zc.x));
        float2 p0 = c_mul(kb0[idx], v0);
        float2 p1 = c_mul(kb1[idx], v1);
        mp0[idx] = pack_f16(p0.x, p0.y);
        mp1[idx] = pack_f16(p1.x, p1.y);
    }
}

// ---------------- chain pass A: per-chunk partial sums ----------------
__global__ __launch_bounds__(256) void chain_partial_kernel() {
    int gid = blockIdx.x * 256 + threadIdx.x;
    int bin = gid & 1023;
    int chunk = (gid >> 10) & (CHUNKS - 1);
    int b = gid >> 14;
    size_t base = ((size_t)b * SEQ + (size_t)chunk * TCHUNK) * DIM + bin;
    float2 s = make_float2(0.f, 0.f);
    #pragma unroll 4
    for (int i = 0; i < TCHUNK; i++) {
        float2 p = unpack_f16(g_Mhat[base + (size_t)i * DIM]);
        s.x += p.x; s.y += p.y;
    }
    g_part[gid] = s;
}

// ---------------- chain pass B: scan within chunk + apply conj(Q̂) --------
__global__ __launch_bounds__(256) void chain_apply_kernel() {
    int gid = blockIdx.x * 256 + threadIdx.x;
    int bin = gid & 1023;
    int chunk = (gid >> 10) & (CHUNKS - 1);
    int b = gid >> 14;
    float2 acc = make_float2(0.f, 0.f);
    for (int c = 0; c < chunk; c++) {
        float2 p = g_part[((b * CHUNKS) + c) * 1024 + bin];
        acc.x += p.x; acc.y += p.y;
    }
    size_t base = ((size_t)b * SEQ + (size_t)chunk * TCHUNK) * DIM + bin;
    #pragma unroll 4
    for (int i = 0; i < TCHUNK; i++) {
        size_t off = base + (size_t)i * DIM;
        float2 p = unpack_f16(g_Mhat[off]);
        acc.x += p.x; acc.y += p.y;
        float2 q = unpack_f16(g_Qhat[off]);
        g_Mhat[off] = pack_f16(acc.x * q.x + acc.y * q.y,
                               acc.y * q.x - acc.x * q.y);
    }
}

// ------- paired inverse FFT + residual + LN2 (2 rows per block) --------
__global__ __launch_bounds__(256) void ifft_res_ln_pair_kernel(
    const float* __restrict__ x, const float* __restrict__ g,
    const float* __restrict__ b, uint16_t* __restrict__ o16)
{
    __shared__ __align__(16) float2 bufA[1024];
    __shared__ __align__(16) float2 bufB[1024];
    size_t row0 = (size_t)blockIdx.x * 2;
    size_t row1 = row0 + 1;
    int tid = threadIdx.x;
    const uint32_t* m0 = g_Mhat + row0 * DIM;
    const uint32_t* m1 = g_Mhat + row1 * DIM;
    #pragma unroll
    for (int j = 0; j < 4; j++) {
        int idx = tid + j * 256;
        float2 a = unpack_f16(m0[idx]);
        float2 c = unpack_f16(m1[idx]);
        // conj(M0) + i*conj(M1)
        bufA[idx] = make_float2(a.x + c.y, c.x - a.y);
    }
    float2* res = fft1024(bufA, bufB);   // = bufB; Y = N*(r0 + i*r1)
    float mixed0[4], mixed1[4];
    #pragma unroll
    for (int j = 0; j < 4; j++) {
        float2 Y = res[tid + j * 256];
        mixed0[j] = Y.x * (1.0f / 1024.0f);
        mixed1[j] = Y.y * (1.0f / 1024.0f);
    }
    __syncthreads();
    float* s0 = (float*)bufA;
    float* s1 = s0 + 1024;
    const float* xp0 = x + row0 * DIM;
    const float* xp1 = x + row1 * DIM;
    float* xo0 = g_xmid + row0 * DIM;
    float* xo1 = g_xmid + row1 * DIM;
    float su0 = 0.f, ss0 = 0.f, su1 = 0.f, ss1 = 0.f;
    #pragma unroll
    for (int j = 0; j < 4; j++) {
        int idx = tid + j * 256;
        float v0 = xp0[idx] + mixed0[j];
        float v1 = xp1[idx] + mixed1[j];
        xo0[idx] = v0; s0[idx] = v0;
        xo1[idx] = v1; s1[idx] = v1;
        su0 += v0; ss0 += v0 * v0;
        su1 += v1; ss1 += v1 * v1;
    }
    __syncthreads();
    float4 tot = block_reduce4(make_float4(su0, ss0, su1, ss1), (float4*)bufB);
    float mu0 = tot.x * (1.0f / DIM);
    float rstd0 = rsqrtf(tot.y * (1.0f / DIM) - mu0 * mu0 + 1e-5f);
    float mu1 = tot.z * (1.0f / DIM);
    float rstd1 = rsqrtf(tot.w * (1.0f / DIM) - mu1 * mu1 + 1e-5f);
    float4 gg = ((const float4*)g)[tid];
    float4 bb = ((const float4*)b)[tid];
    uint32_t* w = (uint32_t*)o16;
    {
        float4 vv = ((const float4*)s0)[tid];
        float y0 = (vv.x - mu0) * rstd0 * gg.x + bb.x;
        float y1 = (vv.y - mu0) * rstd0 * gg.y + bb.y;
        float y2 = (vv.z - mu0) * rstd0 * gg.z + bb.z;
        float y3 = (vv.w - mu0) * rstd0 * gg.w + bb.w;
        size_t wb = row0 * 512 + tid * 2;
        w[wb]     = pack_f16(y0, y1);
        w[wb + 1] = pack_f16(y2, y3);
    }
    {
        float4 vv = ((const float4*)s1)[tid];
        float y0 = (vv.x - mu1) * rstd1 * gg.x + bb.x;
        float y1 = (vv.y - mu1) * rstd1 * gg.y + bb.y;
        float y2 = (vv.z - mu1) * rstd1 * gg.z + bb.z;
        float y3 = (vv.w - mu1) * rstd1 * gg.w + bb.w;
        size_t wb = row1 * 512 + tid * 2;
        w[wb]     = pack_f16(y0, y1);
        w[wb + 1] = pack_f16(y2, y3);
    }
}

// ================== bf16x3 mma.sync GEMM (QKV), 256x128 CTA tile ============
#define A_PL_B 20480u
#define B_PL_B 10240u
#define BSTAGE_B 61440u
#define BSTAGE_W 15360u
#define SMEM_BGEMM (2 * BSTAGE_B)         // 122880

__global__ __launch_bounds__(256) void mma_gemm_qkv(
    const uint16_t* __restrict__ Ahi, const uint16_t* __restrict__ Alo,
    const uint16_t* __restrict__ Bhi, const uint16_t* __restrict__ Blo,
    const float* __restrict__ bias, float* __restrict__ Cf, int N, int K)
{
    extern __shared__ uint32_t smu[];
    uint32_t su = smem_u32(smu);

    int tid = threadIdx.x;
    int wid = tid >> 5;
    int lane = tid & 31;
    int wm = wid & 3;
    int wn = wid >> 2;
    int bx = blockIdx.x, by = blockIdx.y;
    int gq = lane >> 2, tq = lane & 3;

    const uint16_t* aH = Ahi + (size_t)(by * 256 + tid) * K;
    const uint16_t* aL = Alo + (size_t)(by * 256 + tid) * K;
    int brow = tid >> 1;
    int bcp = (tid & 1) * 2;
    const uint16_t* bH = Bhi + (size_t)(bx * 128 + brow) * K;
    const uint16_t* bL = Blo + (size_t)(bx * 128 + brow) * K;

    #define BLOAD_STAGE(s, k0) do { \
        uint32_t _sb = su + (uint32_t)(s) * BSTAGE_B; \
        uint32_t _da = _sb + (uint32_t)tid * 80u; \
        _Pragma("unroll") \
        for (int c = 0; c < 4; c++) { \
            cpa16(_da + c * 16,           aH + (k0) + c * 8); \
            cpa16(_da + A_PL_B + c * 16,  aL + (k0) + c * 8); \
        } \
        uint32_t _db = _sb + 2 * A_PL_B + (uint32_t)brow * 80u + (uint32_t)bcp * 16u; \
        _Pragma("unroll") \
        for (int c = 0; c < 2; c++) { \
            cpa16(_db + c * 16,           bH + (k0) + (bcp + c) * 8); \
            cpa16(_db + B_PL_B + c * 16,  bL + (k0) + (bcp + c) * 8); \
        } \
        asm volatile("cp.async.commit_group;" ::: "memory"); \
    } while (0)

    float acc[4][8][4];
    #pragma unroll
    for (int mt = 0; mt < 4; mt++)
        #pragma unroll
        for (int nt = 0; nt < 8; nt++)
            #pragma unroll
            for (int i = 0; i < 4; i++) acc[mt][nt][i] = 0.f;

    int KT = K >> 5;
    BLOAD_STAGE(0, 0);

    int aBase0 = (wm * 64 + gq) * 20 + tq;
    int bBase0 = (wn * 64 + gq) * 20 + tq;

    for (int it = 0; it < KT; it++) {
        asm volatile("cp.async.wait_group 0;" ::: "memory");
        __syncthreads();
        if (it + 1 < KT) BLOAD_STAGE((it + 1) & 1, (it + 1) * 32);

        int s = it & 1;
        const uint32_t* ah_t = smu + s * BSTAGE_W;
        const uint32_t* al_t = ah_t + 5120;
        const uint32_t* bh_t = ah_t + 10240;
        const uint32_t* bl_t = ah_t + 12800;

        #pragma unroll
        for (int ks = 0; ks < 2; ks++) {
            int ko = ks * 8;
            uint32_t ah[4][4], al[4][4], bb[8][2];
            #pragma unroll
            for (int mt = 0; mt < 4; mt++) {
                int base = aBase0 + mt * 320 + ko;
                ah[mt][0] = ah_t[base];
                ah[mt][1] = ah_t[base + 160];
                ah[mt][2] = ah_t[base + 4];
                ah[mt][3] = ah_t[base + 164];
                al[mt][0] = al_t[base];
                al[mt][1] = al_t[base + 160];
                al[mt][2] = al_t[base + 4];
                al[mt][3] = al_t[base + 164];
            }
            #pragma unroll
            for (int nt = 0; nt < 8; nt++) {
                int base = bBase0 + nt * 160 + ko;
                bb[nt][0] = bh_t[base];
                bb[nt][1] = bh_t[base + 4];
            }
            #pragma unroll
            for (int mt = 0; mt < 4; mt++)
                #pragma unroll
                for (int nt = 0; nt < 8; nt++) {
                    mma_bf16(acc[mt][nt], ah[mt], bb[nt]);
                    mma_bf16(acc[mt][nt], al[mt], bb[nt]);
                }
            #pragma unroll
            for (int nt = 0; nt < 8; nt++) {
                int base = bBase0 + nt * 160 + ko;
                bb[nt][0] = bl_t[base];
                bb[nt][1] = bl_t[base + 4];
            }
            #pragma unroll
            for (int mt = 0; mt < 4; mt++)
                #pragma unroll
                for (int nt = 0; nt < 8; nt++)
                    mma_bf16(acc[mt][nt], ah[mt], bb[nt]);
        }
        __syncthreads();
    }

    #pragma unroll
    for (int mt = 0; mt < 4; mt++) {
        #pragma unroll
        for (int nt = 0; nt < 8; nt++) {
            int r0 = by * 256 + wm * 64 + mt * 16 + gq;
            int c0 = bx * 128 + wn * 64 + nt * 8 + tq * 2;
            float b0 = bias[c0], b1 = bias[c0 + 1];
            #pragma unroll
            for (int half = 0; half < 2; half++) {
                size_t r = r0 + half * 8;
                float2 o;
                o.x = acc[mt][nt][half * 2 + 0] + b0;
                o.y = acc[mt][nt][half * 2 + 1] + b1;
                *(float2*)(Cf + r * (size_t)N + c0) = o;
            }
        }
    }
}

// ================== fp16 single-pass mma.sync GEMM (MLP), 256x128 tile ======
#define FA_PL_B 20480u
#define FSTAGE_B 30720u
#define FSTAGE_W 7680u
#define SMEM_FGEMM (2 * FSTAGE_B)         // 61440

template<int EPI>
__global__ __launch_bounds__(256) void mma_gemm_f16(
    const uint16_t* __restrict__ A, const uint16_t* __restrict__ B,
    const float* __restrict__ bias, const float* __restrict__ res,
    float* __restrict__ Cf, uint32_t* __restrict__ C16,
    int N, int K)
{
    extern __shared__ uint32_t smu[];
    uint32_t su = smem_u32(smu);

    int tid = threadIdx.x;
    int wid = tid >> 5;
    int lane = tid & 31;
    int wm = wid & 3;
    int wn = wid >> 2;
    int bx = blockIdx.x, by = blockIdx.y;
    int gq = lane >> 2, tq = lane & 3;

    const uint16_t* aP = A + (size_t)(by * 256 + tid) * K;
    int brow = tid >> 1;
    int bcp = (tid & 1) * 2;
    const uint16_t* bP = B + (size_t)(bx * 128 + brow) * K;

    #define FLOAD_STAGE(s, k0) do { \
        uint32_t _sb = su + (uint32_t)(s) * FSTAGE_B; \
        uint32_t _da = _sb + (uint32_t)tid * 80u; \
        _Pragma("unroll") \
        for (int c = 0; c < 4; c++) \
            cpa16(_da + c * 16, aP + (k0) + c * 8); \
        uint32_t _db = _sb + FA_PL_B + (uint32_t)brow * 80u + (uint32_t)bcp * 16u; \
        _Pragma("unroll") \
        for (int c = 0; c < 2; c++) \
            cpa16(_db + c * 16, bP + (k0) + (bcp + c) * 8); \
        asm volatile("cp.async.commit_group;" ::: "memory"); \
    } while (0)

    float acc[4][8][4];
    #pragma unroll
    for (int mt = 0; mt < 4; mt++)
        #pragma unroll
        for (int nt = 0; nt < 8; nt++)
            #pragma unroll
            for (int i = 0; i < 4; i++) acc[mt][nt][i] = 0.f;

    int KT = K >> 5;
    FLOAD_STAGE(0, 0);

    int aBase0 = (wm * 64 + gq) * 20 + tq;
    int bBase0 = (wn * 64 + gq) * 20 + tq;

    for (int it = 0; it < KT; it++) {
        asm volatile("cp.async.wait_group 0;" ::: "memory");
        __syncthreads();
        if (it + 1 < KT) FLOAD_STAGE((it + 1) & 1, (it + 1) * 32);

        int s = it & 1;
        const uint32_t* a_t = smu + s * FSTAGE_W;
        const uint32_t* b_t = a_t + 5120;

        #pragma unroll
        for (int ks = 0; ks < 2; ks++) {
            int ko = ks * 8;
            uint32_t ah[4][4], bb[8][2];
            #pragma unroll
            for (int mt = 0; mt < 4; mt++) {
                int base = aBase0 + mt * 320 + ko;
                ah[mt][0] = a_t[base];
                ah[mt][1] = a_t[base + 160];
                ah[mt][2] = a_t[base + 4];
                ah[mt][3] = a_t[base + 164];
            }
            #pragma unroll
            for (int nt = 0; nt < 8; nt++) {
                int base = bBase0 + nt * 160 + ko;
                bb[nt][0] = b_t[base];
                bb[nt][1] = b_t[base + 4];
            }
            #pragma unroll
            for (int mt = 0; mt < 4; mt++)
                #pragma unroll
                for (int nt = 0; nt < 8; nt++)
                    mma_f16(acc[mt][nt], ah[mt], bb[nt]);
        }
        __syncthreads();
    }

    #pragma unroll
    for (int mt = 0; mt < 4; mt++) {
        #pragma unroll
        for (int nt = 0; nt < 8; nt++) {
            int r0 = by * 256 + wm * 64 + mt * 16 + gq;
            int c0 = bx * 128 + wn * 64 + nt * 8 + tq * 2;
            float b0 = bias[c0], b1 = bias[c0 + 1];
            #pragma unroll
            for (int half = 0; half < 2; half++) {
                size_t r = r0 + half * 8;
                float v0 = acc[mt][nt][half * 2 + 0] + b0;
                float v1 = acc[mt][nt][half * 2 + 1] + b1;
                if (EPI == 1) {
                    v0 = 0.5f * v0 * (1.0f + erff(v0 * 0.70710678118654752f));
                    v1 = 0.5f * v1 * (1.0f + erff(v1 * 0.70710678118654752f));
                    C16[(r * (size_t)N + c0) >> 1] = pack_f16(v0, v1);
                } else {
                    float2 rv = *(const float2*)(res + r * (size_t)N + c0);
                    v0 += rv.x; v1 += rv.y;
                    float2 o; o.x = v0; o.y = v1;
                    *(float2*)(Cf + r * (size_t)N + c0) = o;
                }
            }
        }
    }
}

// ---------------- launch ----------------
extern "C" void kernel_launch(void* const* d_in, const int* in_sizes, int n_in,
                              void* d_out, int out_size)
{
    const float* x     = (const float*)d_in[0];
    const float* Wq    = (const float*)d_in[1];
    const float* bq    = (const float*)d_in[2];
    const float* Wk    = (const float*)d_in[3];
    const float* bk    = (const float*)d_in[4];
    const float* Wv    = (const float*)d_in[5];
    const float* bv    = (const float*)d_in[6];
    const float* ln1_g = (const float*)d_in[7];
    const float* ln1_b = (const float*)d_in[8];
    const float* ln2_g = (const float*)d_in[9];
    const float* ln2_b = (const float*)d_in[10];
    const float* W1    = (const float*)d_in[11];
    const float* b1    = (const float*)d_in[12];
    const float* W2    = (const float*)d_in[13];
    const float* b2    = (const float*)d_in[14];
    float* out = (float*)d_out;

    uint16_t *hHi, *hLo, *WqkvHi, *WqkvLo, *W116, *W216, *h216, *m116;
    float *qkv, *xmid, *bqkv;
    cudaGetSymbolAddress((void**)&hHi,    g_h_hi);
    cudaGetSymbolAddress((void**)&hLo,    g_h_lo);
    cudaGetSymbolAddress((void**)&WqkvHi, g_Wqkv_hi);
    cudaGetSymbolAddress((void**)&WqkvLo, g_Wqkv_lo);
    cudaGetSymbolAddress((void**)&W116,   g_W116);
    cudaGetSymbolAddress((void**)&W216,   g_W216);
    cudaGetSymbolAddress((void**)&h216,   g_h216);
    cudaGetSymbolAddress((void**)&m116,   g_m116);
    cudaGetSymbolAddress((void**)&qkv,    g_qkv);
    cudaGetSymbolAddress((void**)&xmid,   g_xmid);
    cudaGetSymbolAddress((void**)&bqkv,   g_bqkv);

    cudaFuncSetAttribute(mma_gemm_qkv, cudaFuncAttributeMaxDynamicSharedMemorySize, SMEM_BGEMM);
    cudaFuncSetAttribute(mma_gemm_f16<1>, cudaFuncAttributeMaxDynamicSharedMemorySize, SMEM_FGEMM);
    cudaFuncSetAttribute(mma_gemm_f16<2>, cudaFuncAttributeMaxDynamicSharedMemorySize, SMEM_FGEMM);

    init_tw_kernel<<<1, 512>>>();
    bias_concat_kernel<<<NQKV / 256, 256>>>(bq, bk, bv);

    // QKV weights -> bf16 hi/lo planes; MLP weights -> fp16
    transpose_split_kernel<<<dim3(32, 32), dim3(32, 8)>>>(Wq, WqkvHi, WqkvLo, DIM, DIM);
    transpose_split_kernel<<<dim3(32, 32), dim3(32, 8)>>>(Wk, WqkvHi + (size_t)1024 * DIM, WqkvLo + (size_t)1024 * DIM, DIM, DIM);
    transpose_split_kernel<<<dim3(32, 32), dim3(32, 8)>>>(Wv, WqkvHi + (size_t)2048 * DIM, WqkvLo + (size_t)2048 * DIM, DIM, DIM);
    transpose_f16_kernel<<<dim3(128, 32), dim3(32, 8)>>>(W1, W116, DIM, HID);
    transpose_f16_kernel<<<dim3(32, 128), dim3(32, 8)>>>(W2, W216, HID, DIM);

    // LN1 -> bf16 planes
    ln_split_kernel<<<NROW, 256>>>(x, ln1_g, ln1_b, hHi, hLo);

    // fused QKV projection (bf16x3, high precision for the amplified path)
    mma_gemm_qkv<<<dim3(NQKV / 128, NROW / 256), 256, SMEM_BGEMM>>>(
        hHi, hLo, WqkvHi, WqkvLo, bqkv, qkv, NQKV, DIM);

    // fused FFT + normalize for q,k,v — real-packed, 2 rows/block
    fft_qkv_pair_kernel<<<NROW / 2, 256>>>();

    // causal cumsum in Fourier domain, fused * conj(Q̂)
    chain_partial_kernel<<<(NBATCH * CHUNKS * DIM) / 256, 256>>>();
    chain_apply_kernel<<<(NBATCH * CHUNKS * DIM) / 256, 256>>>();

    // paired inverse FFT + residual + LN2 (2 rows per transform)
    ifft_res_ln_pair_kernel<<<NROW / 2, 256>>>(x, ln2_g, ln2_b, h216);

    // MLP (fp16 single-pass)
    mma_gemm_f16<1><<<dim3(HID / 128, NROW / 256), 256, SMEM_FGEMM>>>(
        h216, W116, b1, nullptr, nullptr, (uint32_t*)m116, HID, DIM);
    mma_gemm_f16<2><<<dim3(DIM / 128, NROW / 256), 256, SMEM_FGEMM>>>(
        m116, W216, b2, xmid, out, nullptr, DIM, HID);

    (void)in_sizes; (void)n_in; (void)out_size;
}

// round 15
// speedup vs baseline: 3.5927x; 1.0328x over previous
#include <cuda_runtime.h>
#include <cuda_fp16.h>
#include <math.h>
#include <math_constants.h>
#include <stdint.h>

#define NROW 8192   // B*S
#define DIM  1024
#define SEQ  2048
#define NBATCH 4
#define HID  4096
#define CHUNKS 64
#define TCHUNK (SEQ / CHUNKS)   // 32
#define NQKV 3072

// ---------------- scratch (static device globals; no runtime alloc) ----------
__device__ uint16_t g_h_hi[(size_t)NROW * DIM];      // bf16 planes (QKV path)
__device__ uint16_t g_h_lo[(size_t)NROW * DIM];
__device__ uint16_t g_Wqkv_hi[(size_t)NQKV * DIM];
__device__ uint16_t g_Wqkv_lo[(size_t)NQKV * DIM];
__device__ uint16_t g_W116[(size_t)HID * DIM];       // fp16 transposed weights
__device__ uint16_t g_W216[(size_t)DIM * HID];
__device__ uint16_t g_h216[(size_t)NROW * DIM];      // fp16 h2
__device__ uint16_t g_m116[(size_t)NROW * HID];      // fp16 m1
__device__ float  g_qkv[(size_t)NROW * NQKV];
__device__ float  g_bqkv[NQKV];
__device__ uint32_t g_Qhat[(size_t)NROW * DIM];      // half2 complex
__device__ uint32_t g_Mhat[(size_t)NROW * DIM];      // half2 complex
__device__ float  g_xmid[(size_t)NROW * DIM];
__device__ float2 g_tw[512];
__device__ float2 g_part[NBATCH * CHUNKS * DIM];

// ---------------- helpers ----------------
__device__ __forceinline__ uint32_t smem_u32(const void* p) {
    uint32_t a;
    asm("{ .reg .u64 t; cvta.to.shared.u64 t, %1; cvt.u32.u64 %0, t; }" : "=r"(a) : "l"(p));
    return a;
}
__device__ __forceinline__ uint32_t pack_f16(float x0, float x1) {
    uint32_t h;
    asm("cvt.rn.f16x2.f32 %0, %1, %2;" : "=r"(h) : "f"(x1), "f"(x0));
    return h;
}
__device__ __forceinline__ float2 unpack_f16(uint32_t w) {
    __half2 h = *(__half2*)&w;
    return __half22float2(h);
}
// split pair (x0,x1) -> packed bf16x2 hi (low half = x0) and lo
__device__ __forceinline__ void split2(float x0, float x1, uint32_t& hi, uint32_t& lo) {
    uint32_t h;
    asm("cvt.rn.bf16x2.f32 %0, %1, %2;" : "=r"(h) : "f"(x1), "f"(x0));
    float h0 = __uint_as_float(h << 16);
    float h1 = __uint_as_float(h & 0xFFFF0000u);
    float l0 = x0 - h0;
    float l1 = x1 - h1;
    asm("cvt.rn.bf16x2.f32 %0, %1, %2;" : "=r"(lo) : "f"(l1), "f"(l0));
    hi = h;
}
__device__ __forceinline__ void mma_bf16(float* d, const uint32_t* a, const uint32_t* b) {
    asm volatile("mma.sync.aligned.m16n8k16.row.col.f32.bf16.bf16.f32 "
        "{%0,%1,%2,%3}, {%4,%5,%6,%7}, {%8,%9}, {%0,%1,%2,%3};"
        : "+f"(d[0]), "+f"(d[1]), "+f"(d[2]), "+f"(d[3])
        : "r"(a[0]), "r"(a[1]), "r"(a[2]), "r"(a[3]), "r"(b[0]), "r"(b[1]));
}
__device__ __forceinline__ void mma_f16(float* d, const uint32_t* a, const uint32_t* b) {
    asm volatile("mma.sync.aligned.m16n8k16.row.col.f32.f16.f16.f32 "
        "{%0,%1,%2,%3}, {%4,%5,%6,%7}, {%8,%9}, {%0,%1,%2,%3};"
        : "+f"(d[0]), "+f"(d[1]), "+f"(d[2]), "+f"(d[3])
        : "r"(a[0]), "r"(a[1]), "r"(a[2]), "r"(a[3]), "r"(b[0]), "r"(b[1]));
}
__device__ __forceinline__ void cpa16(uint32_t dst, const void* src) {
    asm volatile("cp.async.cg.shared.global [%0], [%1], 16;" :: "r"(dst), "l"(src) : "memory");
}
__device__ __forceinline__ float2 c_add(float2 a, float2 b){return make_float2(a.x+b.x,a.y+b.y);}
__device__ __forceinline__ float2 c_sub(float2 a, float2 b){return make_float2(a.x-b.x,a.y-b.y);}
__device__ __forceinline__ float2 c_mul(float2 a, float2 b){return make_float2(a.x*b.x-a.y*b.y,a.x*b.y+a.y*b.x);}
__device__ __forceinline__ float2 c_negi(float2 a){return make_float2(a.y,-a.x);}
__device__ __forceinline__ float2 c_norm(float2 f) {
    float inv = 1.0f / fmaxf(sqrtf(f.x * f.x + f.y * f.y), 1e-8f);
    return make_float2(f.x * inv, f.y * inv);
}

// ---------------- small init kernels ----------------
__global__ void init_tw_kernel() {
    int i = threadIdx.x;
    double th = -2.0 * CUDART_PI * (double)i / 1024.0;
    g_tw[i] = make_float2((float)cos(th), (float)sin(th));
}
__global__ void bias_concat_kernel(const float* bq, const float* bk, const float* bv) {
    int i = blockIdx.x * 256 + threadIdx.x;
    float v = (i < 1024) ? bq[i] : (i < 2048) ? bk[i - 1024] : bv[i - 2048];
    g_bqkv[i] = v;
}

// ------- QKV weight transpose + bf16 split, all 3 weights in one launch -----
__global__ __launch_bounds__(256) void transpose_split_qkv_kernel(
    const float* __restrict__ Wq, const float* __restrict__ Wk,
    const float* __restrict__ Wv)
{
    __shared__ float t[32][33];
    int bx = blockIdx.x, by = blockIdx.y, bz = blockIdx.z;
    const float* in = (bz == 0) ? Wq : (bz == 1) ? Wk : Wv;
    uint16_t* ohi = g_Wqkv_hi + (size_t)bz * 1024 * DIM;
    uint16_t* olo = g_Wqkv_lo + (size_t)bz * 1024 * DIM;
    int x = bx * 32 + threadIdx.x;
    int y0 = by * 32 + threadIdx.y;
    #pragma unroll
    for (int j = 0; j < 32; j += 8)
        t[threadIdx.y + j][threadIdx.x] = in[(size_t)(y0 + j) * DIM + x];
    __syncthreads();
    int tl = threadIdx.y * 32 + threadIdx.x;
    int kp = tl & 15;
    int nr0 = tl >> 4;
    uint32_t* hw32 = (uint32_t*)ohi;
    uint32_t* lw32 = (uint32_t*)olo;
    #pragma unroll
    for (int rep = 0; rep < 2; rep++) {
        int nrel = nr0 + rep * 16;
        size_t n = (size_t)bx * 32 + nrel;
        int kg = by * 32 + kp * 2;
        uint32_t hw, lw;
        split2(t[kp * 2][nrel], t[kp * 2 + 1][nrel], hw, lw);
        size_t widx = (n * (size_t)DIM + kg) >> 1;
        hw32[widx] = hw;
        lw32[widx] = lw;
    }
}

// ---------------- weight transpose to fp16 (MLP) ----------------
__global__ __launch_bounds__(256) void transpose_f16_kernel(
    const float* __restrict__ in, uint16_t* __restrict__ o16, int R, int C)
{
    __shared__ float t[32][33];
    int bx = blockIdx.x, by = blockIdx.y;
    int x = bx * 32 + threadIdx.x;
    int y0 = by * 32 + threadIdx.y;
    #pragma unroll
    for (int j = 0; j < 32; j += 8)
        t[threadIdx.y + j][threadIdx.x] = in[(size_t)(y0 + j) * C + x];
    __syncthreads();
    int tl = threadIdx.y * 32 + threadIdx.x;
    int kp = tl & 15;
    int nr0 = tl >> 4;
    uint32_t* w32 = (uint32_t*)o16;
    #pragma unroll
    for (int rep = 0; rep < 2; rep++) {
        int nrel = nr0 + rep * 16;
        size_t n = (size_t)bx * 32 + nrel;
        int kg = by * 32 + kp * 2;
        w32[(n * (size_t)R + kg) >> 1] = pack_f16(t[kp * 2][nrel], t[kp * 2 + 1][nrel]);
    }
}

// ---------------- block reductions ----------------
__device__ __forceinline__ float2 block_reduce2(float2 v, float2* sh) {
    int tid = threadIdx.x;
    sh[tid] = v;
    __syncthreads();
    #pragma unroll
    for (int s = 128; s > 0; s >>= 1) {
        if (tid < s) {
            sh[tid].x += sh[tid + s].x;
            sh[tid].y += sh[tid + s].y;
        }
        __syncthreads();
    }
    float2 r = sh[0];
    __syncthreads();
    return r;
}
__device__ __forceinline__ float4 block_reduce4(float4 v, float4* sh) {
    int tid = threadIdx.x;
    sh[tid] = v;
    __syncthreads();
    #pragma unroll
    for (int s = 128; s > 0; s >>= 1) {
        if (tid < s) {
            sh[tid].x += sh[tid + s].x;
            sh[tid].y += sh[tid + s].y;
            sh[tid].z += sh[tid + s].z;
            sh[tid].w += sh[tid + s].w;
        }
        __syncthreads();
    }
    float4 r = sh[0];
    __syncthreads();
    return r;
}

// ---------------- LayerNorm 1 -> bf16 hi/lo planes ----------------
__global__ __launch_bounds__(256) void ln_split_kernel(
    const float* __restrict__ x, const float* __restrict__ g,
    const float* __restrict__ b, uint16_t* __restrict__ ohi,
    uint16_t* __restrict__ olo)
{
    __shared__ float2 red[256];
    size_t row = blockIdx.x;
    int tid = threadIdx.x;
    float4 v = ((const float4*)(x + row * DIM))[tid];
    float s = v.x + v.y + v.z + v.w;
    float ss = v.x * v.x + v.y * v.y + v.z * v.z + v.w * v.w;
    float2 tot = block_reduce2(make_float2(s, ss), red);
    float mu = tot.x * (1.0f / DIM);
    float var = tot.y * (1.0f / DIM) - mu * mu;
    float rstd = rsqrtf(var + 1e-5f);
    float4 gg = ((const float4*)g)[tid];
    float4 bb = ((const float4*)b)[tid];
    float y0 = (v.x - mu) * rstd * gg.x + bb.x;
    float y1 = (v.y - mu) * rstd * gg.y + bb.y;
    float y2 = (v.z - mu) * rstd * gg.z + bb.z;
    float y3 = (v.w - mu) * rstd * gg.w + bb.w;
    uint32_t h0, l0, h1, l1;
    split2(y0, y1, h0, l0);
    split2(y2, y3, h1, l1);
    uint32_t* hw = (uint32_t*)ohi;
    uint32_t* lw = (uint32_t*)olo;
    size_t wb = row * 512 + tid * 2;
    hw[wb] = h0; hw[wb + 1] = h1;
    lw[wb] = l0; lw[wb + 1] = l1;
}

// -------- 1024-pt radix-4 Stockham FFT, bank-conflict-free swizzles --------
__device__ __forceinline__ int swz(int g, int a) {
    if (g == 1) return a ^ ((a >> 4) & 3);
    if (g == 2) return a ^ ((a >> 2) & 0xC);
    return a;
}
__device__ __forceinline__ float2* fft1024(float2* bufA, float2* bufB) {
    float2* x = bufA;
    float2* y = bufB;
    int n4 = 256, s = 1;
    #pragma unroll
    for (int st = 0; st < 5; st++) {
        __syncthreads();
        int i = threadIdx.x;
        int p = i / s;
        int q = i - p * s;
        float2 w1 = g_tw[p * s];
        float2 w2 = g_tw[2 * p * s];
        float2 x0 = x[swz(st, q + s * p)];
        float2 x1 = x[swz(st, q + s * (p + n4))];
        float2 x2 = x[swz(st, q + s * (p + 2 * n4))];
        float2 x3 = x[swz(st, q + s * (p + 3 * n4))];
        float2 za0 = c_add(x0, x2);
        float2 za1 = c_mul(c_sub(x0, x2), w1);
        float2 zb0 = c_add(x1, x3);
        float2 zb1 = c_mul(c_negi(c_sub(x1, x3)), w1);
        int ob = q + s * 4 * p;
        y[swz(st + 1, ob)]         = c_add(za0, zb0);
        y[swz(st + 1, ob + s)]     = c_add(za1, zb1);
        y[swz(st + 1, ob + 2 * s)] = c_mul(c_sub(za0, zb0), w2);
        y[swz(st + 1, ob + 3 * s)] = c_mul(c_sub(za1, zb1), w2);
        float2* t = x; x = y; y = t;
        n4 >>= 2; s <<= 2;
    }
    __syncthreads();
    return x;
}

// -------- fused QKV FFT, 2 rows/block via real-packing; half2 outputs -------
__global__ __launch_bounds__(256) void fft_qkv_pair_kernel() {
    __shared__ __align__(16) float2 bufA[1024];
    __shared__ __align__(16) float2 bufB[1024];
    __shared__ __align__(16) float2 kb0[1024];
    __shared__ __align__(16) float2 kb1[1024];
    size_t row0 = (size_t)blockIdx.x * 2;
    size_t row1 = row0 + 1;
    int tid = threadIdx.x;
    const float* b0 = g_qkv + row0 * NQKV;
    const float* b1 = g_qkv + row1 * NQKV;

    // --- FFT 1: q0 + i*k0 ---
    #pragma unroll
    for (int j = 0; j < 4; j++) {
        int idx = tid + j * 256;
        bufA[idx] = make_float2(b0[idx], b0[1024 + idx]);
    }
    float2* res = fft1024(bufA, bufB);
    uint32_t* qp0 = g_Qhat + row0 * DIM;
    #pragma unroll
    for (int j = 0; j < 4; j++) {
        int idx = tid + j * 256;
        int midx = (1024 - idx) & 1023;
        float2 Zc = res[idx];
        float2 Zm = res[midx];
        float2 fq = c_norm(make_float2(Zc.x + Zm.x, Zc.y - Zm.y));
        float2 fk = c_norm(make_float2(Zc.y + Zm.y, Zm.x - Zc.x));
        qp0[idx] = pack_f16(fq.x, fq.y);
        kb0[idx] = fk;
    }
    __syncthreads();

    // --- FFT 2: q1 + i*k1 ---
    #pragma unroll
    for (int j = 0; j < 4; j++) {
        int idx = tid + j * 256;
        bufA[idx] = make_float2(b1[idx], b1[1024 + idx]);
    }
    res = fft1024(bufA, bufB);
    uint32_t* qp1 = g_Qhat + row1 * DIM;
    #pragma unroll
    for (int j = 0; j < 4; j++) {
        int idx = tid + j * 256;
        int midx = (1024 - idx) & 1023;
        float2 Zc = res[idx];
        float2 Zm = res[midx];
        float2 fq = c_norm(make_float2(Zc.x + Zm.x, Zc.y - Zm.y));
        float2 fk = c_norm(make_float2(Zc.y + Zm.y, Zm.x - Zc.x));
        qp1[idx] = pack_f16(fq.x, fq.y);
        kb1[idx] = fk;
    }
    __syncthreads();

    // --- FFT 3: v0 + i*v1 ---
    #pragma unroll
    for (int j = 0; j < 4; j++) {
        int idx = tid + j * 256;
        bufA[idx] = make_float2(b0[2048 + idx], b1[2048 + idx]);
    }
    res = fft1024(bufA, bufB);
    uint32_t* mp0 = g_Mhat + row0 * DIM;
    uint32_t* mp1 = g_Mhat + row1 * DIM;
    #pragma unroll
    for (int j = 0; j < 4; j++) {
        int idx = tid + j * 256;
        int midx = (1024 - idx) & 1023;
        float2 Zc = res[idx];
        float2 Zm = res[midx];
        float2 v0 = c_norm(make_float2(Zc.x + Zm.x, Zc.y - Zm.y));
        float2 v1 = c_norm(make_float2(Zc.y + Zm.y, Zm.x - Zc.x));
        float2 p0 = c_mul(kb0[idx], v0);
        float2 p1 = c_mul(kb1[idx], v1);
        mp0[idx] = pack_f16(p0.x, p0.y);
        mp1[idx] = pack_f16(p1.x, p1.y);
    }
}

// ---------------- chain pass A: per-chunk partial sums (64 chunks) ----------
__global__ __launch_bounds__(256) void chain_partial_kernel() {
    int gid = blockIdx.x * 256 + threadIdx.x;   // 262144 threads
    int bin = gid & 1023;
    int chunk = (gid >> 10) & (CHUNKS - 1);
    int b = gid >> 16;
    size_t base = ((size_t)b * SEQ + (size_t)chunk * TCHUNK) * DIM + bin;
    float2 s = make_float2(0.f, 0.f);
    #pragma unroll 4
    for (int i = 0; i < TCHUNK; i++) {
        float2 p = unpack_f16(g_Mhat[base + (size_t)i * DIM]);
        s.x += p.x; s.y += p.y;
    }
    g_part[gid] = s;
}

// --------- chain pass A2: exclusive scan of chunk sums (tiny) ---------------
__global__ __launch_bounds__(256) void chain_scan_kernel() {
    int gid = blockIdx.x * 256 + threadIdx.x;   // 4096 threads: (b, bin)
    int bin = gid & 1023;
    int b = gid >> 10;
    float2 acc = make_float2(0.f, 0.f);
    for (int c = 0; c < CHUNKS; c++) {
        size_t idx = ((size_t)(b * CHUNKS + c) << 10) + bin;
        float2 p = g_part[idx];
        g_part[idx] = acc;            // exclusive prefix
        acc.x += p.x; acc.y += p.y;
    }
}

// ---------------- chain pass B: scan within chunk + apply conj(Q̂) --------
__global__ __launch_bounds__(256) void chain_apply_kernel() {
    int gid = blockIdx.x * 256 + threadIdx.x;
    int bin = gid & 1023;
    int chunk = (gid >> 10) & (CHUNKS - 1);
    int b = gid >> 16;
    float2 acc = g_part[((size_t)(b * CHUNKS + chunk) << 10) + bin];
    size_t base = ((size_t)b * SEQ + (size_t)chunk * TCHUNK) * DIM + bin;
    #pragma unroll 4
    for (int i = 0; i < TCHUNK; i++) {
        size_t off = base + (size_t)i * DIM;
        float2 p = unpack_f16(g_Mhat[off]);
        acc.x += p.x; acc.y += p.y;
        float2 q = unpack_f16(g_Qhat[off]);
        g_Mhat[off] = pack_f16(acc.x * q.x + acc.y * q.y,
                               acc.y * q.x - acc.x * q.y);
    }
}

// ------- paired inverse FFT + residual + LN2 (2 rows per block) --------
__global__ __launch_bounds__(256) void ifft_res_ln_pair_kernel(
    const float* __restrict__ x, const float* __restrict__ g,
    const float* __restrict__ b, uint16_t* __restrict__ o16)
{
    __shared__ __align__(16) float2 bufA[1024];
    __shared__ __align__(16) float2 bufB[1024];
    size_t row0 = (size_t)blockIdx.x * 2;
    size_t row1 = row0 + 1;
    int tid = threadIdx.x;
    const uint32_t* m0 = g_Mhat + row0 * DIM;
    const uint32_t* m1 = g_Mhat + row1 * DIM;
    #pragma unroll
    for (int j = 0; j < 4; j++) {
        int idx = tid + j * 256;
        float2 a = unpack_f16(m0[idx]);
        float2 c = unpack_f16(m1[idx]);
        bufA[idx] = make_float2(a.x + c.y, c.x - a.y);
    }
    float2* res = fft1024(bufA, bufB);   // = bufB; Y = N*(r0 + i*r1)
    float mixed0[4], mixed1[4];
    #pragma unroll
    for (int j = 0; j < 4; j++) {
        float2 Y = res[tid + j * 256];
        mixed0[j] = Y.x * (1.0f / 1024.0f);
        mixed1[j] = Y.y * (1.0f / 1024.0f);
    }
    __syncthreads();
    float* s0 = (float*)bufA;
    float* s1 = s0 + 1024;
    const float* xp0 = x + row0 * DIM;
    const float* xp1 = x + row1 * DIM;
    float* xo0 = g_xmid + row0 * DIM;
    float* xo1 = g_xmid + row1 * DIM;
    float su0 = 0.f, ss0 = 0.f, su1 = 0.f, ss1 = 0.f;
    #pragma unroll
    for (int j = 0; j < 4; j++) {
        int idx = tid + j * 256;
        float v0 = xp0[idx] + mixed0[j];
        float v1 = xp1[idx] + mixed1[j];
        xo0[idx] = v0; s0[idx] = v0;
        xo1[idx] = v1; s1[idx] = v1;
        su0 += v0; ss0 += v0 * v0;
        su1 += v1; ss1 += v1 * v1;
    }
    __syncthreads();
    float4 tot = block_reduce4(make_float4(su0, ss0, su1, ss1), (float4*)bufB);
    float mu0 = tot.x * (1.0f / DIM);
    float rstd0 = rsqrtf(tot.y * (1.0f / DIM) - mu0 * mu0 + 1e-5f);
    float mu1 = tot.z * (1.0f / DIM);
    float rstd1 = rsqrtf(tot.w * (1.0f / DIM) - mu1 * mu1 + 1e-5f);
    float4 gg = ((const float4*)g)[tid];
    float4 bb = ((const float4*)b)[tid];
    uint32_t* w = (uint32_t*)o16;
    {
        float4 vv = ((const float4*)s0)[tid];
        float y0 = (vv.x - mu0) * rstd0 * gg.x + bb.x;
        float y1 = (vv.y - mu0) * rstd0 * gg.y + bb.y;
        float y2 = (vv.z - mu0) * rstd0 * gg.z + bb.z;
        float y3 = (vv.w - mu0) * rstd0 * gg.w + bb.w;
        size_t wb = row0 * 512 + tid * 2;
        w[wb]     = pack_f16(y0, y1);
        w[wb + 1] = pack_f16(y2, y3);
    }
    {
        float4 vv = ((const float4*)s1)[tid];
        float y0 = (vv.x - mu1) * rstd1 * gg.x + bb.x;
        float y1 = (vv.y - mu1) * rstd1 * gg.y + bb.y;
        float y2 = (vv.z - mu1) * rstd1 * gg.z + bb.z;
        float y3 = (vv.w - mu1) * rstd1 * gg.w + bb.w;
        size_t wb = row1 * 512 + tid * 2;
        w[wb]     = pack_f16(y0, y1);
        w[wb + 1] = pack_f16(y2, y3);
    }
}

// ================== bf16x3 mma.sync GEMM (QKV), 256x128 CTA tile ============
#define A_PL_B 20480u
#define B_PL_B 10240u
#define BSTAGE_B 61440u
#define BSTAGE_W 15360u
#define SMEM_BGEMM (2 * BSTAGE_B)         // 122880

__global__ __launch_bounds__(256) void mma_gemm_qkv(
    const uint16_t* __restrict__ Ahi, const uint16_t* __restrict__ Alo,
    const uint16_t* __restrict__ Bhi, const uint16_t* __restrict__ Blo,
    const float* __restrict__ bias, float* __restrict__ Cf, int N, int K)
{
    extern __shared__ uint32_t smu[];
    uint32_t su = smem_u32(smu);

    int tid = threadIdx.x;
    int wid = tid >> 5;
    int lane = tid & 31;
    int wm = wid & 3;
    int wn = wid >> 2;
    int bx = blockIdx.x, by = blockIdx.y;
    int gq = lane >> 2, tq = lane & 3;

    const uint16_t* aH = Ahi + (size_t)(by * 256 + tid) * K;
    const uint16_t* aL = Alo + (size_t)(by * 256 + tid) * K;
    int brow = tid >> 1;
    int bcp = (tid & 1) * 2;
    const uint16_t* bH = Bhi + (size_t)(bx * 128 + brow) * K;
    const uint16_t* bL = Blo + (size_t)(bx * 128 + brow) * K;

    #define BLOAD_STAGE(s, k0) do { \
        uint32_t _sb = su + (uint32_t)(s) * BSTAGE_B; \
        uint32_t _da = _sb + (uint32_t)tid * 80u; \
        _Pragma("unroll") \
        for (int c = 0; c < 4; c++) { \
            cpa16(_da + c * 16,           aH + (k0) + c * 8); \
            cpa16(_da + A_PL_B + c * 16,  aL + (k0) + c * 8); \
        } \
        uint32_t _db = _sb + 2 * A_PL_B + (uint32_t)brow * 80u + (uint32_t)bcp * 16u; \
        _Pragma("unroll") \
        for (int c = 0; c < 2; c++) { \
            cpa16(_db + c * 16,           bH + (k0) + (bcp + c) * 8); \
            cpa16(_db + B_PL_B + c * 16,  bL + (k0) + (bcp + c) * 8); \
        } \
        asm volatile("cp.async.commit_group;" ::: "memory"); \
    } while (0)

    float acc[4][8][4];
    #pragma unroll
    for (int mt = 0; mt < 4; mt++)
        #pragma unroll
        for (int nt = 0; nt < 8; nt++)
            #pragma unroll
            for (int i = 0; i < 4; i++) acc[mt][nt][i] = 0.f;

    int KT = K >> 5;
    BLOAD_STAGE(0, 0);

    int aBase0 = (wm * 64 + gq) * 20 + tq;
    int bBase0 = (wn * 64 + gq) * 20 + tq;

    for (int it = 0; it < KT; it++) {
        asm volatile("cp.async.wait_group 0;" ::: "memory");
        __syncthreads();
        if (it + 1 < KT) BLOAD_STAGE((it + 1) & 1, (it + 1) * 32);

        int s = it & 1;
        const uint32_t* ah_t = smu + s * BSTAGE_W;
        const uint32_t* al_t = ah_t + 5120;
        const uint32_t* bh_t = ah_t + 10240;
        const uint32_t* bl_t = ah_t + 12800;

        #pragma unroll
        for (int ks = 0; ks < 2; ks++) {
            int ko = ks * 8;
            uint32_t ah[4][4], al[4][4], bb[8][2];
            #pragma unroll
            for (int mt = 0; mt < 4; mt++) {
                int base = aBase0 + mt * 320 + ko;
                ah[mt][0] = ah_t[base];
                ah[mt][1] = ah_t[base + 160];
                ah[mt][2] = ah_t[base + 4];
                ah[mt][3] = ah_t[base + 164];
                al[mt][0] = al_t[base];
                al[mt][1] = al_t[base + 160];
                al[mt][2] = al_t[base + 4];
                al[mt][3] = al_t[base + 164];
            }
            #pragma unroll
            for (int nt = 0; nt < 8; nt++) {
                int base = bBase0 + nt * 160 + ko;
                bb[nt][0] = bh_t[base];
                bb[nt][1] = bh_t[base + 4];
            }
            #pragma unroll
            for (int mt = 0; mt < 4; mt++)
                #pragma unroll
                for (int nt = 0; nt < 8; nt++) {
                    mma_bf16(acc[mt][nt], ah[mt], bb[nt]);
                    mma_bf16(acc[mt][nt], al[mt], bb[nt]);
                }
            #pragma unroll
            for (int nt = 0; nt < 8; nt++) {
                int base = bBase0 + nt * 160 + ko;
                bb[nt][0] = bl_t[base];
                bb[nt][1] = bl_t[base + 4];
            }
            #pragma unroll
            for (int mt = 0; mt < 4; mt++)
                #pragma unroll
                for (int nt = 0; nt < 8; nt++)
                    mma_bf16(acc[mt][nt], ah[mt], bb[nt]);
        }
        __syncthreads();
    }

    #pragma unroll
    for (int mt = 0; mt < 4; mt++) {
        #pragma unroll
        for (int nt = 0; nt < 8; nt++) {
            int r0 = by * 256 + wm * 64 + mt * 16 + gq;
            int c0 = bx * 128 + wn * 64 + nt * 8 + tq * 2;
            float b0 = bias[c0], b1 = bias[c0 + 1];
            #pragma unroll
            for (int half = 0; half < 2; half++) {
                size_t r = r0 + half * 8;
                float2 o;
                o.x = acc[mt][nt][half * 2 + 0] + b0;
                o.y = acc[mt][nt][half * 2 + 1] + b1;
                *(float2*)(Cf + r * (size_t)N + c0) = o;
            }
        }
    }
}

// ================== fp16 single-pass mma.sync GEMM (MLP), 256x128 tile ======
#define FA_PL_B 20480u
#define FSTAGE_B 30720u
#define FSTAGE_W 7680u
#define SMEM_FGEMM (2 * FSTAGE_B)         // 61440

template<int EPI>
__global__ __launch_bounds__(256) void mma_gemm_f16(
    const uint16_t* __restrict__ A, const uint16_t* __restrict__ B,
    const float* __restrict__ bias, const float* __restrict__ res,
    float* __restrict__ Cf, uint32_t* __restrict__ C16,
    int N, int K)
{
    extern __shared__ uint32_t smu[];
    uint32_t su = smem_u32(smu);

    int tid = threadIdx.x;
    int wid = tid >> 5;
    int lane = tid & 31;
    int wm = wid & 3;
    int wn = wid >> 2;
    int bx = blockIdx.x, by = blockIdx.y;
    int gq = lane >> 2, tq = lane & 3;

    const uint16_t* aP = A + (size_t)(by * 256 + tid) * K;
    int brow = tid >> 1;
    int bcp = (tid & 1) * 2;
    const uint16_t* bP = B + (size_t)(bx * 128 + brow) * K;

    #define FLOAD_STAGE(s, k0) do { \
        uint32_t _sb = su + (uint32_t)(s) * FSTAGE_B; \
        uint32_t _da = _sb + (uint32_t)tid * 80u; \
        _Pragma("unroll") \
        for (int c = 0; c < 4; c++) \
            cpa16(_da + c * 16, aP + (k0) + c * 8); \
        uint32_t _db = _sb + FA_PL_B + (uint32_t)brow * 80u + (uint32_t)bcp * 16u; \
        _Pragma("unroll") \
        for (int c = 0; c < 2; c++) \
            cpa16(_db + c * 16, bP + (k0) + (bcp + c) * 8); \
        asm volatile("cp.async.commit_group;" ::: "memory"); \
    } while (0)

    float acc[4][8][4];
    #pragma unroll
    for (int mt = 0; mt < 4; mt++)
        #pragma unroll
        for (int nt = 0; nt < 8; nt++)
            #pragma unroll
            for (int i = 0; i < 4; i++) acc[mt][nt][i] = 0.f;

    int KT = K >> 5;
    FLOAD_STAGE(0, 0);

    int aBase0 = (wm * 64 + gq) * 20 + tq;
    int bBase0 = (wn * 64 + gq) * 20 + tq;

    for (int it = 0; it < KT; it++) {
        asm volatile("cp.async.wait_group 0;" ::: "memory");
        __syncthreads();
        if (it + 1 < KT) FLOAD_STAGE((it + 1) & 1, (it + 1) * 32);

        int s = it & 1;
        const uint32_t* a_t = smu + s * FSTAGE_W;
        const uint32_t* b_t = a_t + 5120;

        #pragma unroll
        for (int ks = 0; ks < 2; ks++) {
            int ko = ks * 8;
            uint32_t ah[4][4], bb[8][2];
            #pragma unroll
            for (int mt = 0; mt < 4; mt++) {
                int base = aBase0 + mt * 320 + ko;
                ah[mt][0] = a_t[base];
                ah[mt][1] = a_t[base + 160];
                ah[mt][2] = a_t[base + 4];
                ah[mt][3] = a_t[base + 164];
            }
            #pragma unroll
            for (int nt = 0; nt < 8; nt++) {
                int base = bBase0 + nt * 160 + ko;
                bb[nt][0] = b_t[base];
                bb[nt][1] = b_t[base + 4];
            }
            #pragma unroll
            for (int mt = 0; mt < 4; mt++)
                #pragma unroll
                for (int nt = 0; nt < 8; nt++)
                    mma_f16(acc[mt][nt], ah[mt], bb[nt]);
        }
        __syncthreads();
    }

    #pragma unroll
    for (int mt = 0; mt < 4; mt++) {
        #pragma unroll
        for (int nt = 0; nt < 8; nt++) {
            int r0 = by * 256 + wm * 64 + mt * 16 + gq;
            int c0 = bx * 128 + wn * 64 + nt * 8 + tq * 2;
            float b0 = bias[c0], b1 = bias[c0 + 1];
            #pragma unroll
            for (int half = 0; half < 2; half++) {
                size_t r = r0 + half * 8;
                float v0 = acc[mt][nt][half * 2 + 0] + b0;
                float v1 = acc[mt][nt][half * 2 + 1] + b1;
                if (EPI == 1) {
                    v0 = 0.5f * v0 * (1.0f + erff(v0 * 0.70710678118654752f));
                    v1 = 0.5f * v1 * (1.0f + erff(v1 * 0.70710678118654752f));
                    C16[(r * (size_t)N + c0) >> 1] = pack_f16(v0, v1);
                } else {
                    float2 rv = *(const float2*)(res + r * (size_t)N + c0);
                    v0 += rv.x; v1 += rv.y;
                    float2 o; o.x = v0; o.y = v1;
                    *(float2*)(Cf + r * (size_t)N + c0) = o;
                }
            }
        }
    }
}

// ---------------- launch ----------------
extern "C" void kernel_launch(void* const* d_in, const int* in_sizes, int n_in,
                              void* d_out, int out_size)
{
    const float* x     = (const float*)d_in[0];
    const float* Wq    = (const float*)d_in[1];
    const float* bq    = (const float*)d_in[2];
    const float* Wk    = (const float*)d_in[3];
    const float* bk    = (const float*)d_in[4];
    const float* Wv    = (const float*)d_in[5];
    const float* bv    = (const float*)d_in[6];
    const float* ln1_g = (const float*)d_in[7];
    const float* ln1_b = (const float*)d_in[8];
    const float* ln2_g = (const float*)d_in[9];
    const float* ln2_b = (const float*)d_in[10];
    const float* W1    = (const float*)d_in[11];
    const float* b1    = (const float*)d_in[12];
    const float* W2    = (const float*)d_in[13];
    const float* b2    = (const float*)d_in[14];
    float* out = (float*)d_out;

    uint16_t *hHi, *hLo, *WqkvHi, *WqkvLo, *W116, *W216, *h216, *m116;
    float *qkv, *xmid, *bqkv;
    cudaGetSymbolAddress((void**)&hHi,    g_h_hi);
    cudaGetSymbolAddress((void**)&hLo,    g_h_lo);
    cudaGetSymbolAddress((void**)&WqkvHi, g_Wqkv_hi);
    cudaGetSymbolAddress((void**)&WqkvLo, g_Wqkv_lo);
    cudaGetSymbolAddress((void**)&W116,   g_W116);
    cudaGetSymbolAddress((void**)&W216,   g_W216);
    cudaGetSymbolAddress((void**)&h216,   g_h216);
    cudaGetSymbolAddress((void**)&m116,   g_m116);
    cudaGetSymbolAddress((void**)&qkv,    g_qkv);
    cudaGetSymbolAddress((void**)&xmid,   g_xmid);
    cudaGetSymbolAddress((void**)&bqkv,   g_bqkv);

    cudaFuncSetAttribute(mma_gemm_qkv, cudaFuncAttributeMaxDynamicSharedMemorySize, SMEM_BGEMM);
    cudaFuncSetAttribute(mma_gemm_f16<1>, cudaFuncAttributeMaxDynamicSharedMemorySize, SMEM_FGEMM);
    cudaFuncSetAttribute(mma_gemm_f16<2>, cudaFuncAttributeMaxDynamicSharedMemorySize, SMEM_FGEMM);

    init_tw_kernel<<<1, 512>>>();
    bias_concat_kernel<<<NQKV / 256, 256>>>(bq, bk, bv);

    // QKV weights -> bf16 hi/lo planes (one launch); MLP weights -> fp16
    transpose_split_qkv_kernel<<<dim3(32, 32, 3), dim3(32, 8)>>>(Wq, Wk, Wv);
    transpose_f16_kernel<<<dim3(128, 32), dim3(32, 8)>>>(W1, W116, DIM, HID);
    transpose_f16_kernel<<<dim3(32, 128), dim3(32, 8)>>>(W2, W216, HID, DIM);

    // LN1 -> bf16 planes
    ln_split_kernel<<<NROW, 256>>>(x, ln1_g, ln1_b, hHi, hLo);

    // fused QKV projection (bf16x3, high precision for the amplified path)
    mma_gemm_qkv<<<dim3(NQKV / 128, NROW / 256), 256, SMEM_BGEMM>>>(
        hHi, hLo, WqkvHi, WqkvLo, bqkv, qkv, NQKV, DIM);

    // fused FFT + normalize for q,k,v — real-packed, 2 rows/block
    fft_qkv_pair_kernel<<<NROW / 2, 256>>>();

    // causal cumsum in Fourier domain (3-level scan), fused * conj(Q̂)
    chain_partial_kernel<<<(NBATCH * CHUNKS * DIM) / 256, 256>>>();
    chain_scan_kernel<<<(NBATCH * DIM) / 256, 256>>>();
    chain_apply_kernel<<<(NBATCH * CHUNKS * DIM) / 256, 256>>>();

    // paired inverse FFT + residual + LN2 (2 rows per transform)
    ifft_res_ln_pair_kernel<<<NROW / 2, 256>>>(x, ln2_g, ln2_b, h216);

    // MLP (fp16 single-pass)
    mma_gemm_f16<1><<<dim3(HID / 128, NROW / 256), 256, SMEM_FGEMM>>>(
        h216, W116, b1, nullptr, nullptr, (uint32_t*)m116, HID, DIM);
    mma_gemm_f16<2><<<dim3(DIM / 128, NROW / 256), 256, SMEM_FGEMM>>>(
        m116, W216, b2, xmid, out, nullptr, DIM, HID);

    (void)in_sizes; (void)n_in; (void)out_size;
}

// round 16
// speedup vs baseline: 3.6086x; 1.0044x over previous
#include <cuda_runtime.h>
#include <cuda_fp16.h>
#include <math.h>
#include <math_constants.h>
#include <stdint.h>

#define NROW 8192   // B*S
#define DIM  1024
#define SEQ  2048
#define NBATCH 4
#define HID  4096
#define CHUNKS 64
#define TCHUNK (SEQ / CHUNKS)   // 32
#define NQKV 3072

// ---------------- scratch (static device globals; no runtime alloc) ----------
__device__ uint16_t g_h_hi[(size_t)NROW * DIM];      // bf16 planes (QKV path)
__device__ uint16_t g_h_lo[(size_t)NROW * DIM];
__device__ uint16_t g_Wqkv_hi[(size_t)NQKV * DIM];
__device__ uint16_t g_Wqkv_lo[(size_t)NQKV * DIM];
__device__ uint16_t g_W116[(size_t)HID * DIM];       // fp16 transposed weights
__device__ uint16_t g_W216[(size_t)DIM * HID];
__device__ uint16_t g_h216[(size_t)NROW * DIM];      // fp16 h2
__device__ uint16_t g_m116[(size_t)NROW * HID];      // fp16 m1
__device__ float  g_qkv[(size_t)NROW * NQKV];
__device__ float  g_bqkv[NQKV];
__device__ uint32_t g_Qhat[(size_t)NROW * DIM];      // half2 complex
__device__ uint32_t g_Mhat[(size_t)NROW * DIM];      // half2 complex (K̂V̂ -> cumsum S)
__device__ float  g_xmid[(size_t)NROW * DIM];
__device__ float2 g_tw[512];
__device__ float2 g_part[NBATCH * CHUNKS * DIM];

// ---------------- helpers ----------------
__device__ __forceinline__ uint32_t smem_u32(const void* p) {
    uint32_t a;
    asm("{ .reg .u64 t; cvta.to.shared.u64 t, %1; cvt.u32.u64 %0, t; }" : "=r"(a) : "l"(p));
    return a;
}
__device__ __forceinline__ uint32_t pack_f16(float x0, float x1) {
    uint32_t h;
    asm("cvt.rn.f16x2.f32 %0, %1, %2;" : "=r"(h) : "f"(x1), "f"(x0));
    return h;
}
__device__ __forceinline__ float2 unpack_f16(uint32_t w) {
    __half2 h = *(__half2*)&w;
    return __half22float2(h);
}
// split pair (x0,x1) -> packed bf16x2 hi (low half = x0) and lo
__device__ __forceinline__ void split2(float x0, float x1, uint32_t& hi, uint32_t& lo) {
    uint32_t h;
    asm("cvt.rn.bf16x2.f32 %0, %1, %2;" : "=r"(h) : "f"(x1), "f"(x0));
    float h0 = __uint_as_float(h << 16);
    float h1 = __uint_as_float(h & 0xFFFF0000u);
    float l0 = x0 - h0;
    float l1 = x1 - h1;
    asm("cvt.rn.bf16x2.f32 %0, %1, %2;" : "=r"(lo) : "f"(l1), "f"(l0));
    hi = h;
}
__device__ __forceinline__ void mma_bf16(float* d, const uint32_t* a, const uint32_t* b) {
    asm volatile("mma.sync.aligned.m16n8k16.row.col.f32.bf16.bf16.f32 "
        "{%0,%1,%2,%3}, {%4,%5,%6,%7}, {%8,%9}, {%0,%1,%2,%3};"
        : "+f"(d[0]), "+f"(d[1]), "+f"(d[2]), "+f"(d[3])
        : "r"(a[0]), "r"(a[1]), "r"(a[2]), "r"(a[3]), "r"(b[0]), "r"(b[1]));
}
__device__ __forceinline__ void mma_f16(float* d, const uint32_t* a, const uint32_t* b) {
    asm volatile("mma.sync.aligned.m16n8k16.row.col.f32.f16.f16.f32 "
        "{%0,%1,%2,%3}, {%4,%5,%6,%7}, {%8,%9}, {%0,%1,%2,%3};"
        : "+f"(d[0]), "+f"(d[1]), "+f"(d[2]), "+f"(d[3])
        : "r"(a[0]), "r"(a[1]), "r"(a[2]), "r"(a[3]), "r"(b[0]), "r"(b[1]));
}
__device__ __forceinline__ void cpa16(uint32_t dst, const void* src) {
    asm volatile("cp.async.cg.shared.global [%0], [%1], 16;" :: "r"(dst), "l"(src) : "memory");
}
__device__ __forceinline__ float2 c_add(float2 a, float2 b){return make_float2(a.x+b.x,a.y+b.y);}
__device__ __forceinline__ float2 c_sub(float2 a, float2 b){return make_float2(a.x-b.x,a.y-b.y);}
__device__ __forceinline__ float2 c_mul(float2 a, float2 b){return make_float2(a.x*b.x-a.y*b.y,a.x*b.y+a.y*b.x);}
__device__ __forceinline__ float2 c_mulc(float2 s, float2 q){  // s * conj(q)
    return make_float2(s.x*q.x + s.y*q.y, s.y*q.x - s.x*q.y);
}
__device__ __forceinline__ float2 c_negi(float2 a){return make_float2(a.y,-a.x);}
__device__ __forceinline__ float2 c_norm(float2 f) {
    float inv = 1.0f / fmaxf(sqrtf(f.x * f.x + f.y * f.y), 1e-8f);
    return make_float2(f.x * inv, f.y * inv);
}

// ---------------- small init kernels ----------------
__global__ void init_tw_kernel() {
    int i = threadIdx.x;
    double th = -2.0 * CUDART_PI * (double)i / 1024.0;
    g_tw[i] = make_float2((float)cos(th), (float)sin(th));
}
__global__ void bias_concat_kernel(const float* bq, const float* bk, const float* bv) {
    int i = blockIdx.x * 256 + threadIdx.x;
    float v = (i < 1024) ? bq[i] : (i < 2048) ? bk[i - 1024] : bv[i - 2048];
    g_bqkv[i] = v;
}

// ------- QKV weight transpose + bf16 split, all 3 weights in one launch -----
__global__ __launch_bounds__(256) void transpose_split_qkv_kernel(
    const float* __restrict__ Wq, const float* __restrict__ Wk,
    const float* __restrict__ Wv)
{
    __shared__ float t[32][33];
    int bx = blockIdx.x, by = blockIdx.y, bz = blockIdx.z;
    const float* in = (bz == 0) ? Wq : (bz == 1) ? Wk : Wv;
    uint16_t* ohi = g_Wqkv_hi + (size_t)bz * 1024 * DIM;
    uint16_t* olo = g_Wqkv_lo + (size_t)bz * 1024 * DIM;
    int x = bx * 32 + threadIdx.x;
    int y0 = by * 32 + threadIdx.y;
    #pragma unroll
    for (int j = 0; j < 32; j += 8)
        t[threadIdx.y + j][threadIdx.x] = in[(size_t)(y0 + j) * DIM + x];
    __syncthreads();
    int tl = threadIdx.y * 32 + threadIdx.x;
    int kp = tl & 15;
    int nr0 = tl >> 4;
    uint32_t* hw32 = (uint32_t*)ohi;
    uint32_t* lw32 = (uint32_t*)olo;
    #pragma unroll
    for (int rep = 0; rep < 2; rep++) {
        int nrel = nr0 + rep * 16;
        size_t n = (size_t)bx * 32 + nrel;
        int kg = by * 32 + kp * 2;
        uint32_t hw, lw;
        split2(t[kp * 2][nrel], t[kp * 2 + 1][nrel], hw, lw);
        size_t widx = (n * (size_t)DIM + kg) >> 1;
        hw32[widx] = hw;
        lw32[widx] = lw;
    }
}

// ---------------- weight transpose to fp16 (MLP) ----------------
__global__ __launch_bounds__(256) void transpose_f16_kernel(
    const float* __restrict__ in, uint16_t* __restrict__ o16, int R, int C)
{
    __shared__ float t[32][33];
    int bx = blockIdx.x, by = blockIdx.y;
    int x = bx * 32 + threadIdx.x;
    int y0 = by * 32 + threadIdx.y;
    #pragma unroll
    for (int j = 0; j < 32; j += 8)
        t[threadIdx.y + j][threadIdx.x] = in[(size_t)(y0 + j) * C + x];
    __syncthreads();
    int tl = threadIdx.y * 32 + threadIdx.x;
    int kp = tl & 15;
    int nr0 = tl >> 4;
    uint32_t* w32 = (uint32_t*)o16;
    #pragma unroll
    for (int rep = 0; rep < 2; rep++) {
        int nrel = nr0 + rep * 16;
        size_t n = (size_t)bx * 32 + nrel;
        int kg = by * 32 + kp * 2;
        w32[(n * (size_t)R + kg) >> 1] = pack_f16(t[kp * 2][nrel], t[kp * 2 + 1][nrel]);
    }
}

// ---------------- block reductions ----------------
__device__ __forceinline__ float2 block_reduce2(float2 v, float2* sh) {
    int tid = threadIdx.x;
    sh[tid] = v;
    __syncthreads();
    #pragma unroll
    for (int s = 128; s > 0; s >>= 1) {
        if (tid < s) {
            sh[tid].x += sh[tid + s].x;
            sh[tid].y += sh[tid + s].y;
        }
        __syncthreads();
    }
    float2 r = sh[0];
    __syncthreads();
    return r;
}
__device__ __forceinline__ float4 block_reduce4(float4 v, float4* sh) {
    int tid = threadIdx.x;
    sh[tid] = v;
    __syncthreads();
    #pragma unroll
    for (int s = 128; s > 0; s >>= 1) {
        if (tid < s) {
            sh[tid].x += sh[tid + s].x;
            sh[tid].y += sh[tid + s].y;
            sh[tid].z += sh[tid + s].z;
            sh[tid].w += sh[tid + s].w;
        }
        __syncthreads();
    }
    float4 r = sh[0];
    __syncthreads();
    return r;
}

// ---------------- LayerNorm 1 -> bf16 hi/lo planes ----------------
__global__ __launch_bounds__(256) void ln_split_kernel(
    const float* __restrict__ x, const float* __restrict__ g,
    const float* __restrict__ b, uint16_t* __restrict__ ohi,
    uint16_t* __restrict__ olo)
{
    __shared__ float2 red[256];
    size_t row = blockIdx.x;
    int tid = threadIdx.x;
    float4 v = ((const float4*)(x + row * DIM))[tid];
    float s = v.x + v.y + v.z + v.w;
    float ss = v.x * v.x + v.y * v.y + v.z * v.z + v.w * v.w;
    float2 tot = block_reduce2(make_float2(s, ss), red);
    float mu = tot.x * (1.0f / DIM);
    float var = tot.y * (1.0f / DIM) - mu * mu;
    float rstd = rsqrtf(var + 1e-5f);
    float4 gg = ((const float4*)g)[tid];
    float4 bb = ((const float4*)b)[tid];
    float y0 = (v.x - mu) * rstd * gg.x + bb.x;
    float y1 = (v.y - mu) * rstd * gg.y + bb.y;
    float y2 = (v.z - mu) * rstd * gg.z + bb.z;
    float y3 = (v.w - mu) * rstd * gg.w + bb.w;
    uint32_t h0, l0, h1, l1;
    split2(y0, y1, h0, l0);
    split2(y2, y3, h1, l1);
    uint32_t* hw = (uint32_t*)ohi;
    uint32_t* lw = (uint32_t*)olo;
    size_t wb = row * 512 + tid * 2;
    hw[wb] = h0; hw[wb + 1] = h1;
    lw[wb] = l0; lw[wb + 1] = l1;
}

// -------- 1024-pt radix-4 Stockham FFT, bank-conflict-free swizzles --------
__device__ __forceinline__ int swz(int g, int a) {
    if (g == 1) return a ^ ((a >> 4) & 3);
    if (g == 2) return a ^ ((a >> 2) & 0xC);
    return a;
}
__device__ __forceinline__ float2* fft1024(float2* bufA, float2* bufB) {
    float2* x = bufA;
    float2* y = bufB;
    int n4 = 256, s = 1;
    #pragma unroll
    for (int st = 0; st < 5; st++) {
        __syncthreads();
        int i = threadIdx.x;
        int p = i / s;
        int q = i - p * s;
        float2 w1 = g_tw[p * s];
        float2 w2 = g_tw[2 * p * s];
        float2 x0 = x[swz(st, q + s * p)];
        float2 x1 = x[swz(st, q + s * (p + n4))];
        float2 x2 = x[swz(st, q + s * (p + 2 * n4))];
        float2 x3 = x[swz(st, q + s * (p + 3 * n4))];
        float2 za0 = c_add(x0, x2);
        float2 za1 = c_mul(c_sub(x0, x2), w1);
        float2 zb0 = c_add(x1, x3);
        float2 zb1 = c_mul(c_negi(c_sub(x1, x3)), w1);
        int ob = q + s * 4 * p;
        y[swz(st + 1, ob)]         = c_add(za0, zb0);
        y[swz(st + 1, ob + s)]     = c_add(za1, zb1);
        y[swz(st + 1, ob + 2 * s)] = c_mul(c_sub(za0, zb0), w2);
        y[swz(st + 1, ob + 3 * s)] = c_mul(c_sub(za1, zb1), w2);
        float2* t = x; x = y; y = t;
        n4 >>= 2; s <<= 2;
    }
    __syncthreads();
    return x;
}

// -------- fused QKV FFT, 2 rows/block via real-packing; half2 outputs -------
__global__ __launch_bounds__(256) void fft_qkv_pair_kernel() {
    __shared__ __align__(16) float2 bufA[1024];
    __shared__ __align__(16) float2 bufB[1024];
    __shared__ __align__(16) float2 kb0[1024];
    __shared__ __align__(16) float2 kb1[1024];
    size_t row0 = (size_t)blockIdx.x * 2;
    size_t row1 = row0 + 1;
    int tid = threadIdx.x;
    const float* b0 = g_qkv + row0 * NQKV;
    const float* b1 = g_qkv + row1 * NQKV;

    // --- FFT 1: q0 + i*k0 ---
    #pragma unroll
    for (int j = 0; j < 4; j++) {
        int idx = tid + j * 256;
        bufA[idx] = make_float2(b0[idx], b0[1024 + idx]);
    }
    float2* res = fft1024(bufA, bufB);
    uint32_t* qp0 = g_Qhat + row0 * DIM;
    #pragma unroll
    for (int j = 0; j < 4; j++) {
        int idx = tid + j * 256;
        int midx = (1024 - idx) & 1023;
        float2 Zc = res[idx];
        float2 Zm = res[midx];
        float2 fq = c_norm(make_float2(Zc.x + Zm.x, Zc.y - Zm.y));
        float2 fk = c_norm(make_float2(Zc.y + Zm.y, Zm.x - Zc.x));
        qp0[idx] = pack_f16(fq.x, fq.y);
        kb0[idx] = fk;
    }
    __syncthreads();

    // --- FFT 2: q1 + i*k1 ---
    #pragma unroll
    for (int j = 0; j < 4; j++) {
        int idx = tid + j * 256;
        bufA[idx] = make_float2(b1[idx], b1[1024 + idx]);
    }
    res = fft1024(bufA, bufB);
    uint32_t* qp1 = g_Qhat + row1 * DIM;
    #pragma unroll
    for (int j = 0; j < 4; j++) {
        int idx = tid + j * 256;
        int midx = (1024 - idx) & 1023;
        float2 Zc = res[idx];
        float2 Zm = res[midx];
        float2 fq = c_norm(make_float2(Zc.x + Zm.x, Zc.y - Zm.y));
        float2 fk = c_norm(make_float2(Zc.y + Zm.y, Zm.x - Zc.x));
        qp1[idx] = pack_f16(fq.x, fq.y);
        kb1[idx] = fk;
    }
    __syncthreads();

    // --- FFT 3: v0 + i*v1 ---
    #pragma unroll
    for (int j = 0; j < 4; j++) {
        int idx = tid + j * 256;
        bufA[idx] = make_float2(b0[2048 + idx], b1[2048 + idx]);
    }
    res = fft1024(bufA, bufB);
    uint32_t* mp0 = g_Mhat + row0 * DIM;
    uint32_t* mp1 = g_Mhat + row1 * DIM;
    #pragma unroll
    for (int j = 0; j < 4; j++) {
        int idx = tid + j * 256;
        int midx = (1024 - idx) & 1023;
        float2 Zc = res[idx];
        float2 Zm = res[midx];
        float2 v0 = c_norm(make_float2(Zc.x + Zm.x, Zc.y - Zm.y));
        float2 v1 = c_norm(make_float2(Zc.y + Zm.y, Zm.x - Zc.x));
        float2 p0 = c_mul(kb0[idx], v0);
        float2 p1 = c_mul(kb1[idx], v1);
        mp0[idx] = pack_f16(p0.x, p0.y);
        mp1[idx] = pack_f16(p1.x, p1.y);
    }
}

// -------- chain pass A: per-chunk partial sums (2 bins/thread) --------------
__global__ __launch_bounds__(256) void chain_partial_kernel() {
    int gid = blockIdx.x * 256 + threadIdx.x;   // 131072 threads
    int bp = gid & 511;                          // bin pair 0..511
    int chunk = (gid >> 9) & (CHUNKS - 1);
    int b = gid >> 15;
    size_t base = ((size_t)b * SEQ + (size_t)chunk * TCHUNK) * DIM + (size_t)bp * 2;
    float2 s0 = make_float2(0.f, 0.f), s1 = make_float2(0.f, 0.f);
    #pragma unroll 4
    for (int i = 0; i < TCHUNK; i++) {
        uint2 w = *(const uint2*)&g_Mhat[base + (size_t)i * DIM];
        float2 p0 = unpack_f16(w.x);
        float2 p1 = unpack_f16(w.y);
        s0.x += p0.x; s0.y += p0.y;
        s1.x += p1.x; s1.y += p1.y;
    }
    size_t pidx = ((size_t)(b * CHUNKS + chunk) << 10) + (size_t)bp * 2;
    *(float4*)&g_part[pidx] = make_float4(s0.x, s0.y, s1.x, s1.y);
}

// --------- chain pass A2: exclusive scan of chunk sums (tiny) ---------------
__global__ __launch_bounds__(256) void chain_scan_kernel() {
    int gid = blockIdx.x * 256 + threadIdx.x;   // 4096 threads: (b, bin)
    int bin = gid & 1023;
    int b = gid >> 10;
    float2 acc = make_float2(0.f, 0.f);
    for (int c = 0; c < CHUNKS; c++) {
        size_t idx = ((size_t)(b * CHUNKS + c) << 10) + bin;
        float2 p = g_part[idx];
        g_part[idx] = acc;            // exclusive prefix
        acc.x += p.x; acc.y += p.y;
    }
}

// ------ chain pass B: cumsum within chunk (2 bins/thread); S -> Mhat --------
__global__ __launch_bounds__(256) void chain_apply_kernel() {
    int gid = blockIdx.x * 256 + threadIdx.x;
    int bp = gid & 511;
    int chunk = (gid >> 9) & (CHUNKS - 1);
    int b = gid >> 15;
    size_t pidx = ((size_t)(b * CHUNKS + chunk) << 10) + (size_t)bp * 2;
    float4 pr = *(const float4*)&g_part[pidx];
    float2 acc0 = make_float2(pr.x, pr.y);
    float2 acc1 = make_float2(pr.z, pr.w);
    size_t base = ((size_t)b * SEQ + (size_t)chunk * TCHUNK) * DIM + (size_t)bp * 2;
    #pragma unroll 4
    for (int i = 0; i < TCHUNK; i++) {
        size_t off = base + (size_t)i * DIM;
        uint2 w = *(const uint2*)&g_Mhat[off];
        float2 p0 = unpack_f16(w.x);
        float2 p1 = unpack_f16(w.y);
        acc0.x += p0.x; acc0.y += p0.y;
        acc1.x += p1.x; acc1.y += p1.y;
        uint2 o;
        o.x = pack_f16(acc0.x, acc0.y);
        o.y = pack_f16(acc1.x, acc1.y);
        *(uint2*)&g_Mhat[off] = o;
    }
}

// --- paired inverse FFT (applies conj(Q̂) at load) + residual + LN2 ---------
__global__ __launch_bounds__(256) void ifft_res_ln_pair_kernel(
    const float* __restrict__ x, const float* __restrict__ g,
    const float* __restrict__ b, uint16_t* __restrict__ o16)
{
    __shared__ __align__(16) float2 bufA[1024];
    __shared__ __align__(16) float2 bufB[1024];
    size_t row0 = (size_t)blockIdx.x * 2;
    size_t row1 = row0 + 1;
    int tid = threadIdx.x;
    const uint32_t* m0 = g_Mhat + row0 * DIM;
    const uint32_t* m1 = g_Mhat + row1 * DIM;
    const uint32_t* q0 = g_Qhat + row0 * DIM;
    const uint32_t* q1 = g_Qhat + row1 * DIM;
    #pragma unroll
    for (int j = 0; j < 4; j++) {
        int idx = tid + j * 256;
        float2 a = c_mulc(unpack_f16(m0[idx]), unpack_f16(q0[idx]));
        float2 c = c_mulc(unpack_f16(m1[idx]), unpack_f16(q1[idx]));
        // conj(M0) + i*conj(M1)
        bufA[idx] = make_float2(a.x + c.y, c.x - a.y);
    }
    float2* res = fft1024(bufA, bufB);   // = bufB; Y = N*(r0 + i*r1)
    float mixed0[4], mixed1[4];
    #pragma unroll
    for (int j = 0; j < 4; j++) {
        float2 Y = res[tid + j * 256];
        mixed0[j] = Y.x * (1.0f / 1024.0f);
        mixed1[j] = Y.y * (1.0f / 1024.0f);
    }
    __syncthreads();
    float* s0 = (float*)bufA;
    float* s1 = s0 + 1024;
    const float* xp0 = x + row0 * DIM;
    const float* xp1 = x + row1 * DIM;
    float* xo0 = g_xmid + row0 * DIM;
    float* xo1 = g_xmid + row1 * DIM;
    float su0 = 0.f, ss0 = 0.f, su1 = 0.f, ss1 = 0.f;
    #pragma unroll
    for (int j = 0; j < 4; j++) {
        int idx = tid + j * 256;
        float v0 = xp0[idx] + mixed0[j];
        float v1 = xp1[idx] + mixed1[j];
        xo0[idx] = v0; s0[idx] = v0;
        xo1[idx] = v1; s1[idx] = v1;
        su0 += v0; ss0 += v0 * v0;
        su1 += v1; ss1 += v1 * v1;
    }
    __syncthreads();
    float4 tot = block_reduce4(make_float4(su0, ss0, su1, ss1), (float4*)bufB);
    float mu0 = tot.x * (1.0f / DIM);
    float rstd0 = rsqrtf(tot.y * (1.0f / DIM) - mu0 * mu0 + 1e-5f);
    float mu1 = tot.z * (1.0f / DIM);
    float rstd1 = rsqrtf(tot.w * (1.0f / DIM) - mu1 * mu1 + 1e-5f);
    float4 gg = ((const float4*)g)[tid];
    float4 bb = ((const float4*)b)[tid];
    uint32_t* w = (uint32_t*)o16;
    {
        float4 vv = ((const float4*)s0)[tid];
        float y0 = (vv.x - mu0) * rstd0 * gg.x + bb.x;
        float y1 = (vv.y - mu0) * rstd0 * gg.y + bb.y;
        float y2 = (vv.z - mu0) * rstd0 * gg.z + bb.z;
        float y3 = (vv.w - mu0) * rstd0 * gg.w + bb.w;
        size_t wb = row0 * 512 + tid * 2;
        w[wb]     = pack_f16(y0, y1);
        w[wb + 1] = pack_f16(y2, y3);
    }
    {
        float4 vv = ((const float4*)s1)[tid];
        float y0 = (vv.x - mu1) * rstd1 * gg.x + bb.x;
        float y1 = (vv.y - mu1) * rstd1 * gg.y + bb.y;
        float y2 = (vv.z - mu1) * rstd1 * gg.z + bb.z;
        float y3 = (vv.w - mu1) * rstd1 * gg.w + bb.w;
        size_t wb = row1 * 512 + tid * 2;
        w[wb]     = pack_f16(y0, y1);
        w[wb + 1] = pack_f16(y2, y3);
    }
}

// ================== bf16x3 mma.sync GEMM (QKV), 256x128 CTA tile ============
#define A_PL_B 20480u
#define B_PL_B 10240u
#define BSTAGE_B 61440u
#define BSTAGE_W 15360u
#define SMEM_BGEMM (2 * BSTAGE_B)         // 122880

__global__ __launch_bounds__(256) void mma_gemm_qkv(
    const uint16_t* __restrict__ Ahi, const uint16_t* __restrict__ Alo,
    const uint16_t* __restrict__ Bhi, const uint16_t* __restrict__ Blo,
    const float* __restrict__ bias, float* __restrict__ Cf, int N, int K)
{
    extern __shared__ uint32_t smu[];
    uint32_t su = smem_u32(smu);

    int tid = threadIdx.x;
    int wid = tid >> 5;
    int lane = tid & 31;
    int wm = wid & 3;
    int wn = wid >> 2;
    int bx = blockIdx.x, by = blockIdx.y;
    int gq = lane >> 2, tq = lane & 3;

    const uint16_t* aH = Ahi + (size_t)(by * 256 + tid) * K;
    const uint16_t* aL = Alo + (size_t)(by * 256 + tid) * K;
    int brow = tid >> 1;
    int bcp = (tid & 1) * 2;
    const uint16_t* bH = Bhi + (size_t)(bx * 128 + brow) * K;
    const uint16_t* bL = Blo + (size_t)(bx * 128 + brow) * K;

    #define BLOAD_STAGE(s, k0) do { \
        uint32_t _sb = su + (uint32_t)(s) * BSTAGE_B; \
        uint32_t _da = _sb + (uint32_t)tid * 80u; \
        _Pragma("unroll") \
        for (int c = 0; c < 4; c++) { \
            cpa16(_da + c * 16,           aH + (k0) + c * 8); \
            cpa16(_da + A_PL_B + c * 16,  aL + (k0) + c * 8); \
        } \
        uint32_t _db = _sb + 2 * A_PL_B + (uint32_t)brow * 80u + (uint32_t)bcp * 16u; \
        _Pragma("unroll") \
        for (int c = 0; c < 2; c++) { \
            cpa16(_db + c * 16,           bH + (k0) + (bcp + c) * 8); \
            cpa16(_db + B_PL_B + c * 16,  bL + (k0) + (bcp + c) * 8); \
        } \
        asm volatile("cp.async.commit_group;" ::: "memory"); \
    } while (0)

    float acc[4][8][4];
    #pragma unroll
    for (int mt = 0; mt < 4; mt++)
        #pragma unroll
        for (int nt = 0; nt < 8; nt++)
            #pragma unroll
            for (int i = 0; i < 4; i++) acc[mt][nt][i] = 0.f;

    int KT = K >> 5;
    BLOAD_STAGE(0, 0);

    int aBase0 = (wm * 64 + gq) * 20 + tq;
    int bBase0 = (wn * 64 + gq) * 20 + tq;

    for (int it = 0; it < KT; it++) {
        asm volatile("cp.async.wait_group 0;" ::: "memory");
        __syncthreads();
        if (it + 1 < KT) BLOAD_STAGE((it + 1) & 1, (it + 1) * 32);

        int s = it & 1;
        const uint32_t* ah_t = smu + s * BSTAGE_W;
        const uint32_t* al_t = ah_t + 5120;
        const uint32_t* bh_t = ah_t + 10240;
        const uint32_t* bl_t = ah_t + 12800;

        #pragma unroll
        for (int ks = 0; ks < 2; ks++) {
            int ko = ks * 8;
            uint32_t ah[4][4], al[4][4], bb[8][2];
            #pragma unroll
            for (int mt = 0; mt < 4; mt++) {
                int base = aBase0 + mt * 320 + ko;
                ah[mt][0] = ah_t[base];
                ah[mt][1] = ah_t[base + 160];
                ah[mt][2] = ah_t[base + 4];
                ah[mt][3] = ah_t[base + 164];
                al[mt][0] = al_t[base];
                al[mt][1] = al_t[base + 160];
                al[mt][2] = al_t[base + 4];
                al[mt][3] = al_t[base + 164];
            }
            #pragma unroll
            for (int nt = 0; nt < 8; nt++) {
                int base = bBase0 + nt * 160 + ko;
                bb[nt][0] = bh_t[base];
                bb[nt][1] = bh_t[base + 4];
            }
            #pragma unroll
            for (int mt = 0; mt < 4; mt++)
                #pragma unroll
                for (int nt = 0; nt < 8; nt++) {
                    mma_bf16(acc[mt][nt], ah[mt], bb[nt]);
                    mma_bf16(acc[mt][nt], al[mt], bb[nt]);
                }
            #pragma unroll
            for (int nt = 0; nt < 8; nt++) {
                int base = bBase0 + nt * 160 + ko;
                bb[nt][0] = bl_t[base];
                bb[nt][1] = bl_t[base + 4];
            }
            #pragma unroll
            for (int mt = 0; mt < 4; mt++)
                #pragma unroll
                for (int nt = 0; nt < 8; nt++)
                    mma_bf16(acc[mt][nt], ah[mt], bb[nt]);
        }
        __syncthreads();
    }

    #pragma unroll
    for (int mt = 0; mt < 4; mt++) {
        #pragma unroll
        for (int nt = 0; nt < 8; nt++) {
            int r0 = by * 256 + wm * 64 + mt * 16 + gq;
            int c0 = bx * 128 + wn * 64 + nt * 8 + tq * 2;
            float b0 = bias[c0], b1 = bias[c0 + 1];
            #pragma unroll
            for (int half = 0; half < 2; half++) {
                size_t r = r0 + half * 8;
                float2 o;
                o.x = acc[mt][nt][half * 2 + 0] + b0;
                o.y = acc[mt][nt][half * 2 + 1] + b1;
                *(float2*)(Cf + r * (size_t)N + c0) = o;
            }
        }
    }
}

// ================== fp16 single-pass mma.sync GEMM (MLP), 256x128 tile ======
#define FA_PL_B 20480u
#define FSTAGE_B 30720u
#define FSTAGE_W 7680u
#define SMEM_FGEMM (2 * FSTAGE_B)         // 61440

template<int EPI>
__global__ __launch_bounds__(256) void mma_gemm_f16(
    const uint16_t* __restrict__ A, const uint16_t* __restrict__ B,
    const float* __restrict__ bias, const float* __restrict__ res,
    float* __restrict__ Cf, uint32_t* __restrict__ C16,
    int N, int K)
{
    extern __shared__ uint32_t smu[];
    uint32_t su = smem_u32(smu);

    int tid = threadIdx.x;
    int wid = tid >> 5;
    int lane = tid & 31;
    int wm = wid & 3;
    int wn = wid >> 2;
    int bx = blockIdx.x, by = blockIdx.y;
    int gq = lane >> 2, tq = lane & 3;

    const uint16_t* aP = A + (size_t)(by * 256 + tid) * K;
    int brow = tid >> 1;
    int bcp = (tid & 1) * 2;
    const uint16_t* bP = B + (size_t)(bx * 128 + brow) * K;

    #define FLOAD_STAGE(s, k0) do { \
        uint32_t _sb = su + (uint32_t)(s) * FSTAGE_B; \
        uint32_t _da = _sb + (uint32_t)tid * 80u; \
        _Pragma("unroll") \
        for (int c = 0; c < 4; c++) \
            cpa16(_da + c * 16, aP + (k0) + c * 8); \
        uint32_t _db = _sb + FA_PL_B + (uint32_t)brow * 80u + (uint32_t)bcp * 16u; \
        _Pragma("unroll") \
        for (int c = 0; c < 2; c++) \
            cpa16(_db + c * 16, bP + (k0) + (bcp + c) * 8); \
        asm volatile("cp.async.commit_group;" ::: "memory"); \
    } while (0)

    float acc[4][8][4];
    #pragma unroll
    for (int mt = 0; mt < 4; mt++)
        #pragma unroll
        for (int nt = 0; nt < 8; nt++)
            #pragma unroll
            for (int i = 0; i < 4; i++) acc[mt][nt][i] = 0.f;

    int KT = K >> 5;
    FLOAD_STAGE(0, 0);

    int aBase0 = (wm * 64 + gq) * 20 + tq;
    int bBase0 = (wn * 64 + gq) * 20 + tq;

    for (int it = 0; it < KT; it++) {
        asm volatile("cp.async.wait_group 0;" ::: "memory");
        __syncthreads();
        if (it + 1 < KT) FLOAD_STAGE((it + 1) & 1, (it + 1) * 32);

        int s = it & 1;
        const uint32_t* a_t = smu + s * FSTAGE_W;
        const uint32_t* b_t = a_t + 5120;

        #pragma unroll
        for (int ks = 0; ks < 2; ks++) {
            int ko = ks * 8;
            uint32_t ah[4][4], bb[8][2];
            #pragma unroll
            for (int mt = 0; mt < 4; mt++) {
                int base = aBase0 + mt * 320 + ko;
                ah[mt][0] = a_t[base];
                ah[mt][1] = a_t[base + 160];
                ah[mt][2] = a_t[base + 4];
                ah[mt][3] = a_t[base + 164];
            }
            #pragma unroll
            for (int nt = 0; nt < 8; nt++) {
                int base = bBase0 + nt * 160 + ko;
                bb[nt][0] = b_t[base];
                bb[nt][1] = b_t[base + 4];
            }
            #pragma unroll
            for (int mt = 0; mt < 4; mt++)
                #pragma unroll
                for (int nt = 0; nt < 8; nt++)
                    mma_f16(acc[mt][nt], ah[mt], bb[nt]);
        }
        __syncthreads();
    }

    #pragma unroll
    for (int mt = 0; mt < 4; mt++) {
        #pragma unroll
        for (int nt = 0; nt < 8; nt++) {
            int r0 = by * 256 + wm * 64 + mt * 16 + gq;
            int c0 = bx * 128 + wn * 64 + nt * 8 + tq * 2;
            float b0 = bias[c0], b1 = bias[c0 + 1];
            #pragma unroll
            for (int half = 0; half < 2; half++) {
                size_t r = r0 + half * 8;
                float v0 = acc[mt][nt][half * 2 + 0] + b0;
                float v1 = acc[mt][nt][half * 2 + 1] + b1;
                if (EPI == 1) {
                    v0 = 0.5f * v0 * (1.0f + erff(v0 * 0.70710678118654752f));
                    v1 = 0.5f * v1 * (1.0f + erff(v1 * 0.70710678118654752f));
                    C16[(r * (size_t)N + c0) >> 1] = pack_f16(v0, v1);
                } else {
                    float2 rv = *(const float2*)(res + r * (size_t)N + c0);
                    v0 += rv.x; v1 += rv.y;
                    float2 o; o.x = v0; o.y = v1;
                    *(float2*)(Cf + r * (size_t)N + c0) = o;
                }
            }
        }
    }
}

// ---------------- launch ----------------
extern "C" void kernel_launch(void* const* d_in, const int* in_sizes, int n_in,
                              void* d_out, int out_size)
{
    const float* x     = (const float*)d_in[0];
    const float* Wq    = (const float*)d_in[1];
    const float* bq    = (const float*)d_in[2];
    const float* Wk    = (const float*)d_in[3];
    const float* bk    = (const float*)d_in[4];
    const float* Wv    = (const float*)d_in[5];
    const float* bv    = (const float*)d_in[6];
    const float* ln1_g = (const float*)d_in[7];
    const float* ln1_b = (const float*)d_in[8];
    const float* ln2_g = (const float*)d_in[9];
    const float* ln2_b = (const float*)d_in[10];
    const float* W1    = (const float*)d_in[11];
    const float* b1    = (const float*)d_in[12];
    const float* W2    = (const float*)d_in[13];
    const float* b2    = (const float*)d_in[14];
    float* out = (float*)d_out;

    uint16_t *hHi, *hLo, *WqkvHi, *WqkvLo, *W116, *W216, *h216, *m116;
    float *qkv, *xmid, *bqkv;
    cudaGetSymbolAddress((void**)&hHi,    g_h_hi);
    cudaGetSymbolAddress((void**)&hLo,    g_h_lo);
    cudaGetSymbolAddress((void**)&WqkvHi, g_Wqkv_hi);
    cudaGetSymbolAddress((void**)&WqkvLo, g_Wqkv_lo);
    cudaGetSymbolAddress((void**)&W116,   g_W116);
    cudaGetSymbolAddress((void**)&W216,   g_W216);
    cudaGetSymbolAddress((void**)&h216,   g_h216);
    cudaGetSymbolAddress((void**)&m116,   g_m116);
    cudaGetSymbolAddress((void**)&qkv,    g_qkv);
    cudaGetSymbolAddress((void**)&xmid,   g_xmid);
    cudaGetSymbolAddress((void**)&bqkv,   g_bqkv);

    cudaFuncSetAttribute(mma_gemm_qkv, cudaFuncAttributeMaxDynamicSharedMemorySize, SMEM_BGEMM);
    cudaFuncSetAttribute(mma_gemm_f16<1>, cudaFuncAttributeMaxDynamicSharedMemorySize, SMEM_FGEMM);
    cudaFuncSetAttribute(mma_gemm_f16<2>, cudaFuncAttributeMaxDynamicSharedMemorySize, SMEM_FGEMM);

    init_tw_kernel<<<1, 512>>>();
    bias_concat_kernel<<<NQKV / 256, 256>>>(bq, bk, bv);

    // QKV weights -> bf16 hi/lo planes (one launch); MLP weights -> fp16
    transpose_split_qkv_kernel<<<dim3(32, 32, 3), dim3(32, 8)>>>(Wq, Wk, Wv);
    transpose_f16_kernel<<<dim3(128, 32), dim3(32, 8)>>>(W1, W116, DIM, HID);
    transpose_f16_kernel<<<dim3(32, 128), dim3(32, 8)>>>(W2, W216, HID, DIM);

    // LN1 -> bf16 planes
    ln_split_kernel<<<NROW, 256>>>(x, ln1_g, ln1_b, hHi, hLo);

    // fused QKV projection (bf16x3, high precision for the amplified path)
    mma_gemm_qkv<<<dim3(NQKV / 128, NROW / 256), 256, SMEM_BGEMM>>>(
        hHi, hLo, WqkvHi, WqkvLo, bqkv, qkv, NQKV, DIM);

    // fused FFT + normalize for q,k,v — real-packed, 2 rows/block
    fft_qkv_pair_kernel<<<NROW / 2, 256>>>();

    // causal cumsum in Fourier domain (3-level scan, 2 bins/thread)
    chain_partial_kernel<<<(NBATCH * CHUNKS * DIM / 2) / 256, 256>>>();
    chain_scan_kernel<<<(NBATCH * DIM) / 256, 256>>>();
    chain_apply_kernel<<<(NBATCH * CHUNKS * DIM / 2) / 256, 256>>>();

    // paired inverse FFT (applies conj(Q̂)) + residual + LN2
    ifft_res_ln_pair_kernel<<<NROW / 2, 256>>>(x, ln2_g, ln2_b, h216);

    // MLP (fp16 single-pass)
    mma_gemm_f16<1><<<dim3(HID / 128, NROW / 256), 256, SMEM_FGEMM>>>(
        h216, W116, b1, nullptr, nullptr, (uint32_t*)m116, HID, DIM);
    mma_gemm_f16<2><<<dim3(DIM / 128, NROW / 256), 256, SMEM_FGEMM>>>(
        m116, W216, b2, xmid, out, nullptr, DIM, HID);

    (void)in_sizes; (void)n_in; (void)out_size;
}